// round 1
// baseline (speedup 1.0000x reference)
#include <cuda_runtime.h>
#include <math.h>

#define EPSQ 1e-5f

// Problem sizes (fixed by the reference setup_inputs)
#define S_ 1024
#define B_ 4
#define E_ 1024
#define H_ 16
#define D_ 64
#define R_ (S_*B_)   // 4096 flattened (s,b) rows

// ---------------------------------------------------------------------------
// Static device scratch (no runtime allocation allowed)
// ---------------------------------------------------------------------------
__device__ float g_LN[31];
__device__ float g_MIDS[30];

__device__ __align__(16) float g_Wi[3*E_*E_];
__device__ __align__(16) float g_Wo[E_*E_];
__device__ __align__(16) float g_bi[3*E_];
__device__ __align__(16) float g_bo[E_];
__device__ __align__(16) float g_qq[R_*E_];
__device__ __align__(16) float g_kq[R_*E_];
__device__ __align__(16) float g_vq[R_*E_];
__device__ __align__(16) float g_qp[R_*E_];
__device__ __align__(16) float g_kp[R_*E_];
__device__ __align__(16) float g_vp[R_*E_];
__device__ __align__(16) float g_ctx[R_*E_];
__device__ __align__(16) float g_scores[(long)B_*H_*S_*S_];   // 256 MB

// ---------------------------------------------------------------------------
// APoT level tables: built exactly as the numpy reference does, in float32.
// bit_width=4, k=2 -> 15 positive levels, gamma = float(1.0/1.5).
// ---------------------------------------------------------------------------
__global__ void init_tables_kernel() {
    const float pos[15] = {0.03125f, 0.0625f, 0.09375f, 0.125f, 0.1875f,
                           0.25f, 0.28125f, 0.375f, 0.5f, 0.5625f,
                           0.75f, 1.0f, 1.03125f, 1.125f, 1.5f};
    const float G = (float)(1.0 / 1.5);
    for (int i = 0; i < 15; i++) {
        g_LN[i]      = (-pos[14 - i]) * G;
        g_LN[16 + i] = pos[i] * G;
    }
    g_LN[15] = 0.0f;
    for (int i = 0; i < 30; i++)
        g_MIDS[i] = (g_LN[i] + g_LN[i + 1]) * 0.5f;
}

// rcf: xn = x/(alpha+eps); clip to [-1,1]; searchsorted(MIDS, xc, side='left')
// == count(MIDS[i] < xc); return LN[idx]*alpha.
__device__ __forceinline__ float rcf_dev(float x, float alpha,
                                         const float* __restrict__ LN,
                                         const float* __restrict__ MD) {
    float xn = x / (alpha + EPSQ);
    float xc = fminf(1.0f, fmaxf(-1.0f, xn));
    int idx = 0;
#pragma unroll
    for (int i = 0; i < 30; i++) idx += (MD[i] < xc) ? 1 : 0;
    return LN[idx] * alpha;
}

// ---------------------------------------------------------------------------
// Elementwise quantization (activations and biases): y = rcf(x, alpha)
// ---------------------------------------------------------------------------
__global__ void quant_elem_kernel(const float* __restrict__ x,
                                  float* __restrict__ y, int n,
                                  const float* __restrict__ alpha_p) {
    __shared__ float LN[31], MD[30];
    if (threadIdx.x < 31) LN[threadIdx.x] = g_LN[threadIdx.x];
    if (threadIdx.x < 30) MD[threadIdx.x] = g_MIDS[threadIdx.x];
    __syncthreads();
    float a = alpha_p[0];
    int i = blockIdx.x * blockDim.x + threadIdx.x;
    if (i < n) y[i] = rcf_dev(x[i], a, LN, MD);
}

// ---------------------------------------------------------------------------
// Per-row (per output channel) weight quantization:
//   mu, var over the row; wn = (w-mu)/sqrt(var+eps); rcf(wn, alpha)
// One block (256 threads) per row; double accumulation for the reductions.
// ---------------------------------------------------------------------------
__global__ void quant_weight_rows_kernel(const float* __restrict__ W,
                                         float* __restrict__ Wq,
                                         const float* __restrict__ alpha_p) {
    __shared__ float LN[31], MD[30];
    __shared__ double red[256];
    const int row = blockIdx.x, tid = threadIdx.x;
    if (tid < 31) LN[tid] = g_LN[tid];
    if (tid < 30) MD[tid] = g_MIDS[tid];
    const float* w = W + (long)row * E_;

    double s = 0.0;
    for (int c = tid; c < E_; c += 256) s += (double)w[c];
    red[tid] = s; __syncthreads();
    for (int o = 128; o > 0; o >>= 1) {
        if (tid < o) red[tid] += red[tid + o];
        __syncthreads();
    }
    double mu = red[0] / (double)E_;
    __syncthreads();

    double s2 = 0.0;
    for (int c = tid; c < E_; c += 256) {
        double d = (double)w[c] - mu;
        s2 += d * d;
    }
    red[tid] = s2; __syncthreads();
    for (int o = 128; o > 0; o >>= 1) {
        if (tid < o) red[tid] += red[tid + o];
        __syncthreads();
    }
    double var = red[0] / (double)E_;

    float inv = 1.0f / sqrtf((float)var + EPSQ);
    float muf = (float)mu;
    float a = alpha_p[0];
    for (int c = tid; c < E_; c += 256) {
        float wn = (w[c] - muf) * inv;
        Wq[(long)row * E_ + c] = rcf_dev(wn, a, LN, MD);
    }
}

// ---------------------------------------------------------------------------
// Generic strided batched fp32 GEMM:  C[m,n] = scale * sum_k A[m,k]*B[n,k] (+bias[n])
//   A[m,k] at A + m*sAm + k            (A is always K-contiguous here)
//   B[n,k] at B + n*sBn + k*sBk        (sBk==1 fast path uses float4 loads)
//   C[m,n] at C + m*sCm + n
// Assumes M % BM == 0, N % BN == 0, K % BK == 0 (true for every call below).
// ---------------------------------------------------------------------------
template <int BM, int BN, int BK, int TM, int TN>
__global__ void gemm_tn_kernel(const float* __restrict__ A,
                               const float* __restrict__ B,
                               float* __restrict__ C,
                               const float* __restrict__ bias,
                               int K,
                               long sAm, long sBn, long sBk, long sCm,
                               long bsA, long bsB, long bsC, float scale) {
    constexpr int THREADS = (BM / TM) * (BN / TN);
    __shared__ __align__(16) float As[BK][BM];
    __shared__ __align__(16) float Bs[BK][BN];

    const int tid = threadIdx.x;
    const long z = blockIdx.z;
    A += z * bsA; B += z * bsB; C += z * bsC;
    const int m0 = blockIdx.y * BM;
    const int n0 = blockIdx.x * BN;
    const int ty = tid / (BN / TN);     // row group
    const int tx = tid % (BN / TN);     // col group

    float acc[TM][TN];
#pragma unroll
    for (int i = 0; i < TM; i++)
#pragma unroll
        for (int j = 0; j < TN; j++) acc[i][j] = 0.0f;

    for (int k0 = 0; k0 < K; k0 += BK) {
        // Load A tile (BM x BK), K-contiguous -> float4 along k
        for (int i = tid; i < BM * (BK / 4); i += THREADS) {
            int m = i / (BK / 4), k4 = i % (BK / 4);
            float4 v = *reinterpret_cast<const float4*>(
                A + (long)(m0 + m) * sAm + k0 + k4 * 4);
            As[k4 * 4 + 0][m] = v.x;
            As[k4 * 4 + 1][m] = v.y;
            As[k4 * 4 + 2][m] = v.z;
            As[k4 * 4 + 3][m] = v.w;
        }
        // Load B tile (BN x BK)
        if (sBk == 1) {
            for (int i = tid; i < BN * (BK / 4); i += THREADS) {
                int n = i / (BK / 4), k4 = i % (BK / 4);
                float4 v = *reinterpret_cast<const float4*>(
                    B + (long)(n0 + n) * sBn + k0 + k4 * 4);
                Bs[k4 * 4 + 0][n] = v.x;
                Bs[k4 * 4 + 1][n] = v.y;
                Bs[k4 * 4 + 2][n] = v.z;
                Bs[k4 * 4 + 3][n] = v.w;
            }
        } else {
            // generic strided path (PV: sBn==1 -> coalesced along n)
            for (int i = tid; i < BN * BK; i += THREADS) {
                int n = i % BN, k = i / BN;
                Bs[k][n] = B[(long)(n0 + n) * sBn + (long)(k0 + k) * sBk];
            }
        }
        __syncthreads();

#pragma unroll
        for (int k = 0; k < BK; k++) {
            float a[TM], b[TN];
#pragma unroll
            for (int i = 0; i < TM; i += 4)
                *reinterpret_cast<float4*>(&a[i]) =
                    *reinterpret_cast<const float4*>(&As[k][ty * TM + i]);
#pragma unroll
            for (int j = 0; j < TN; j += 4)
                *reinterpret_cast<float4*>(&b[j]) =
                    *reinterpret_cast<const float4*>(&Bs[k][tx * TN + j]);
#pragma unroll
            for (int i = 0; i < TM; i++)
#pragma unroll
                for (int j = 0; j < TN; j++) acc[i][j] += a[i] * b[j];
        }
        __syncthreads();
    }

#pragma unroll
    for (int i = 0; i < TM; i++) {
#pragma unroll
        for (int j = 0; j < TN; j++) {
            long m = m0 + ty * TM + i;
            long n = n0 + tx * TN + j;
            float v = acc[i][j] * scale;
            if (bias) v += bias[n];
            C[m * sCm + n] = v;
        }
    }
}

// ---------------------------------------------------------------------------
// Row softmax over 1024 columns, in place. One block (256 thr) per row.
// ---------------------------------------------------------------------------
__global__ void softmax_rows_kernel(float* __restrict__ P) {
    __shared__ float red[256];
    const long row = blockIdx.x;
    float* p = P + row * (long)S_;
    const int tid = threadIdx.x;

    float4 v = reinterpret_cast<float4*>(p)[tid];
    float m = fmaxf(fmaxf(v.x, v.y), fmaxf(v.z, v.w));
    red[tid] = m; __syncthreads();
    for (int o = 128; o > 0; o >>= 1) {
        if (tid < o) red[tid] = fmaxf(red[tid], red[tid + o]);
        __syncthreads();
    }
    float M = red[0];
    __syncthreads();

    v.x = expf(v.x - M); v.y = expf(v.y - M);
    v.z = expf(v.z - M); v.w = expf(v.w - M);
    float s = v.x + v.y + v.z + v.w;
    red[tid] = s; __syncthreads();
    for (int o = 128; o > 0; o >>= 1) {
        if (tid < o) red[tid] += red[tid + o];
        __syncthreads();
    }
    float inv = 1.0f / red[0];
    v.x *= inv; v.y *= inv; v.z *= inv; v.w *= inv;
    reinterpret_cast<float4*>(p)[tid] = v;
}

// ---------------------------------------------------------------------------
// Orchestration.
// Head-view batching trick: for z = b*16 + h, the (b,h) view of a (4096,1024)
// projection matrix starts at offset b*1024 + h*64 == z*64, with row (s)
// stride 4096. So batch strides are a uniform 64 floats.
// ---------------------------------------------------------------------------
extern "C" void kernel_launch(void* const* d_in, const int* in_sizes, int n_in,
                              void* d_out, int out_size) {
    const float* q    = (const float*)d_in[0];
    const float* k    = (const float*)d_in[1];
    const float* v    = (const float*)d_in[2];
    const float* Wi   = (const float*)d_in[3];
    const float* bi   = (const float*)d_in[4];
    const float* Wo   = (const float*)d_in[5];
    const float* bo   = (const float*)d_in[6];
    const float* a_act = (const float*)d_in[7];
    const float* a_wi  = (const float*)d_in[8];
    const float* a_bi  = (const float*)d_in[9];
    const float* a_wo  = (const float*)d_in[10];
    const float* a_bo  = (const float*)d_in[11];
    float* out = (float*)d_out;

    float *p_Wi, *p_Wo, *p_bi, *p_bo, *p_qq, *p_kq, *p_vq,
          *p_qp, *p_kp, *p_vp, *p_ctx, *p_sc;
    cudaGetSymbolAddress((void**)&p_Wi, g_Wi);
    cudaGetSymbolAddress((void**)&p_Wo, g_Wo);
    cudaGetSymbolAddress((void**)&p_bi, g_bi);
    cudaGetSymbolAddress((void**)&p_bo, g_bo);
    cudaGetSymbolAddress((void**)&p_qq, g_qq);
    cudaGetSymbolAddress((void**)&p_kq, g_kq);
    cudaGetSymbolAddress((void**)&p_vq, g_vq);
    cudaGetSymbolAddress((void**)&p_qp, g_qp);
    cudaGetSymbolAddress((void**)&p_kp, g_kp);
    cudaGetSymbolAddress((void**)&p_vp, g_vp);
    cudaGetSymbolAddress((void**)&p_ctx, g_ctx);
    cudaGetSymbolAddress((void**)&p_sc, g_scores);

    init_tables_kernel<<<1, 1>>>();

    // Weight + bias quantization
    quant_weight_rows_kernel<<<3 * E_, 256>>>(Wi, p_Wi, a_wi);
    quant_weight_rows_kernel<<<E_, 256>>>(Wo, p_Wo, a_wo);
    quant_elem_kernel<<<(3 * E_ + 255) / 256, 256>>>(bi, p_bi, 3 * E_, a_bi);
    quant_elem_kernel<<<(E_ + 255) / 256, 256>>>(bo, p_bo, E_, a_bo);

    // Activation quantization
    quant_elem_kernel<<<R_ * E_ / 256, 256>>>(q, p_qq, R_ * E_, a_act);
    quant_elem_kernel<<<R_ * E_ / 256, 256>>>(k, p_kq, R_ * E_, a_act);
    quant_elem_kernel<<<R_ * E_ / 256, 256>>>(v, p_vq, R_ * E_, a_act);

    // Projections: P = Aq @ Wsec^T + bsec   (M=4096, N=1024, K=1024)
    dim3 gproj(E_ / 128, R_ / 128, 1);
    gemm_tn_kernel<128, 128, 16, 8, 8><<<gproj, 256>>>(
        p_qq, p_Wi, p_qp, p_bi, E_,
        (long)E_, (long)E_, 1L, (long)E_, 0L, 0L, 0L, 1.0f);
    gemm_tn_kernel<128, 128, 16, 8, 8><<<gproj, 256>>>(
        p_kq, p_Wi + (long)E_ * E_, p_kp, p_bi + E_, E_,
        (long)E_, (long)E_, 1L, (long)E_, 0L, 0L, 0L, 1.0f);
    gemm_tn_kernel<128, 128, 16, 8, 8><<<gproj, 256>>>(
        p_vq, p_Wi + 2L * E_ * E_, p_vp, p_bi + 2 * E_, E_,
        (long)E_, (long)E_, 1L, (long)E_, 0L, 0L, 0L, 1.0f);

    // Scores: per (b,h): S[s,t] = (qh[s,:] . kh[t,:]) / 8   (M=N=1024, K=64)
    gemm_tn_kernel<128, 128, 16, 8, 8><<<dim3(8, 8, 64), 256>>>(
        p_qp, p_kp, p_sc, nullptr, D_,
        (long)(B_ * E_), (long)(B_ * E_), 1L, (long)S_,
        64L, 64L, (long)S_ * S_, 0.125f);

    // Softmax over k positions
    softmax_rows_kernel<<<B_ * H_ * S_, 256>>>(p_sc);

    // PV: per (b,h): ctx[s,d] = sum_t attn[s,t] * vh[t,d]  (M=1024, N=64, K=1024)
    gemm_tn_kernel<128, 64, 16, 8, 4><<<dim3(1, 8, 64), 256>>>(
        p_sc, p_vp, p_ctx, nullptr, S_,
        (long)S_, 1L, (long)(B_ * E_), (long)(B_ * E_),
        (long)S_ * S_, 64L, 64L, 1.0f);

    // Output projection: out = ctx @ Wo^T + bo  (M=4096, N=1024, K=1024)
    gemm_tn_kernel<128, 128, 16, 8, 8><<<gproj, 256>>>(
        p_ctx, p_Wo, out, p_bo, E_,
        (long)E_, (long)E_, 1L, (long)E_, 0L, 0L, 0L, 1.0f);
}

// round 2
// speedup vs baseline: 1.5896x; 1.5896x over previous
#include <cuda_runtime.h>
#include <math.h>
#include <stdint.h>

#define EPSQ 1e-5f

// Problem sizes (fixed by the reference setup_inputs)
#define S_ 1024
#define B_ 4
#define E_ 1024
#define H_ 16
#define D_ 64
#define R_ (S_*B_)   // 4096 flattened (s,b) rows

// ---------------------------------------------------------------------------
// Static device scratch (no runtime allocation allowed)
// ---------------------------------------------------------------------------
__device__ float g_LN[31];
__device__ float g_MIDS[30];
__device__ int   g_LN48[31];          // LN * 48 as exact integers

__device__ __align__(16) int8_t g_Wi_i8[3*E_*E_];     // quantized Wi (k-values)
__device__ __align__(16) float  g_Wo[E_*E_];
__device__ __align__(16) float  g_bi[3*E_];
__device__ __align__(16) float  g_bo[E_];
__device__ __align__(16) int8_t g_act_i8[3L*R_*E_];   // q,k,v quantized k-values
__device__ __align__(16) float  g_proj[3L*R_*E_];     // qp,kp,vp
__device__ __align__(16) float  g_ctx[R_*E_];
__device__ __align__(16) float  g_scores[(long)B_*H_*S_*S_];   // 256 MB

// ---------------------------------------------------------------------------
// APoT level tables (exact float emulation of the numpy construction).
// bit_width=4, k=2 -> 15 positive levels, gamma = 1/1.5. LN = k/48 exactly.
// ---------------------------------------------------------------------------
__global__ void init_tables_kernel() {
    const float pos[15] = {0.03125f, 0.0625f, 0.09375f, 0.125f, 0.1875f,
                           0.25f, 0.28125f, 0.375f, 0.5f, 0.5625f,
                           0.75f, 1.0f, 1.03125f, 1.125f, 1.5f};
    const float G = (float)(1.0 / 1.5);
    for (int i = 0; i < 15; i++) {
        g_LN[i]      = (-pos[14 - i]) * G;
        g_LN[16 + i] = pos[i] * G;
    }
    g_LN[15] = 0.0f;
    for (int i = 0; i < 30; i++)
        g_MIDS[i] = (g_LN[i] + g_LN[i + 1]) * 0.5f;
    for (int i = 0; i < 31; i++)
        g_LN48[i] = (int)lrintf(g_LN[i] * 48.0f);
}

// searchsorted(MIDS, xc, side='left') == count(MIDS[i] < xc)
__device__ __forceinline__ int rcf_idx(float x, float alpha,
                                       const float* __restrict__ MD) {
    float xn = x / (alpha + EPSQ);
    float xc = fminf(1.0f, fmaxf(-1.0f, xn));
    int idx = 0;
#pragma unroll
    for (int i = 0; i < 30; i++) idx += (MD[i] < xc) ? 1 : 0;
    return idx;
}

__device__ __forceinline__ float rcf_dev(float x, float alpha,
                                         const float* __restrict__ LN,
                                         const float* __restrict__ MD) {
    return LN[rcf_idx(x, alpha, MD)] * alpha;
}

// ---------------------------------------------------------------------------
// Elementwise quantization to fp32 (biases)
// ---------------------------------------------------------------------------
__global__ void quant_elem_kernel(const float* __restrict__ x,
                                  float* __restrict__ y, int n,
                                  const float* __restrict__ alpha_p) {
    __shared__ float LN[31], MD[30];
    if (threadIdx.x < 31) LN[threadIdx.x] = g_LN[threadIdx.x];
    if (threadIdx.x < 30) MD[threadIdx.x] = g_MIDS[threadIdx.x];
    __syncthreads();
    float a = alpha_p[0];
    int i = blockIdx.x * blockDim.x + threadIdx.x;
    if (i < n) y[i] = rcf_dev(x[i], a, LN, MD);
}

// ---------------------------------------------------------------------------
// Elementwise quantization to int8 k-values (activations): y = LN48[idx]
// ---------------------------------------------------------------------------
__global__ void quant_elem_i8_kernel(const float* __restrict__ x,
                                     int8_t* __restrict__ y, int n,
                                     const float* __restrict__ alpha_p) {
    __shared__ float MD[30];
    __shared__ int   L48[31];
    if (threadIdx.x < 30) MD[threadIdx.x] = g_MIDS[threadIdx.x];
    if (threadIdx.x < 31) L48[threadIdx.x] = g_LN48[threadIdx.x];
    __syncthreads();
    float a = alpha_p[0];
    int i0 = (blockIdx.x * blockDim.x + threadIdx.x) * 4;
    if (i0 < n) {
        float4 v = *reinterpret_cast<const float4*>(x + i0);
        char4 o;
        o.x = (int8_t)L48[rcf_idx(v.x, a, MD)];
        o.y = (int8_t)L48[rcf_idx(v.y, a, MD)];
        o.z = (int8_t)L48[rcf_idx(v.z, a, MD)];
        o.w = (int8_t)L48[rcf_idx(v.w, a, MD)];
        *reinterpret_cast<char4*>(y + i0) = o;
    }
}

// ---------------------------------------------------------------------------
// Per-row weight quantization -> fp32 (for Wo)
// ---------------------------------------------------------------------------
__global__ void quant_weight_rows_kernel(const float* __restrict__ W,
                                         float* __restrict__ Wq,
                                         const float* __restrict__ alpha_p) {
    __shared__ float LN[31], MD[30];
    __shared__ double red[256];
    const int row = blockIdx.x, tid = threadIdx.x;
    if (tid < 31) LN[tid] = g_LN[tid];
    if (tid < 30) MD[tid] = g_MIDS[tid];
    const float* w = W + (long)row * E_;

    double s = 0.0;
    for (int c = tid; c < E_; c += 256) s += (double)w[c];
    red[tid] = s; __syncthreads();
    for (int o = 128; o > 0; o >>= 1) {
        if (tid < o) red[tid] += red[tid + o];
        __syncthreads();
    }
    double mu = red[0] / (double)E_;
    __syncthreads();

    double s2 = 0.0;
    for (int c = tid; c < E_; c += 256) {
        double d = (double)w[c] - mu;
        s2 += d * d;
    }
    red[tid] = s2; __syncthreads();
    for (int o = 128; o > 0; o >>= 1) {
        if (tid < o) red[tid] += red[tid + o];
        __syncthreads();
    }
    double var = red[0] / (double)E_;

    float inv = 1.0f / sqrtf((float)var + EPSQ);
    float muf = (float)mu;
    float a = alpha_p[0];
    for (int c = tid; c < E_; c += 256) {
        float wn = (w[c] - muf) * inv;
        Wq[(long)row * E_ + c] = rcf_dev(wn, a, LN, MD);
    }
}

// ---------------------------------------------------------------------------
// Per-row weight quantization -> int8 k-values (for Wi)
// ---------------------------------------------------------------------------
__global__ void quant_weight_rows_i8_kernel(const float* __restrict__ W,
                                            int8_t* __restrict__ Wq,
                                            const float* __restrict__ alpha_p) {
    __shared__ float MD[30];
    __shared__ int   L48[31];
    __shared__ double red[256];
    const int row = blockIdx.x, tid = threadIdx.x;
    if (tid < 30) MD[tid] = g_MIDS[tid];
    if (tid < 31) L48[tid] = g_LN48[tid];
    const float* w = W + (long)row * E_;

    double s = 0.0;
    for (int c = tid; c < E_; c += 256) s += (double)w[c];
    red[tid] = s; __syncthreads();
    for (int o = 128; o > 0; o >>= 1) {
        if (tid < o) red[tid] += red[tid + o];
        __syncthreads();
    }
    double mu = red[0] / (double)E_;
    __syncthreads();

    double s2 = 0.0;
    for (int c = tid; c < E_; c += 256) {
        double d = (double)w[c] - mu;
        s2 += d * d;
    }
    red[tid] = s2; __syncthreads();
    for (int o = 128; o > 0; o >>= 1) {
        if (tid < o) red[tid] += red[tid + o];
        __syncthreads();
    }
    double var = red[0] / (double)E_;

    float inv = 1.0f / sqrtf((float)var + EPSQ);
    float muf = (float)mu;
    float a = alpha_p[0];
    for (int c = tid; c < E_; c += 256) {
        float wn = (w[c] - muf) * inv;
        Wq[(long)row * E_ + c] = (int8_t)L48[rcf_idx(wn, a, MD)];
    }
}

// ---------------------------------------------------------------------------
// int8 tensor-core GEMM (mma.sync.m16n8k32.s8.s8.s32), batched over z:
//   C[z][m,n] = float(sum_k A[z][m,k]*B[z][n,k]) * (aA*aB/2304) + bias[z][n]
// A: int8 [3][M,K] row-major, B: int8 [3][N,K] row-major, C: fp32 [3][M,N].
// BM=BN=128, BK=64, 256 threads = 8 warps (2x4), warp tile 64x32.
// ---------------------------------------------------------------------------
__device__ __forceinline__ void mma_i8(int* d, const uint32_t* a,
                                       const uint32_t* b) {
    asm volatile(
        "mma.sync.aligned.m16n8k32.row.col.s32.s8.s8.s32 "
        "{%0,%1,%2,%3}, {%4,%5,%6,%7}, {%8,%9}, {%0,%1,%2,%3};\n"
        : "+r"(d[0]), "+r"(d[1]), "+r"(d[2]), "+r"(d[3])
        : "r"(a[0]), "r"(a[1]), "r"(a[2]), "r"(a[3]), "r"(b[0]), "r"(b[1]));
}

#define I8_STRIDE 80   // padded smem row stride in bytes (16B aligned, conflict-free)

__global__ __launch_bounds__(256) void gemm_i8_kernel(
    const int8_t* __restrict__ A, const int8_t* __restrict__ B,
    float* __restrict__ C, const float* __restrict__ bias,
    const float* __restrict__ aA, const float* __restrict__ aB,
    int K, int N) {
    __shared__ __align__(16) int8_t As[128 * I8_STRIDE];
    __shared__ __align__(16) int8_t Bs[128 * I8_STRIDE];

    const int tid  = threadIdx.x;
    const int warp = tid >> 5;
    const int lane = tid & 31;
    const int g    = lane >> 2;   // group id (row within fragment)
    const int tig  = lane & 3;    // thread in group

    const long z = blockIdx.z;
    A += z * (long)R_ * K;
    B += z * (long)N * K;
    C += z * (long)R_ * N;
    bias += z * N;

    const int m0 = blockIdx.y * 128;
    const int n0 = blockIdx.x * 128;
    const int wm = (warp >> 2) * 64;   // warp row offset
    const int wn = (warp & 3) * 32;    // warp col offset

    int acc[4][4][4];
#pragma unroll
    for (int a_ = 0; a_ < 4; a_++)
#pragma unroll
        for (int b_ = 0; b_ < 4; b_++)
#pragma unroll
            for (int c_ = 0; c_ < 4; c_++) acc[a_][b_][c_] = 0;

    const uint32_t* Aw = reinterpret_cast<const uint32_t*>(As);
    const uint32_t* Bw = reinterpret_cast<const uint32_t*>(Bs);
    const int WSTR = I8_STRIDE / 4;   // words per row (20)

    for (int k0 = 0; k0 < K; k0 += 64) {
        // Load A and B tiles: 128 rows x 64 bytes each, int4 vectorized.
#pragma unroll
        for (int it = 0; it < 2; it++) {
            int idx = it * 256 + tid;
            int row = idx >> 2, c = idx & 3;
            *reinterpret_cast<int4*>(&As[row * I8_STRIDE + c * 16]) =
                *reinterpret_cast<const int4*>(A + (long)(m0 + row) * K + k0 + c * 16);
            *reinterpret_cast<int4*>(&Bs[row * I8_STRIDE + c * 16]) =
                *reinterpret_cast<const int4*>(B + (long)(n0 + row) * K + k0 + c * 16);
        }
        __syncthreads();

#pragma unroll
        for (int ks = 0; ks < 2; ks++) {
            uint32_t af[4][4], bf[4][2];
#pragma unroll
            for (int mt = 0; mt < 4; mt++) {
                int base = (wm + mt * 16 + g) * WSTR + ks * 8 + tig;
                af[mt][0] = Aw[base];
                af[mt][1] = Aw[base + 8 * WSTR];
                af[mt][2] = Aw[base + 4];
                af[mt][3] = Aw[base + 8 * WSTR + 4];
            }
#pragma unroll
            for (int nt = 0; nt < 4; nt++) {
                int base = (wn + nt * 8 + g) * WSTR + ks * 8 + tig;
                bf[nt][0] = Bw[base];
                bf[nt][1] = Bw[base + 4];
            }
#pragma unroll
            for (int mt = 0; mt < 4; mt++)
#pragma unroll
                for (int nt = 0; nt < 4; nt++)
                    mma_i8(acc[mt][nt], af[mt], bf[nt]);
        }
        __syncthreads();
    }

    // Epilogue: fp32 scale + bias
    const float scale = __ldg(aA) * __ldg(aB) * (1.0f / 2304.0f);
#pragma unroll
    for (int mt = 0; mt < 4; mt++) {
#pragma unroll
        for (int nt = 0; nt < 4; nt++) {
            int row = m0 + wm + mt * 16 + g;
            int col = n0 + wn + nt * 8 + tig * 2;
            float b0 = bias[col], b1 = bias[col + 1];
            float2 v0, v1;
            v0.x = (float)acc[mt][nt][0] * scale + b0;
            v0.y = (float)acc[mt][nt][1] * scale + b1;
            v1.x = (float)acc[mt][nt][2] * scale + b0;
            v1.y = (float)acc[mt][nt][3] * scale + b1;
            *reinterpret_cast<float2*>(C + (long)row * N + col) = v0;
            *reinterpret_cast<float2*>(C + (long)(row + 8) * N + col) = v1;
        }
    }
}

// ---------------------------------------------------------------------------
// Generic strided batched fp32 GEMM (unchanged from round 1)
// ---------------------------------------------------------------------------
template <int BM, int BN, int BK, int TM, int TN>
__global__ void gemm_tn_kernel(const float* __restrict__ A,
                               const float* __restrict__ B,
                               float* __restrict__ C,
                               const float* __restrict__ bias,
                               int K,
                               long sAm, long sBn, long sBk, long sCm,
                               long bsA, long bsB, long bsC, float scale) {
    constexpr int THREADS = (BM / TM) * (BN / TN);
    __shared__ __align__(16) float As[BK][BM];
    __shared__ __align__(16) float Bs[BK][BN];

    const int tid = threadIdx.x;
    const long z = blockIdx.z;
    A += z * bsA; B += z * bsB; C += z * bsC;
    const int m0 = blockIdx.y * BM;
    const int n0 = blockIdx.x * BN;
    const int ty = tid / (BN / TN);
    const int tx = tid % (BN / TN);

    float acc[TM][TN];
#pragma unroll
    for (int i = 0; i < TM; i++)
#pragma unroll
        for (int j = 0; j < TN; j++) acc[i][j] = 0.0f;

    for (int k0 = 0; k0 < K; k0 += BK) {
        for (int i = tid; i < BM * (BK / 4); i += THREADS) {
            int m = i / (BK / 4), k4 = i % (BK / 4);
            float4 v = *reinterpret_cast<const float4*>(
                A + (long)(m0 + m) * sAm + k0 + k4 * 4);
            As[k4 * 4 + 0][m] = v.x;
            As[k4 * 4 + 1][m] = v.y;
            As[k4 * 4 + 2][m] = v.z;
            As[k4 * 4 + 3][m] = v.w;
        }
        if (sBk == 1) {
            for (int i = tid; i < BN * (BK / 4); i += THREADS) {
                int n = i / (BK / 4), k4 = i % (BK / 4);
                float4 v = *reinterpret_cast<const float4*>(
                    B + (long)(n0 + n) * sBn + k0 + k4 * 4);
                Bs[k4 * 4 + 0][n] = v.x;
                Bs[k4 * 4 + 1][n] = v.y;
                Bs[k4 * 4 + 2][n] = v.z;
                Bs[k4 * 4 + 3][n] = v.w;
            }
        } else {
            for (int i = tid; i < BN * BK; i += THREADS) {
                int n = i % BN, k = i / BN;
                Bs[k][n] = B[(long)(n0 + n) * sBn + (long)(k0 + k) * sBk];
            }
        }
        __syncthreads();

#pragma unroll
        for (int k = 0; k < BK; k++) {
            float a[TM], b[TN];
#pragma unroll
            for (int i = 0; i < TM; i += 4)
                *reinterpret_cast<float4*>(&a[i]) =
                    *reinterpret_cast<const float4*>(&As[k][ty * TM + i]);
#pragma unroll
            for (int j = 0; j < TN; j += 4)
                *reinterpret_cast<float4*>(&b[j]) =
                    *reinterpret_cast<const float4*>(&Bs[k][tx * TN + j]);
#pragma unroll
            for (int i = 0; i < TM; i++)
#pragma unroll
                for (int j = 0; j < TN; j++) acc[i][j] += a[i] * b[j];
        }
        __syncthreads();
    }

#pragma unroll
    for (int i = 0; i < TM; i++) {
#pragma unroll
        for (int j = 0; j < TN; j++) {
            long m = m0 + ty * TM + i;
            long n = n0 + tx * TN + j;
            float v = acc[i][j] * scale;
            if (bias) v += bias[n];
            C[m * sCm + n] = v;
        }
    }
}

// ---------------------------------------------------------------------------
// Row softmax over 1024 columns, in place. One block (256 thr) per row.
// ---------------------------------------------------------------------------
__global__ void softmax_rows_kernel(float* __restrict__ P) {
    __shared__ float red[256];
    const long row = blockIdx.x;
    float* p = P + row * (long)S_;
    const int tid = threadIdx.x;

    float4 v = reinterpret_cast<float4*>(p)[tid];
    float m = fmaxf(fmaxf(v.x, v.y), fmaxf(v.z, v.w));
    red[tid] = m; __syncthreads();
    for (int o = 128; o > 0; o >>= 1) {
        if (tid < o) red[tid] = fmaxf(red[tid], red[tid + o]);
        __syncthreads();
    }
    float M = red[0];
    __syncthreads();

    v.x = expf(v.x - M); v.y = expf(v.y - M);
    v.z = expf(v.z - M); v.w = expf(v.w - M);
    float s = v.x + v.y + v.z + v.w;
    red[tid] = s; __syncthreads();
    for (int o = 128; o > 0; o >>= 1) {
        if (tid < o) red[tid] += red[tid + o];
        __syncthreads();
    }
    float inv = 1.0f / red[0];
    v.x *= inv; v.y *= inv; v.z *= inv; v.w *= inv;
    reinterpret_cast<float4*>(p)[tid] = v;
}

// ---------------------------------------------------------------------------
// Orchestration.
// ---------------------------------------------------------------------------
extern "C" void kernel_launch(void* const* d_in, const int* in_sizes, int n_in,
                              void* d_out, int out_size) {
    const float* q    = (const float*)d_in[0];
    const float* k    = (const float*)d_in[1];
    const float* v    = (const float*)d_in[2];
    const float* Wi   = (const float*)d_in[3];
    const float* bi   = (const float*)d_in[4];
    const float* Wo   = (const float*)d_in[5];
    const float* bo   = (const float*)d_in[6];
    const float* a_act = (const float*)d_in[7];
    const float* a_wi  = (const float*)d_in[8];
    const float* a_bi  = (const float*)d_in[9];
    const float* a_wo  = (const float*)d_in[10];
    const float* a_bo  = (const float*)d_in[11];
    float* out = (float*)d_out;

    int8_t *p_Wi8, *p_act8;
    float *p_Wo, *p_bi, *p_bo, *p_proj, *p_ctx, *p_sc;
    cudaGetSymbolAddress((void**)&p_Wi8, g_Wi_i8);
    cudaGetSymbolAddress((void**)&p_act8, g_act_i8);
    cudaGetSymbolAddress((void**)&p_Wo, g_Wo);
    cudaGetSymbolAddress((void**)&p_bi, g_bi);
    cudaGetSymbolAddress((void**)&p_bo, g_bo);
    cudaGetSymbolAddress((void**)&p_proj, g_proj);
    cudaGetSymbolAddress((void**)&p_ctx, g_ctx);
    cudaGetSymbolAddress((void**)&p_sc, g_scores);

    const long RE = (long)R_ * E_;
    float* p_qp = p_proj;
    float* p_kp = p_proj + RE;
    float* p_vp = p_proj + 2 * RE;

    init_tables_kernel<<<1, 1>>>();

    // Weight + bias quantization
    quant_weight_rows_i8_kernel<<<3 * E_, 256>>>(Wi, p_Wi8, a_wi);
    quant_weight_rows_kernel<<<E_, 256>>>(Wo, p_Wo, a_wo);
    quant_elem_kernel<<<(3 * E_ + 255) / 256, 256>>>(bi, p_bi, 3 * E_, a_bi);
    quant_elem_kernel<<<(E_ + 255) / 256, 256>>>(bo, p_bo, E_, a_bo);

    // Activation quantization -> int8 k-values
    quant_elem_i8_kernel<<<RE / 1024, 256>>>(q, p_act8, RE, a_act);
    quant_elem_i8_kernel<<<RE / 1024, 256>>>(k, p_act8 + RE, RE, a_act);
    quant_elem_i8_kernel<<<RE / 1024, 256>>>(v, p_act8 + 2 * RE, RE, a_act);

    // Projections via int8 tensor cores (exact):
    // qp/kp/vp[m,n] = int_acc * (a_act*a_wi/2304) + bi_sec[n]
    gemm_i8_kernel<<<dim3(E_ / 128, R_ / 128, 3), 256>>>(
        p_act8, p_Wi8, p_proj, p_bi, a_act, a_wi, E_, E_);

    // Scores: per (b,h): S[s,t] = (qh[s,:] . kh[t,:]) / 8
    gemm_tn_kernel<128, 128, 16, 8, 8><<<dim3(8, 8, 64), 256>>>(
        p_qp, p_kp, p_sc, nullptr, D_,
        (long)(B_ * E_), (long)(B_ * E_), 1L, (long)S_,
        64L, 64L, (long)S_ * S_, 0.125f);

    // Softmax over k positions
    softmax_rows_kernel<<<B_ * H_ * S_, 256>>>(p_sc);

    // PV: per (b,h): ctx[s,d] = sum_t attn[s,t] * vh[t,d]
    gemm_tn_kernel<128, 64, 16, 8, 4><<<dim3(1, 8, 64), 256>>>(
        p_sc, p_vp, p_ctx, nullptr, S_,
        (long)S_, 1L, (long)(B_ * E_), (long)(B_ * E_),
        (long)S_ * S_, 64L, 64L, 1.0f);

    // Output projection: out = ctx @ Wo^T + bo
    gemm_tn_kernel<128, 128, 16, 8, 8><<<dim3(E_ / 128, R_ / 128, 1), 256>>>(
        p_ctx, p_Wo, out, p_bo, E_,
        (long)E_, (long)E_, 1L, (long)E_, 0L, 0L, 0L, 1.0f);
}

// round 8
// speedup vs baseline: 3.2098x; 2.0192x over previous
#include <cuda_runtime.h>
#include <cuda_fp16.h>
#include <math.h>
#include <stdint.h>

#define EPSQ 1e-5f

// Problem sizes (fixed by the reference setup_inputs)
#define S_ 1024
#define B_ 4
#define E_ 1024
#define H_ 16
#define D_ 64
#define R_ (S_*B_)   // 4096 flattened (s,b) rows
#define Z_ (B_*H_)   // 64 batched heads

// ---------------------------------------------------------------------------
// Static device scratch (no runtime allocation allowed)
// ---------------------------------------------------------------------------
__device__ float g_LN[31];
__device__ float g_MIDS[30];
__device__ int   g_LN48[31];

__device__ __align__(16) int8_t g_Wi_i8[3*E_*E_];
__device__ __align__(16) float  g_Wo[E_*E_];
__device__ __align__(16) float  g_bi[3*E_];
__device__ __align__(16) float  g_bo[E_];
__device__ __align__(16) int8_t g_act_i8[3L*R_*E_];
__device__ __align__(16) float  g_proj[3L*R_*E_];     // qp,kp,vp
__device__ __align__(16) float  g_vpT[(long)Z_*D_*S_];// vp transposed per head
__device__ __align__(16) float  g_ctx[R_*E_];
__device__ __align__(16) float  g_scores[(long)Z_*S_*S_];   // 256 MB

// ---------------------------------------------------------------------------
// APoT tables (exact float emulation of the numpy construction)
// ---------------------------------------------------------------------------
__global__ void init_tables_kernel() {
    const float pos[15] = {0.03125f, 0.0625f, 0.09375f, 0.125f, 0.1875f,
                           0.25f, 0.28125f, 0.375f, 0.5f, 0.5625f,
                           0.75f, 1.0f, 1.03125f, 1.125f, 1.5f};
    const float G = (float)(1.0 / 1.5);
    for (int i = 0; i < 15; i++) {
        g_LN[i]      = (-pos[14 - i]) * G;
        g_LN[16 + i] = pos[i] * G;
    }
    g_LN[15] = 0.0f;
    for (int i = 0; i < 30; i++)
        g_MIDS[i] = (g_LN[i] + g_LN[i + 1]) * 0.5f;
    for (int i = 0; i < 31; i++)
        g_LN48[i] = (int)lrintf(g_LN[i] * 48.0f);
}

__device__ __forceinline__ int rcf_idx(float x, float alpha,
                                       const float* __restrict__ MD) {
    float xn = x / (alpha + EPSQ);
    float xc = fminf(1.0f, fmaxf(-1.0f, xn));
    int idx = 0;
#pragma unroll
    for (int i = 0; i < 30; i++) idx += (MD[i] < xc) ? 1 : 0;
    return idx;
}
__device__ __forceinline__ float rcf_dev(float x, float alpha,
                                         const float* __restrict__ LN,
                                         const float* __restrict__ MD) {
    return LN[rcf_idx(x, alpha, MD)] * alpha;
}

// ---------------------------------------------------------------------------
// Quantization kernels
// ---------------------------------------------------------------------------
__global__ void quant_elem_kernel(const float* __restrict__ x,
                                  float* __restrict__ y, int n,
                                  const float* __restrict__ alpha_p) {
    __shared__ float LN[31], MD[30];
    if (threadIdx.x < 31) LN[threadIdx.x] = g_LN[threadIdx.x];
    if (threadIdx.x < 30) MD[threadIdx.x] = g_MIDS[threadIdx.x];
    __syncthreads();
    float a = alpha_p[0];
    int i = blockIdx.x * blockDim.x + threadIdx.x;
    if (i < n) y[i] = rcf_dev(x[i], a, LN, MD);
}

__global__ void quant_elem_i8_kernel(const float* __restrict__ x,
                                     int8_t* __restrict__ y, int n,
                                     const float* __restrict__ alpha_p) {
    __shared__ float MD[30];
    __shared__ int   L48[31];
    if (threadIdx.x < 30) MD[threadIdx.x] = g_MIDS[threadIdx.x];
    if (threadIdx.x < 31) L48[threadIdx.x] = g_LN48[threadIdx.x];
    __syncthreads();
    float a = alpha_p[0];
    int i0 = (blockIdx.x * blockDim.x + threadIdx.x) * 4;
    if (i0 < n) {
        float4 v = *reinterpret_cast<const float4*>(x + i0);
        char4 o;
        o.x = (int8_t)L48[rcf_idx(v.x, a, MD)];
        o.y = (int8_t)L48[rcf_idx(v.y, a, MD)];
        o.z = (int8_t)L48[rcf_idx(v.z, a, MD)];
        o.w = (int8_t)L48[rcf_idx(v.w, a, MD)];
        *reinterpret_cast<char4*>(y + i0) = o;
    }
}

__global__ void quant_weight_rows_kernel(const float* __restrict__ W,
                                         float* __restrict__ Wq,
                                         const float* __restrict__ alpha_p) {
    __shared__ float LN[31], MD[30];
    __shared__ double red[256];
    const int row = blockIdx.x, tid = threadIdx.x;
    if (tid < 31) LN[tid] = g_LN[tid];
    if (tid < 30) MD[tid] = g_MIDS[tid];
    const float* w = W + (long)row * E_;

    double s = 0.0;
    for (int c = tid; c < E_; c += 256) s += (double)w[c];
    red[tid] = s; __syncthreads();
    for (int o = 128; o > 0; o >>= 1) {
        if (tid < o) red[tid] += red[tid + o];
        __syncthreads();
    }
    double mu = red[0] / (double)E_;
    __syncthreads();

    double s2 = 0.0;
    for (int c = tid; c < E_; c += 256) {
        double d = (double)w[c] - mu;
        s2 += d * d;
    }
    red[tid] = s2; __syncthreads();
    for (int o = 128; o > 0; o >>= 1) {
        if (tid < o) red[tid] += red[tid + o];
        __syncthreads();
    }
    double var = red[0] / (double)E_;

    float inv = 1.0f / sqrtf((float)var + EPSQ);
    float muf = (float)mu;
    float a = alpha_p[0];
    for (int c = tid; c < E_; c += 256) {
        float wn = (w[c] - muf) * inv;
        Wq[(long)row * E_ + c] = rcf_dev(wn, a, LN, MD);
    }
}

__global__ void quant_weight_rows_i8_kernel(const float* __restrict__ W,
                                            int8_t* __restrict__ Wq,
                                            const float* __restrict__ alpha_p) {
    __shared__ float MD[30];
    __shared__ int   L48[31];
    __shared__ double red[256];
    const int row = blockIdx.x, tid = threadIdx.x;
    if (tid < 30) MD[tid] = g_MIDS[tid];
    if (tid < 31) L48[tid] = g_LN48[tid];
    const float* w = W + (long)row * E_;

    double s = 0.0;
    for (int c = tid; c < E_; c += 256) s += (double)w[c];
    red[tid] = s; __syncthreads();
    for (int o = 128; o > 0; o >>= 1) {
        if (tid < o) red[tid] += red[tid + o];
        __syncthreads();
    }
    double mu = red[0] / (double)E_;
    __syncthreads();

    double s2 = 0.0;
    for (int c = tid; c < E_; c += 256) {
        double d = (double)w[c] - mu;
        s2 += d * d;
    }
    red[tid] = s2; __syncthreads();
    for (int o = 128; o > 0; o >>= 1) {
        if (tid < o) red[tid] += red[tid + o];
        __syncthreads();
    }
    double var = red[0] / (double)E_;

    float inv = 1.0f / sqrtf((float)var + EPSQ);
    float muf = (float)mu;
    float a = alpha_p[0];
    for (int c = tid; c < E_; c += 256) {
        float wn = (w[c] - muf) * inv;
        Wq[(long)row * E_ + c] = (int8_t)L48[rcf_idx(wn, a, MD)];
    }
}

// ---------------------------------------------------------------------------
// int8 tensor-core projection GEMM (proven in round 2)
// ---------------------------------------------------------------------------
__device__ __forceinline__ void mma_i8(int* d, const uint32_t* a,
                                       const uint32_t* b) {
    asm volatile(
        "mma.sync.aligned.m16n8k32.row.col.s32.s8.s8.s32 "
        "{%0,%1,%2,%3}, {%4,%5,%6,%7}, {%8,%9}, {%0,%1,%2,%3};\n"
        : "+r"(d[0]), "+r"(d[1]), "+r"(d[2]), "+r"(d[3])
        : "r"(a[0]), "r"(a[1]), "r"(a[2]), "r"(a[3]), "r"(b[0]), "r"(b[1]));
}

#define I8_STRIDE 80

__global__ __launch_bounds__(256) void gemm_i8_kernel(
    const int8_t* __restrict__ A, const int8_t* __restrict__ B,
    float* __restrict__ C, const float* __restrict__ bias,
    const float* __restrict__ aA, const float* __restrict__ aB,
    int K, int N) {
    __shared__ __align__(16) int8_t As[128 * I8_STRIDE];
    __shared__ __align__(16) int8_t Bs[128 * I8_STRIDE];

    const int tid  = threadIdx.x;
    const int warp = tid >> 5;
    const int lane = tid & 31;
    const int g    = lane >> 2;
    const int tig  = lane & 3;

    const long z = blockIdx.z;
    A += z * (long)R_ * K;
    B += z * (long)N * K;
    C += z * (long)R_ * N;
    bias += z * N;

    const int m0 = blockIdx.y * 128;
    const int n0 = blockIdx.x * 128;
    const int wm = (warp >> 2) * 64;
    const int wn = (warp & 3) * 32;

    int acc[4][4][4];
#pragma unroll
    for (int a_ = 0; a_ < 4; a_++)
#pragma unroll
        for (int b_ = 0; b_ < 4; b_++)
#pragma unroll
            for (int c_ = 0; c_ < 4; c_++) acc[a_][b_][c_] = 0;

    const uint32_t* Aw = reinterpret_cast<const uint32_t*>(As);
    const uint32_t* Bw = reinterpret_cast<const uint32_t*>(Bs);
    const int WSTR = I8_STRIDE / 4;

    for (int k0 = 0; k0 < K; k0 += 64) {
#pragma unroll
        for (int it = 0; it < 2; it++) {
            int idx = it * 256 + tid;
            int row = idx >> 2, c = idx & 3;
            *reinterpret_cast<int4*>(&As[row * I8_STRIDE + c * 16]) =
                *reinterpret_cast<const int4*>(A + (long)(m0 + row) * K + k0 + c * 16);
            *reinterpret_cast<int4*>(&Bs[row * I8_STRIDE + c * 16]) =
                *reinterpret_cast<const int4*>(B + (long)(n0 + row) * K + k0 + c * 16);
        }
        __syncthreads();

#pragma unroll
        for (int ks = 0; ks < 2; ks++) {
            uint32_t af[4][4], bf[4][2];
#pragma unroll
            for (int mt = 0; mt < 4; mt++) {
                int base = (wm + mt * 16 + g) * WSTR + ks * 8 + tig;
                af[mt][0] = Aw[base];
                af[mt][1] = Aw[base + 8 * WSTR];
                af[mt][2] = Aw[base + 4];
                af[mt][3] = Aw[base + 8 * WSTR + 4];
            }
#pragma unroll
            for (int nt = 0; nt < 4; nt++) {
                int base = (wn + nt * 8 + g) * WSTR + ks * 8 + tig;
                bf[nt][0] = Bw[base];
                bf[nt][1] = Bw[base + 4];
            }
#pragma unroll
            for (int mt = 0; mt < 4; mt++)
#pragma unroll
                for (int nt = 0; nt < 4; nt++)
                    mma_i8(acc[mt][nt], af[mt], bf[nt]);
        }
        __syncthreads();
    }

    const float scale = __ldg(aA) * __ldg(aB) * (1.0f / 2304.0f);
#pragma unroll
    for (int mt = 0; mt < 4; mt++) {
#pragma unroll
        for (int nt = 0; nt < 4; nt++) {
            int row = m0 + wm + mt * 16 + g;
            int col = n0 + wn + nt * 8 + tig * 2;
            float b0 = bias[col], b1 = bias[col + 1];
            float2 v0, v1;
            v0.x = (float)acc[mt][nt][0] * scale + b0;
            v0.y = (float)acc[mt][nt][1] * scale + b1;
            v1.x = (float)acc[mt][nt][2] * scale + b0;
            v1.y = (float)acc[mt][nt][3] * scale + b1;
            *reinterpret_cast<float2*>(C + (long)row * N + col) = v0;
            *reinterpret_cast<float2*>(C + (long)(row + 8) * N + col) = v1;
        }
    }
}

// ---------------------------------------------------------------------------
// Per-head transpose of vp: vpT[z][d][t] = vp[t*4096 + 64*z + d]
// ---------------------------------------------------------------------------
__global__ void transpose_v_kernel(const float* __restrict__ vp,
                                   float* __restrict__ vpT) {
    __shared__ float tile[32][33];
    const int z = blockIdx.z;
    const int t0 = blockIdx.x * 32;
    const int d0 = blockIdx.y * 32;
    const float* src = vp + 64L * z;
    float* dst = vpT + (long)z * D_ * S_;
    for (int r = threadIdx.y; r < 32; r += 8)
        tile[r][threadIdx.x] = src[(long)(t0 + r) * 4096 + d0 + threadIdx.x];
    __syncthreads();
    for (int r = threadIdx.y; r < 32; r += 8)
        dst[(long)(d0 + r) * S_ + t0 + threadIdx.x] = tile[threadIdx.x][r];
}

// ---------------------------------------------------------------------------
// fp16x2-split (3-pass) fp32-precision GEMM on legacy mma.sync m16n8k16:
//   C[z][m,n] = scale * sum_k A[z][m,k]*B[z][n,k] (+bias[n])
// A: fp32, row m at A + z*bsA + m*sAm, K-contiguous
// B: fp32, row n at B + z*bsB + n*sBn, K-contiguous
// Each fp32 operand chunk splits to hi/lo fp16 planes in smem; accumulate
// hi*hi + hi*lo + lo*hi in the fp32 mma accumulator (residual rel ~2^-22).
// BM=128, BN=NT (64 or 128), BK=32. 256 thr = 8 warps. Register-prefetch
// double buffering for global loads.
// ---------------------------------------------------------------------------
__device__ __forceinline__ void mma_f16(float* d, const uint32_t* a,
                                        const uint32_t* b) {
    asm volatile(
        "mma.sync.aligned.m16n8k16.row.col.f32.f16.f16.f32 "
        "{%0,%1,%2,%3}, {%4,%5,%6,%7}, {%8,%9}, {%0,%1,%2,%3};\n"
        : "+f"(d[0]), "+f"(d[1]), "+f"(d[2]), "+f"(d[3])
        : "r"(a[0]), "r"(a[1]), "r"(a[2]), "r"(a[3]), "r"(b[0]), "r"(b[1]));
}

// split a float4 into hi/lo packed half2 word pairs
__device__ __forceinline__ void split4(const float4& v, uint2& hi, uint2& lo) {
    __half2 h01 = __floats2half2_rn(v.x, v.y);
    __half2 h23 = __floats2half2_rn(v.z, v.w);
    __half2 l01 = __floats2half2_rn(v.x - __low2float(h01),
                                    v.y - __high2float(h01));
    __half2 l23 = __floats2half2_rn(v.z - __low2float(h23),
                                    v.w - __high2float(h23));
    hi.x = *reinterpret_cast<uint32_t*>(&h01);
    hi.y = *reinterpret_cast<uint32_t*>(&h23);
    lo.x = *reinterpret_cast<uint32_t*>(&l01);
    lo.y = *reinterpret_cast<uint32_t*>(&l23);
}

#define F16_STRIDE_H 40   // halves per smem row (80 bytes)

template <int NT>
__global__ __launch_bounds__(256) void gemm_f16x3_kernel(
    const float* __restrict__ A, const float* __restrict__ B,
    float* __restrict__ C, const float* __restrict__ bias,
    int K, long sAm, long sBn, long sCm, long bsA, long bsB, long bsC,
    float scale) {
    constexpr int WCOLS = NT / 32;             // warps along n
    constexpr int WM    = 128 / (8 / WCOLS);   // warp tile rows
    constexpr int MT    = WM / 16;             // mma tiles along m per warp
    constexpr int LB    = NT / 32;             // B float4 loads per thread

    __shared__ __align__(16) __half Ah[128 * F16_STRIDE_H];
    __shared__ __align__(16) __half Al[128 * F16_STRIDE_H];
    __shared__ __align__(16) __half Bh[NT * F16_STRIDE_H];
    __shared__ __align__(16) __half Bl[NT * F16_STRIDE_H];

    const int tid  = threadIdx.x;
    const int warp = tid >> 5;
    const int lane = tid & 31;
    const int g    = lane >> 2;
    const int tig  = lane & 3;

    const long z = blockIdx.z;
    A += z * bsA; B += z * bsB; C += z * bsC;
    const int m0 = blockIdx.y * 128;
    const int n0 = blockIdx.x * NT;
    const int wm = (warp / WCOLS) * WM;
    const int wn = (warp % WCOLS) * 32;

    float acc[MT][4][4];
#pragma unroll
    for (int mt = 0; mt < MT; mt++)
#pragma unroll
        for (int nt = 0; nt < 4; nt++)
#pragma unroll
            for (int c = 0; c < 4; c++) acc[mt][nt][c] = 0.0f;

    const uint32_t* Ahw = reinterpret_cast<const uint32_t*>(Ah);
    const uint32_t* Alw = reinterpret_cast<const uint32_t*>(Al);
    const uint32_t* Bhw = reinterpret_cast<const uint32_t*>(Bh);
    const uint32_t* Blw = reinterpret_cast<const uint32_t*>(Bl);
    const int WSTR = F16_STRIDE_H / 2;   // 20 words per row

    // register prefetch buffers: 4 float4 for A, LB for B
    float4 pa[4], pb[LB];
#pragma unroll
    for (int it = 0; it < 4; it++) {
        int idx = it * 256 + tid;
        pa[it] = *reinterpret_cast<const float4*>(
            A + (long)(m0 + (idx >> 3)) * sAm + (idx & 7) * 4);
    }
#pragma unroll
    for (int it = 0; it < LB; it++) {
        int idx = it * 256 + tid;
        pb[it] = *reinterpret_cast<const float4*>(
            B + (long)(n0 + (idx >> 3)) * sBn + (idx & 7) * 4);
    }

    for (int k0 = 0; k0 < K; k0 += 32) {
        // store prefetched chunk (split) to smem; smem row = 80 bytes = 10 uint2
#pragma unroll
        for (int it = 0; it < 4; it++) {
            int idx = it * 256 + tid;
            int row = idx >> 3, qd = idx & 7;
            uint2 hi, lo;
            split4(pa[it], hi, lo);
            reinterpret_cast<uint2*>(Ah)[row * 10 + qd] = hi;
            reinterpret_cast<uint2*>(Al)[row * 10 + qd] = lo;
        }
#pragma unroll
        for (int it = 0; it < LB; it++) {
            int idx = it * 256 + tid;
            int row = idx >> 3, qd = idx & 7;
            uint2 hi, lo;
            split4(pb[it], hi, lo);
            reinterpret_cast<uint2*>(Bh)[row * 10 + qd] = hi;
            reinterpret_cast<uint2*>(Bl)[row * 10 + qd] = lo;
        }
        __syncthreads();

        // prefetch next chunk while computing this one
        if (k0 + 32 < K) {
#pragma unroll
            for (int it = 0; it < 4; it++) {
                int idx = it * 256 + tid;
                pa[it] = *reinterpret_cast<const float4*>(
                    A + (long)(m0 + (idx >> 3)) * sAm + k0 + 32 + (idx & 7) * 4);
            }
#pragma unroll
            for (int it = 0; it < LB; it++) {
                int idx = it * 256 + tid;
                pb[it] = *reinterpret_cast<const float4*>(
                    B + (long)(n0 + (idx >> 3)) * sBn + k0 + 32 + (idx & 7) * 4);
            }
        }

#pragma unroll
        for (int ks = 0; ks < 2; ks++) {
            uint32_t ah[MT][4], al[MT][4], bh[4][2], bl[4][2];
#pragma unroll
            for (int mt = 0; mt < MT; mt++) {
                int base = (wm + mt * 16 + g) * WSTR + ks * 8 + tig;
                ah[mt][0] = Ahw[base];
                ah[mt][1] = Ahw[base + 8 * WSTR];
                ah[mt][2] = Ahw[base + 4];
                ah[mt][3] = Ahw[base + 8 * WSTR + 4];
                al[mt][0] = Alw[base];
                al[mt][1] = Alw[base + 8 * WSTR];
                al[mt][2] = Alw[base + 4];
                al[mt][3] = Alw[base + 8 * WSTR + 4];
            }
#pragma unroll
            for (int nt = 0; nt < 4; nt++) {
                int base = (wn + nt * 8 + g) * WSTR + ks * 8 + tig;
                bh[nt][0] = Bhw[base];
                bh[nt][1] = Bhw[base + 4];
                bl[nt][0] = Blw[base];
                bl[nt][1] = Blw[base + 4];
            }
#pragma unroll
            for (int mt = 0; mt < MT; mt++)
#pragma unroll
                for (int nt = 0; nt < 4; nt++) {
                    mma_f16(acc[mt][nt], ah[mt], bh[nt]);
                    mma_f16(acc[mt][nt], ah[mt], bl[nt]);
                    mma_f16(acc[mt][nt], al[mt], bh[nt]);
                }
        }
        __syncthreads();
    }

    // epilogue
#pragma unroll
    for (int mt = 0; mt < MT; mt++) {
#pragma unroll
        for (int nt = 0; nt < 4; nt++) {
            long row = m0 + wm + mt * 16 + g;
            long col = n0 + wn + nt * 8 + tig * 2;
            float b0 = 0.0f, b1 = 0.0f;
            if (bias) { b0 = bias[col]; b1 = bias[col + 1]; }
            float2 v0, v1;
            v0.x = acc[mt][nt][0] * scale + b0;
            v0.y = acc[mt][nt][1] * scale + b1;
            v1.x = acc[mt][nt][2] * scale + b0;
            v1.y = acc[mt][nt][3] * scale + b1;
            *reinterpret_cast<float2*>(C + row * sCm + col) = v0;
            *reinterpret_cast<float2*>(C + (row + 8) * sCm + col) = v1;
        }
    }
}

// ---------------------------------------------------------------------------
// Row softmax over 1024 columns, in place. One block (256 thr) per row.
// Warp-shuffle reductions (2 block syncs total).
// ---------------------------------------------------------------------------
__global__ void softmax_rows_kernel(float* __restrict__ P) {
    __shared__ float red[8];
    const long row = blockIdx.x;
    float* p = P + row * (long)S_;
    const int tid = threadIdx.x, lane = tid & 31, warp = tid >> 5;

    float4 v = reinterpret_cast<float4*>(p)[tid];
    float m = fmaxf(fmaxf(v.x, v.y), fmaxf(v.z, v.w));
#pragma unroll
    for (int o = 16; o > 0; o >>= 1)
        m = fmaxf(m, __shfl_xor_sync(0xffffffffu, m, o));
    if (lane == 0) red[warp] = m;
    __syncthreads();
    float M = red[0];
#pragma unroll
    for (int i = 1; i < 8; i++) M = fmaxf(M, red[i]);

    v.x = expf(v.x - M); v.y = expf(v.y - M);
    v.z = expf(v.z - M); v.w = expf(v.w - M);
    float s = v.x + v.y + v.z + v.w;
#pragma unroll
    for (int o = 16; o > 0; o >>= 1)
        s += __shfl_xor_sync(0xffffffffu, s, o);
    __syncthreads();
    if (lane == 0) red[warp] = s;
    __syncthreads();
    float T = red[0];
#pragma unroll
    for (int i = 1; i < 8; i++) T += red[i];
    float inv = 1.0f / T;
    v.x *= inv; v.y *= inv; v.z *= inv; v.w *= inv;
    reinterpret_cast<float4*>(p)[tid] = v;
}

// ---------------------------------------------------------------------------
// Orchestration.
// ---------------------------------------------------------------------------
extern "C" void kernel_launch(void* const* d_in, const int* in_sizes, int n_in,
                              void* d_out, int out_size) {
    const float* q    = (const float*)d_in[0];
    const float* k    = (const float*)d_in[1];
    const float* v    = (const float*)d_in[2];
    const float* Wi   = (const float*)d_in[3];
    const float* bi   = (const float*)d_in[4];
    const float* Wo   = (const float*)d_in[5];
    const float* bo   = (const float*)d_in[6];
    const float* a_act = (const float*)d_in[7];
    const float* a_wi  = (const float*)d_in[8];
    const float* a_bi  = (const float*)d_in[9];
    const float* a_wo  = (const float*)d_in[10];
    const float* a_bo  = (const float*)d_in[11];
    float* out = (float*)d_out;

    int8_t *p_Wi8, *p_act8;
    float *p_Wo, *p_bi, *p_bo, *p_proj, *p_vpT, *p_ctx, *p_sc;
    cudaGetSymbolAddress((void**)&p_Wi8, g_Wi_i8);
    cudaGetSymbolAddress((void**)&p_act8, g_act_i8);
    cudaGetSymbolAddress((void**)&p_Wo, g_Wo);
    cudaGetSymbolAddress((void**)&p_bi, g_bi);
    cudaGetSymbolAddress((void**)&p_bo, g_bo);
    cudaGetSymbolAddress((void**)&p_proj, g_proj);
    cudaGetSymbolAddress((void**)&p_vpT, g_vpT);
    cudaGetSymbolAddress((void**)&p_ctx, g_ctx);
    cudaGetSymbolAddress((void**)&p_sc, g_scores);

    const long RE = (long)R_ * E_;
    float* p_qp = p_proj;
    float* p_kp = p_proj + RE;
    float* p_vp = p_proj + 2 * RE;

    init_tables_kernel<<<1, 1>>>();

    // Weight + bias quantization
    quant_weight_rows_i8_kernel<<<3 * E_, 256>>>(Wi, p_Wi8, a_wi);
    quant_weight_rows_kernel<<<E_, 256>>>(Wo, p_Wo, a_wo);
    quant_elem_kernel<<<(3 * E_ + 255) / 256, 256>>>(bi, p_bi, 3 * E_, a_bi);
    quant_elem_kernel<<<(E_ + 255) / 256, 256>>>(bo, p_bo, E_, a_bo);

    // Activation quantization -> int8 k-values
    quant_elem_i8_kernel<<<RE / 1024, 256>>>(q, p_act8, RE, a_act);
    quant_elem_i8_kernel<<<RE / 1024, 256>>>(k, p_act8 + RE, RE, a_act);
    quant_elem_i8_kernel<<<RE / 1024, 256>>>(v, p_act8 + 2 * RE, RE, a_act);

    // Projections via int8 tensor cores (exact)
    gemm_i8_kernel<<<dim3(E_ / 128, R_ / 128, 3), 256>>>(
        p_act8, p_Wi8, p_proj, p_bi, a_act, a_wi, E_, E_);

    // Transpose vp per head for the PV GEMM
    transpose_v_kernel<<<dim3(S_ / 32, D_ / 32, Z_), dim3(32, 8)>>>(p_vp, p_vpT);

    // Scores: per z: S[s,t] = 0.125 * qh[s,:].kh[t,:]   (M=N=1024, K=64)
    gemm_f16x3_kernel<128><<<dim3(8, 8, Z_), 256>>>(
        p_qp, p_kp, p_sc, nullptr, D_,
        (long)(B_ * E_), (long)(B_ * E_), (long)S_,
        64L, 64L, (long)S_ * S_, 0.125f);

    // Softmax over key positions
    softmax_rows_kernel<<<Z_ * S_, 256>>>(p_sc);

    // PV: per z: ctx[s,d] = sum_t attn[s,t] * vpT[d,t]  (M=1024, N=64, K=1024)
    gemm_f16x3_kernel<64><<<dim3(1, 8, Z_), 256>>>(
        p_sc, p_vpT, p_ctx, nullptr, S_,
        (long)S_, (long)S_, (long)(B_ * E_),
        (long)S_ * S_, (long)D_ * S_, 64L, 1.0f);

    // Output projection: out = ctx @ Wo^T + bo  (M=4096, N=1024, K=1024)
    gemm_f16x3_kernel<128><<<dim3(8, 32, 1), 256>>>(
        p_ctx, p_Wo, out, p_bo, E_,
        (long)E_, (long)E_, (long)E_, 0L, 0L, 0L, 1.0f);
}

// round 10
// speedup vs baseline: 4.3909x; 1.3680x over previous
#include <cuda_runtime.h>
#include <cuda_fp16.h>
#include <math.h>
#include <stdint.h>

#define EPSQ 1e-5f

// Problem sizes (fixed by the reference setup_inputs)
#define S_ 1024
#define B_ 4
#define E_ 1024
#define H_ 16
#define D_ 64
#define R_ (S_*B_)   // 4096 flattened (s,b) rows
#define Z_ (B_*H_)   // 64 batched heads

// ---------------------------------------------------------------------------
// Static device scratch (no runtime allocation allowed)
// ---------------------------------------------------------------------------
__device__ float g_LN[31];
__device__ float g_MIDS[30];
__device__ int   g_LN48[31];

__device__ __align__(16) int8_t g_Wi_i8[3*E_*E_];
__device__ __align__(16) float  g_Wo[E_*E_];
__device__ __align__(16) float  g_bi[3*E_];
__device__ __align__(16) float  g_bo[E_];
__device__ __align__(16) int8_t g_act_i8[3L*R_*E_];
__device__ __align__(16) float  g_proj[3L*R_*E_];     // qp,kp,vp
__device__ __align__(16) float  g_vpT[(long)Z_*D_*S_];// vp transposed per head
__device__ __align__(16) float  g_ctx[R_*E_];

// ---------------------------------------------------------------------------
// APoT tables (exact float emulation of the numpy construction)
// ---------------------------------------------------------------------------
__global__ void init_tables_kernel() {
    const float pos[15] = {0.03125f, 0.0625f, 0.09375f, 0.125f, 0.1875f,
                           0.25f, 0.28125f, 0.375f, 0.5f, 0.5625f,
                           0.75f, 1.0f, 1.03125f, 1.125f, 1.5f};
    const float G = (float)(1.0 / 1.5);
    for (int i = 0; i < 15; i++) {
        g_LN[i]      = (-pos[14 - i]) * G;
        g_LN[16 + i] = pos[i] * G;
    }
    g_LN[15] = 0.0f;
    for (int i = 0; i < 30; i++)
        g_MIDS[i] = (g_LN[i] + g_LN[i + 1]) * 0.5f;
    for (int i = 0; i < 31; i++)
        g_LN48[i] = (int)lrintf(g_LN[i] * 48.0f);
}

__device__ __forceinline__ int rcf_idx(float x, float alpha,
                                       const float* __restrict__ MD) {
    float xn = x / (alpha + EPSQ);
    float xc = fminf(1.0f, fmaxf(-1.0f, xn));
    int idx = 0;
#pragma unroll
    for (int i = 0; i < 30; i++) idx += (MD[i] < xc) ? 1 : 0;
    return idx;
}
__device__ __forceinline__ float rcf_dev(float x, float alpha,
                                         const float* __restrict__ LN,
                                         const float* __restrict__ MD) {
    return LN[rcf_idx(x, alpha, MD)] * alpha;
}

// ---------------------------------------------------------------------------
// Quantization kernels
// ---------------------------------------------------------------------------
__global__ void quant_elem_kernel(const float* __restrict__ x,
                                  float* __restrict__ y, int n,
                                  const float* __restrict__ alpha_p) {
    __shared__ float LN[31], MD[30];
    if (threadIdx.x < 31) LN[threadIdx.x] = g_LN[threadIdx.x];
    if (threadIdx.x < 30) MD[threadIdx.x] = g_MIDS[threadIdx.x];
    __syncthreads();
    float a = alpha_p[0];
    int i = blockIdx.x * blockDim.x + threadIdx.x;
    if (i < n) y[i] = rcf_dev(x[i], a, LN, MD);
}

__global__ void quant_elem_i8_kernel(const float* __restrict__ x,
                                     int8_t* __restrict__ y, int n,
                                     const float* __restrict__ alpha_p) {
    __shared__ float MD[30];
    __shared__ int   L48[31];
    if (threadIdx.x < 30) MD[threadIdx.x] = g_MIDS[threadIdx.x];
    if (threadIdx.x < 31) L48[threadIdx.x] = g_LN48[threadIdx.x];
    __syncthreads();
    float a = alpha_p[0];
    int i0 = (blockIdx.x * blockDim.x + threadIdx.x) * 4;
    if (i0 < n) {
        float4 v = *reinterpret_cast<const float4*>(x + i0);
        char4 o;
        o.x = (int8_t)L48[rcf_idx(v.x, a, MD)];
        o.y = (int8_t)L48[rcf_idx(v.y, a, MD)];
        o.z = (int8_t)L48[rcf_idx(v.z, a, MD)];
        o.w = (int8_t)L48[rcf_idx(v.w, a, MD)];
        *reinterpret_cast<char4*>(y + i0) = o;
    }
}

__global__ void quant_weight_rows_kernel(const float* __restrict__ W,
                                         float* __restrict__ Wq,
                                         const float* __restrict__ alpha_p) {
    __shared__ float LN[31], MD[30];
    __shared__ double red[256];
    const int row = blockIdx.x, tid = threadIdx.x;
    if (tid < 31) LN[tid] = g_LN[tid];
    if (tid < 30) MD[tid] = g_MIDS[tid];
    const float* w = W + (long)row * E_;

    double s = 0.0;
    for (int c = tid; c < E_; c += 256) s += (double)w[c];
    red[tid] = s; __syncthreads();
    for (int o = 128; o > 0; o >>= 1) {
        if (tid < o) red[tid] += red[tid + o];
        __syncthreads();
    }
    double mu = red[0] / (double)E_;
    __syncthreads();

    double s2 = 0.0;
    for (int c = tid; c < E_; c += 256) {
        double d = (double)w[c] - mu;
        s2 += d * d;
    }
    red[tid] = s2; __syncthreads();
    for (int o = 128; o > 0; o >>= 1) {
        if (tid < o) red[tid] += red[tid + o];
        __syncthreads();
    }
    double var = red[0] / (double)E_;

    float inv = 1.0f / sqrtf((float)var + EPSQ);
    float muf = (float)mu;
    float a = alpha_p[0];
    for (int c = tid; c < E_; c += 256) {
        float wn = (w[c] - muf) * inv;
        Wq[(long)row * E_ + c] = rcf_dev(wn, a, LN, MD);
    }
}

__global__ void quant_weight_rows_i8_kernel(const float* __restrict__ W,
                                            int8_t* __restrict__ Wq,
                                            const float* __restrict__ alpha_p) {
    __shared__ float MD[30];
    __shared__ int   L48[31];
    __shared__ double red[256];
    const int row = blockIdx.x, tid = threadIdx.x;
    if (tid < 30) MD[tid] = g_MIDS[tid];
    if (tid < 31) L48[tid] = g_LN48[tid];
    const float* w = W + (long)row * E_;

    double s = 0.0;
    for (int c = tid; c < E_; c += 256) s += (double)w[c];
    red[tid] = s; __syncthreads();
    for (int o = 128; o > 0; o >>= 1) {
        if (tid < o) red[tid] += red[tid + o];
        __syncthreads();
    }
    double mu = red[0] / (double)E_;
    __syncthreads();

    double s2 = 0.0;
    for (int c = tid; c < E_; c += 256) {
        double d = (double)w[c] - mu;
        s2 += d * d;
    }
    red[tid] = s2; __syncthreads();
    for (int o = 128; o > 0; o >>= 1) {
        if (tid < o) red[tid] += red[tid + o];
        __syncthreads();
    }
    double var = red[0] / (double)E_;

    float inv = 1.0f / sqrtf((float)var + EPSQ);
    float muf = (float)mu;
    float a = alpha_p[0];
    for (int c = tid; c < E_; c += 256) {
        float wn = (w[c] - muf) * inv;
        Wq[(long)row * E_ + c] = (int8_t)L48[rcf_idx(wn, a, MD)];
    }
}

// ---------------------------------------------------------------------------
// int8 tensor-core projection GEMM (proven in round 2)
// ---------------------------------------------------------------------------
__device__ __forceinline__ void mma_i8(int* d, const uint32_t* a,
                                       const uint32_t* b) {
    asm volatile(
        "mma.sync.aligned.m16n8k32.row.col.s32.s8.s8.s32 "
        "{%0,%1,%2,%3}, {%4,%5,%6,%7}, {%8,%9}, {%0,%1,%2,%3};\n"
        : "+r"(d[0]), "+r"(d[1]), "+r"(d[2]), "+r"(d[3])
        : "r"(a[0]), "r"(a[1]), "r"(a[2]), "r"(a[3]), "r"(b[0]), "r"(b[1]));
}

#define I8_STRIDE 80

__global__ __launch_bounds__(256) void gemm_i8_kernel(
    const int8_t* __restrict__ A, const int8_t* __restrict__ B,
    float* __restrict__ C, const float* __restrict__ bias,
    const float* __restrict__ aA, const float* __restrict__ aB,
    int K, int N) {
    __shared__ __align__(16) int8_t As[128 * I8_STRIDE];
    __shared__ __align__(16) int8_t Bs[128 * I8_STRIDE];

    const int tid  = threadIdx.x;
    const int warp = tid >> 5;
    const int lane = tid & 31;
    const int g    = lane >> 2;
    const int tig  = lane & 3;

    const long z = blockIdx.z;
    A += z * (long)R_ * K;
    B += z * (long)N * K;
    C += z * (long)R_ * N;
    bias += z * N;

    const int m0 = blockIdx.y * 128;
    const int n0 = blockIdx.x * 128;
    const int wm = (warp >> 2) * 64;
    const int wn = (warp & 3) * 32;

    int acc[4][4][4];
#pragma unroll
    for (int a_ = 0; a_ < 4; a_++)
#pragma unroll
        for (int b_ = 0; b_ < 4; b_++)
#pragma unroll
            for (int c_ = 0; c_ < 4; c_++) acc[a_][b_][c_] = 0;

    const uint32_t* Aw = reinterpret_cast<const uint32_t*>(As);
    const uint32_t* Bw = reinterpret_cast<const uint32_t*>(Bs);
    const int WSTR = I8_STRIDE / 4;

    for (int k0 = 0; k0 < K; k0 += 64) {
#pragma unroll
        for (int it = 0; it < 2; it++) {
            int idx = it * 256 + tid;
            int row = idx >> 2, c = idx & 3;
            *reinterpret_cast<int4*>(&As[row * I8_STRIDE + c * 16]) =
                *reinterpret_cast<const int4*>(A + (long)(m0 + row) * K + k0 + c * 16);
            *reinterpret_cast<int4*>(&Bs[row * I8_STRIDE + c * 16]) =
                *reinterpret_cast<const int4*>(B + (long)(n0 + row) * K + k0 + c * 16);
        }
        __syncthreads();

#pragma unroll
        for (int ks = 0; ks < 2; ks++) {
            uint32_t af[4][4], bf[4][2];
#pragma unroll
            for (int mt = 0; mt < 4; mt++) {
                int base = (wm + mt * 16 + g) * WSTR + ks * 8 + tig;
                af[mt][0] = Aw[base];
                af[mt][1] = Aw[base + 8 * WSTR];
                af[mt][2] = Aw[base + 4];
                af[mt][3] = Aw[base + 8 * WSTR + 4];
            }
#pragma unroll
            for (int nt = 0; nt < 4; nt++) {
                int base = (wn + nt * 8 + g) * WSTR + ks * 8 + tig;
                bf[nt][0] = Bw[base];
                bf[nt][1] = Bw[base + 4];
            }
#pragma unroll
            for (int mt = 0; mt < 4; mt++)
#pragma unroll
                for (int nt = 0; nt < 4; nt++)
                    mma_i8(acc[mt][nt], af[mt], bf[nt]);
        }
        __syncthreads();
    }

    const float scale = __ldg(aA) * __ldg(aB) * (1.0f / 2304.0f);
#pragma unroll
    for (int mt = 0; mt < 4; mt++) {
#pragma unroll
        for (int nt = 0; nt < 4; nt++) {
            int row = m0 + wm + mt * 16 + g;
            int col = n0 + wn + nt * 8 + tig * 2;
            float b0 = bias[col], b1 = bias[col + 1];
            float2 v0, v1;
            v0.x = (float)acc[mt][nt][0] * scale + b0;
            v0.y = (float)acc[mt][nt][1] * scale + b1;
            v1.x = (float)acc[mt][nt][2] * scale + b0;
            v1.y = (float)acc[mt][nt][3] * scale + b1;
            *reinterpret_cast<float2*>(C + (long)row * N + col) = v0;
            *reinterpret_cast<float2*>(C + (long)(row + 8) * N + col) = v1;
        }
    }
}

// ---------------------------------------------------------------------------
// Per-head transpose of vp: vpT[z][d][t] = vp[t*4096 + 64*z + d]
// ---------------------------------------------------------------------------
__global__ void transpose_v_kernel(const float* __restrict__ vp,
                                   float* __restrict__ vpT) {
    __shared__ float tile[32][33];
    const int z = blockIdx.z;
    const int t0 = blockIdx.x * 32;
    const int d0 = blockIdx.y * 32;
    const float* src = vp + 64L * z;
    float* dst = vpT + (long)z * D_ * S_;
    for (int r = threadIdx.y; r < 32; r += 8)
        tile[r][threadIdx.x] = src[(long)(t0 + r) * 4096 + d0 + threadIdx.x];
    __syncthreads();
    for (int r = threadIdx.y; r < 32; r += 8)
        dst[(long)(d0 + r) * S_ + t0 + threadIdx.x] = tile[threadIdx.x][r];
}

// ---------------------------------------------------------------------------
// fp16 helpers
// ---------------------------------------------------------------------------
__device__ __forceinline__ void mma_f16(float* d, const uint32_t* a,
                                        const uint32_t* b) {
    asm volatile(
        "mma.sync.aligned.m16n8k16.row.col.f32.f16.f16.f32 "
        "{%0,%1,%2,%3}, {%4,%5,%6,%7}, {%8,%9}, {%0,%1,%2,%3};\n"
        : "+f"(d[0]), "+f"(d[1]), "+f"(d[2]), "+f"(d[3])
        : "r"(a[0]), "r"(a[1]), "r"(a[2]), "r"(a[3]), "r"(b[0]), "r"(b[1]));
}

// split a float4 into hi/lo packed half2 word pairs
__device__ __forceinline__ void split4(const float4& v, uint2& hi, uint2& lo) {
    __half2 h01 = __floats2half2_rn(v.x, v.y);
    __half2 h23 = __floats2half2_rn(v.z, v.w);
    __half2 l01 = __floats2half2_rn(v.x - __low2float(h01),
                                    v.y - __high2float(h01));
    __half2 l23 = __floats2half2_rn(v.z - __low2float(h23),
                                    v.w - __high2float(h23));
    hi.x = *reinterpret_cast<uint32_t*>(&h01);
    hi.y = *reinterpret_cast<uint32_t*>(&h23);
    lo.x = *reinterpret_cast<uint32_t*>(&l01);
    lo.y = *reinterpret_cast<uint32_t*>(&l23);
}

__device__ __forceinline__ void split2(float a, float b, uint32_t& hi,
                                       uint32_t& lo) {
    __half2 h = __floats2half2_rn(a, b);
    __half2 l = __floats2half2_rn(a - __low2float(h), b - __high2float(h));
    hi = *reinterpret_cast<uint32_t*>(&h);
    lo = *reinterpret_cast<uint32_t*>(&l);
}

// ---------------------------------------------------------------------------
// Fused flash attention: scores (f16x3) + online softmax + PV (f16x3).
// Grid: (8 q-tiles, 64 heads). 256 threads, warp w owns q rows w*16..w*16+15.
// smem (dynamic 72KB): K hi/lo (128 rows x 64 halves, stride 36 words),
//                      Q-then-VT hi/lo (Q: 128x64 stride 36; VT: 64 rows x
//                      128 halves, stride 68 words).
// ---------------------------------------------------------------------------
#define KWORDS 36   // K/Q smem row stride in 32-bit words
#define VWORDS 68   // VT smem row stride in words
#define SM_K   18432
#define SM_QVT 18432
#define SM_TOTAL_FLASH (2*SM_K + 2*SM_QVT)   // 73728

__global__ __launch_bounds__(256) void flash_attn_kernel(
    const float* __restrict__ Q, const float* __restrict__ Kp,
    const float* __restrict__ VT, float* __restrict__ O) {
    extern __shared__ char sm[];
    uint32_t* KH = reinterpret_cast<uint32_t*>(sm);
    uint32_t* KL = reinterpret_cast<uint32_t*>(sm + SM_K);
    uint32_t* PH = reinterpret_cast<uint32_t*>(sm + 2 * SM_K);           // Q, then VT
    uint32_t* PL = reinterpret_cast<uint32_t*>(sm + 2 * SM_K + SM_QVT);

    const int tid = threadIdx.x;
    const int warp = tid >> 5, lane = tid & 31;
    const int g = lane >> 2, tig = lane & 3;
    const int z = blockIdx.y;
    const int q0 = blockIdx.x * 128;

    const float* Qb = Q + (long)z * 64;          // row s stride 4096
    const float* Kb = Kp + (long)z * 64;
    const float* Vb = VT + (long)z * D_ * S_;    // row d stride 1024

    // ---- stage Q tile (128 rows x 64 fp32 = 16 float4/row) split to PH/PL
#pragma unroll
    for (int it = 0; it < 8; it++) {
        int idx = it * 256 + tid;                // 2048 float4 total
        int row = idx >> 4, qd = idx & 15;       // 128 rows x 16 float4
        float4 v = *reinterpret_cast<const float4*>(
            Qb + (long)(q0 + row) * 4096 + qd * 4);
        uint2 hi, lo;
        split4(v, hi, lo);
        reinterpret_cast<uint2*>(PH)[row * 18 + qd] = hi;
        reinterpret_cast<uint2*>(PL)[row * 18 + qd] = lo;
    }
    __syncthreads();
    uint32_t qh[4][4], ql[4][4];
#pragma unroll
    for (int ks = 0; ks < 4; ks++) {
        int base = (warp * 16 + g) * KWORDS + ks * 8 + tig;
        qh[ks][0] = PH[base];
        qh[ks][1] = PH[base + 8 * KWORDS];
        qh[ks][2] = PH[base + 4];
        qh[ks][3] = PH[base + 8 * KWORDS + 4];
        ql[ks][0] = PL[base];
        ql[ks][1] = PL[base + 8 * KWORDS];
        ql[ks][2] = PL[base + 4];
        ql[ks][3] = PL[base + 8 * KWORDS + 4];
    }
    __syncthreads();

    float ctx[8][4];
#pragma unroll
    for (int d8 = 0; d8 < 8; d8++)
#pragma unroll
        for (int c = 0; c < 4; c++) ctx[d8][c] = 0.0f;
    float M0 = -1e30f, M1 = -1e30f, T0 = 0.0f, T1 = 0.0f;

    for (int t0 = 0; t0 < S_; t0 += 128) {
        // ---- load K tile (128 rows x 64 = 16 float4/row), split to KH/KL
#pragma unroll
        for (int it = 0; it < 8; it++) {
            int idx = it * 256 + tid;
            int row = idx >> 4, qd = idx & 15;
            float4 v = *reinterpret_cast<const float4*>(
                Kb + (long)(t0 + row) * 4096 + qd * 4);
            uint2 hi, lo;
            split4(v, hi, lo);
            reinterpret_cast<uint2*>(KH)[row * 18 + qd] = hi;
            reinterpret_cast<uint2*>(KL)[row * 18 + qd] = lo;
        }
        // ---- load VT tile (64 rows x 128 = 32 float4/row), split to PH/PL
#pragma unroll
        for (int it = 0; it < 8; it++) {
            int idx = it * 256 + tid;
            int row = idx >> 5, qd = idx & 31;
            float4 v = *reinterpret_cast<const float4*>(
                Vb + (long)row * 1024 + t0 + qd * 4);
            uint2 hi, lo;
            split4(v, hi, lo);
            reinterpret_cast<uint2*>(PH)[row * 34 + qd] = hi;
            reinterpret_cast<uint2*>(PL)[row * 34 + qd] = lo;
        }
        __syncthreads();

        // ---- S = Q K^T (f16x3), warp tile 16 x 128
        float acc[16][4];
#pragma unroll
        for (int nt = 0; nt < 16; nt++)
#pragma unroll
            for (int c = 0; c < 4; c++) acc[nt][c] = 0.0f;
#pragma unroll
        for (int nt = 0; nt < 16; nt++) {
#pragma unroll
            for (int ks = 0; ks < 4; ks++) {
                int base = (nt * 8 + g) * KWORDS + ks * 8 + tig;
                uint32_t bh[2] = {KH[base], KH[base + 4]};
                uint32_t bl[2] = {KL[base], KL[base + 4]};
                mma_f16(acc[nt], qh[ks], bh);
                mma_f16(acc[nt], qh[ks], bl);
                mma_f16(acc[nt], ql[ks], bh);
            }
        }

        // ---- scale + online softmax stats (rows g and g+8, quad shuffles)
        float m0 = -1e30f, m1 = -1e30f;
#pragma unroll
        for (int nt = 0; nt < 16; nt++) {
            acc[nt][0] *= 0.125f; acc[nt][1] *= 0.125f;
            acc[nt][2] *= 0.125f; acc[nt][3] *= 0.125f;
            m0 = fmaxf(m0, fmaxf(acc[nt][0], acc[nt][1]));
            m1 = fmaxf(m1, fmaxf(acc[nt][2], acc[nt][3]));
        }
        m0 = fmaxf(m0, __shfl_xor_sync(0xffffffffu, m0, 1));
        m0 = fmaxf(m0, __shfl_xor_sync(0xffffffffu, m0, 2));
        m1 = fmaxf(m1, __shfl_xor_sync(0xffffffffu, m1, 1));
        m1 = fmaxf(m1, __shfl_xor_sync(0xffffffffu, m1, 2));
        float Mn0 = fmaxf(M0, m0), Mn1 = fmaxf(M1, m1);
        float a0 = __expf(M0 - Mn0), a1 = __expf(M1 - Mn1);
        M0 = Mn0; M1 = Mn1;

        float s0 = 0.0f, s1 = 0.0f;
#pragma unroll
        for (int nt = 0; nt < 16; nt++) {
            acc[nt][0] = __expf(acc[nt][0] - M0);
            acc[nt][1] = __expf(acc[nt][1] - M0);
            acc[nt][2] = __expf(acc[nt][2] - M1);
            acc[nt][3] = __expf(acc[nt][3] - M1);
            s0 += acc[nt][0] + acc[nt][1];
            s1 += acc[nt][2] + acc[nt][3];
        }
        s0 += __shfl_xor_sync(0xffffffffu, s0, 1);
        s0 += __shfl_xor_sync(0xffffffffu, s0, 2);
        s1 += __shfl_xor_sync(0xffffffffu, s1, 1);
        s1 += __shfl_xor_sync(0xffffffffu, s1, 2);
        T0 = T0 * a0 + s0;
        T1 = T1 * a1 + s1;
#pragma unroll
        for (int d8 = 0; d8 < 8; d8++) {
            ctx[d8][0] *= a0; ctx[d8][1] *= a0;
            ctx[d8][2] *= a1; ctx[d8][3] *= a1;
        }

        // ---- PV: P (16x128, in regs as score-C-fragments) x VT (f16x3)
#pragma unroll
        for (int c = 0; c < 8; c++) {
            uint32_t ah[4], al[4];
            split2(acc[2 * c][0],     acc[2 * c][1],     ah[0], al[0]);
            split2(acc[2 * c][2],     acc[2 * c][3],     ah[1], al[1]);
            split2(acc[2 * c + 1][0], acc[2 * c + 1][1], ah[2], al[2]);
            split2(acc[2 * c + 1][2], acc[2 * c + 1][3], ah[3], al[3]);
#pragma unroll
            for (int d8 = 0; d8 < 8; d8++) {
                int base = (d8 * 8 + g) * VWORDS + c * 8 + tig;
                uint32_t bh[2] = {PH[base], PH[base + 4]};
                uint32_t bl[2] = {PL[base], PL[base + 4]};
                mma_f16(ctx[d8], ah, bh);
                mma_f16(ctx[d8], ah, bl);
                mma_f16(ctx[d8], al, bh);
            }
        }
        __syncthreads();
    }

    // ---- normalize and write ctx tile: rows q0+warp*16+g (+8), cols z*64+..
    float i0 = 1.0f / T0, i1 = 1.0f / T1;
    const long r0 = q0 + warp * 16 + g;
#pragma unroll
    for (int d8 = 0; d8 < 8; d8++) {
        int col = z * 64 + d8 * 8 + tig * 2;
        float2 v0, v1;
        v0.x = ctx[d8][0] * i0; v0.y = ctx[d8][1] * i0;
        v1.x = ctx[d8][2] * i1; v1.y = ctx[d8][3] * i1;
        *reinterpret_cast<float2*>(O + r0 * 4096 + col) = v0;
        *reinterpret_cast<float2*>(O + (r0 + 8) * 4096 + col) = v1;
    }
}

// ---------------------------------------------------------------------------
// fp16x2-split (3-pass) GEMM (proven round 8) — used for output projection
// ---------------------------------------------------------------------------
#define F16_STRIDE_H 40   // halves per smem row (80 bytes)

template <int NT>
__global__ __launch_bounds__(256) void gemm_f16x3_kernel(
    const float* __restrict__ A, const float* __restrict__ B,
    float* __restrict__ C, const float* __restrict__ bias,
    int K, long sAm, long sBn, long sCm, long bsA, long bsB, long bsC,
    float scale) {
    constexpr int WCOLS = NT / 32;
    constexpr int WM    = 128 / (8 / WCOLS);
    constexpr int MT    = WM / 16;
    constexpr int LB    = NT / 32;

    __shared__ __align__(16) __half Ah[128 * F16_STRIDE_H];
    __shared__ __align__(16) __half Al[128 * F16_STRIDE_H];
    __shared__ __align__(16) __half Bh[NT * F16_STRIDE_H];
    __shared__ __align__(16) __half Bl[NT * F16_STRIDE_H];

    const int tid  = threadIdx.x;
    const int warp = tid >> 5;
    const int lane = tid & 31;
    const int g    = lane >> 2;
    const int tig  = lane & 3;

    const long z = blockIdx.z;
    A += z * bsA; B += z * bsB; C += z * bsC;
    const int m0 = blockIdx.y * 128;
    const int n0 = blockIdx.x * NT;
    const int wm = (warp / WCOLS) * WM;
    const int wn = (warp % WCOLS) * 32;

    float acc[MT][4][4];
#pragma unroll
    for (int mt = 0; mt < MT; mt++)
#pragma unroll
        for (int nt = 0; nt < 4; nt++)
#pragma unroll
            for (int c = 0; c < 4; c++) acc[mt][nt][c] = 0.0f;

    const uint32_t* Ahw = reinterpret_cast<const uint32_t*>(Ah);
    const uint32_t* Alw = reinterpret_cast<const uint32_t*>(Al);
    const uint32_t* Bhw = reinterpret_cast<const uint32_t*>(Bh);
    const uint32_t* Blw = reinterpret_cast<const uint32_t*>(Bl);
    const int WSTR = F16_STRIDE_H / 2;

    float4 pa[4], pb[LB];
#pragma unroll
    for (int it = 0; it < 4; it++) {
        int idx = it * 256 + tid;
        pa[it] = *reinterpret_cast<const float4*>(
            A + (long)(m0 + (idx >> 3)) * sAm + (idx & 7) * 4);
    }
#pragma unroll
    for (int it = 0; it < LB; it++) {
        int idx = it * 256 + tid;
        pb[it] = *reinterpret_cast<const float4*>(
            B + (long)(n0 + (idx >> 3)) * sBn + (idx & 7) * 4);
    }

    for (int k0 = 0; k0 < K; k0 += 32) {
#pragma unroll
        for (int it = 0; it < 4; it++) {
            int idx = it * 256 + tid;
            int row = idx >> 3, qd = idx & 7;
            uint2 hi, lo;
            split4(pa[it], hi, lo);
            reinterpret_cast<uint2*>(Ah)[row * 10 + qd] = hi;
            reinterpret_cast<uint2*>(Al)[row * 10 + qd] = lo;
        }
#pragma unroll
        for (int it = 0; it < LB; it++) {
            int idx = it * 256 + tid;
            int row = idx >> 3, qd = idx & 7;
            uint2 hi, lo;
            split4(pb[it], hi, lo);
            reinterpret_cast<uint2*>(Bh)[row * 10 + qd] = hi;
            reinterpret_cast<uint2*>(Bl)[row * 10 + qd] = lo;
        }
        __syncthreads();

        if (k0 + 32 < K) {
#pragma unroll
            for (int it = 0; it < 4; it++) {
                int idx = it * 256 + tid;
                pa[it] = *reinterpret_cast<const float4*>(
                    A + (long)(m0 + (idx >> 3)) * sAm + k0 + 32 + (idx & 7) * 4);
            }
#pragma unroll
            for (int it = 0; it < LB; it++) {
                int idx = it * 256 + tid;
                pb[it] = *reinterpret_cast<const float4*>(
                    B + (long)(n0 + (idx >> 3)) * sBn + k0 + 32 + (idx & 7) * 4);
            }
        }

#pragma unroll
        for (int ks = 0; ks < 2; ks++) {
            uint32_t ah[MT][4], al[MT][4], bh[4][2], bl[4][2];
#pragma unroll
            for (int mt = 0; mt < MT; mt++) {
                int base = (wm + mt * 16 + g) * WSTR + ks * 8 + tig;
                ah[mt][0] = Ahw[base];
                ah[mt][1] = Ahw[base + 8 * WSTR];
                ah[mt][2] = Ahw[base + 4];
                ah[mt][3] = Ahw[base + 8 * WSTR + 4];
                al[mt][0] = Alw[base];
                al[mt][1] = Alw[base + 8 * WSTR];
                al[mt][2] = Alw[base + 4];
                al[mt][3] = Alw[base + 8 * WSTR + 4];
            }
#pragma unroll
            for (int nt = 0; nt < 4; nt++) {
                int base = (wn + nt * 8 + g) * WSTR + ks * 8 + tig;
                bh[nt][0] = Bhw[base];
                bh[nt][1] = Bhw[base + 4];
                bl[nt][0] = Blw[base];
                bl[nt][1] = Blw[base + 4];
            }
#pragma unroll
            for (int mt = 0; mt < MT; mt++)
#pragma unroll
                for (int nt = 0; nt < 4; nt++) {
                    mma_f16(acc[mt][nt], ah[mt], bh[nt]);
                    mma_f16(acc[mt][nt], ah[mt], bl[nt]);
                    mma_f16(acc[mt][nt], al[mt], bh[nt]);
                }
        }
        __syncthreads();
    }

#pragma unroll
    for (int mt = 0; mt < MT; mt++) {
#pragma unroll
        for (int nt = 0; nt < 4; nt++) {
            long row = m0 + wm + mt * 16 + g;
            long col = n0 + wn + nt * 8 + tig * 2;
            float b0 = 0.0f, b1 = 0.0f;
            if (bias) { b0 = bias[col]; b1 = bias[col + 1]; }
            float2 v0, v1;
            v0.x = acc[mt][nt][0] * scale + b0;
            v0.y = acc[mt][nt][1] * scale + b1;
            v1.x = acc[mt][nt][2] * scale + b0;
            v1.y = acc[mt][nt][3] * scale + b1;
            *reinterpret_cast<float2*>(C + row * sCm + col) = v0;
            *reinterpret_cast<float2*>(C + (row + 8) * sCm + col) = v1;
        }
    }
}

// ---------------------------------------------------------------------------
// Orchestration.
// ---------------------------------------------------------------------------
extern "C" void kernel_launch(void* const* d_in, const int* in_sizes, int n_in,
                              void* d_out, int out_size) {
    const float* q    = (const float*)d_in[0];
    const float* k    = (const float*)d_in[1];
    const float* v    = (const float*)d_in[2];
    const float* Wi   = (const float*)d_in[3];
    const float* bi   = (const float*)d_in[4];
    const float* Wo   = (const float*)d_in[5];
    const float* bo   = (const float*)d_in[6];
    const float* a_act = (const float*)d_in[7];
    const float* a_wi  = (const float*)d_in[8];
    const float* a_bi  = (const float*)d_in[9];
    const float* a_wo  = (const float*)d_in[10];
    const float* a_bo  = (const float*)d_in[11];
    float* out = (float*)d_out;

    int8_t *p_Wi8, *p_act8;
    float *p_Wo, *p_bi, *p_bo, *p_proj, *p_vpT, *p_ctx;
    cudaGetSymbolAddress((void**)&p_Wi8, g_Wi_i8);
    cudaGetSymbolAddress((void**)&p_act8, g_act_i8);
    cudaGetSymbolAddress((void**)&p_Wo, g_Wo);
    cudaGetSymbolAddress((void**)&p_bi, g_bi);
    cudaGetSymbolAddress((void**)&p_bo, g_bo);
    cudaGetSymbolAddress((void**)&p_proj, g_proj);
    cudaGetSymbolAddress((void**)&p_vpT, g_vpT);
    cudaGetSymbolAddress((void**)&p_ctx, g_ctx);

    const long RE = (long)R_ * E_;
    float* p_qp = p_proj;
    float* p_kp = p_proj + RE;
    float* p_vp = p_proj + 2 * RE;

    cudaFuncSetAttribute(flash_attn_kernel,
                         cudaFuncAttributeMaxDynamicSharedMemorySize,
                         SM_TOTAL_FLASH);

    init_tables_kernel<<<1, 1>>>();

    // Weight + bias quantization
    quant_weight_rows_i8_kernel<<<3 * E_, 256>>>(Wi, p_Wi8, a_wi);
    quant_weight_rows_kernel<<<E_, 256>>>(Wo, p_Wo, a_wo);
    quant_elem_kernel<<<(3 * E_ + 255) / 256, 256>>>(bi, p_bi, 3 * E_, a_bi);
    quant_elem_kernel<<<(E_ + 255) / 256, 256>>>(bo, p_bo, E_, a_bo);

    // Activation quantization -> int8 k-values
    quant_elem_i8_kernel<<<RE / 1024, 256>>>(q, p_act8, RE, a_act);
    quant_elem_i8_kernel<<<RE / 1024, 256>>>(k, p_act8 + RE, RE, a_act);
    quant_elem_i8_kernel<<<RE / 1024, 256>>>(v, p_act8 + 2 * RE, RE, a_act);

    // Projections via int8 tensor cores (exact)
    gemm_i8_kernel<<<dim3(E_ / 128, R_ / 128, 3), 256>>>(
        p_act8, p_Wi8, p_proj, p_bi, a_act, a_wi, E_, E_);

    // Transpose vp per head (B-operand layout for PV inside flash kernel)
    transpose_v_kernel<<<dim3(S_ / 32, D_ / 32, Z_), dim3(32, 8)>>>(p_vp, p_vpT);

    // Fused attention: scores + online softmax + PV -> ctx
    flash_attn_kernel<<<dim3(S_ / 128, Z_), 256, SM_TOTAL_FLASH>>>(
        p_qp, p_kp, p_vpT, p_ctx);

    // Output projection: out = ctx @ Wo^T + bo  (M=4096, N=1024, K=1024)
    gemm_f16x3_kernel<128><<<dim3(8, 32, 1), 256>>>(
        p_ctx, p_Wo, out, p_bo, E_,
        (long)E_, (long)E_, (long)E_, 0L, 0L, 0L, 1.0f);
}

// round 11
// speedup vs baseline: 4.8075x; 1.0949x over previous
#include <cuda_runtime.h>
#include <cuda_fp16.h>
#include <math.h>
#include <stdint.h>

#define EPSQ 1e-5f

// Problem sizes (fixed by the reference setup_inputs)
#define S_ 1024
#define B_ 4
#define E_ 1024
#define H_ 16
#define D_ 64
#define R_ (S_*B_)   // 4096 flattened (s,b) rows
#define Z_ (B_*H_)   // 64 batched heads

// ---------------------------------------------------------------------------
// Static device scratch (no runtime allocation allowed)
// ---------------------------------------------------------------------------
__device__ float g_LN[31];
__device__ float g_MIDS[30];
__device__ int   g_LN48[31];

__device__ __align__(16) int8_t g_Wi_i8[3*E_*E_];
__device__ __align__(16) __half g_Wo_h[E_*E_];        // Wo k-values (exact fp16)
__device__ __align__(16) float  g_bi[3*E_];
__device__ __align__(16) float  g_bo[E_];
__device__ __align__(16) int8_t g_act_i8[3L*R_*E_];
__device__ __align__(16) float  g_proj[3L*R_*E_];     // qp,kp,vp
__device__ __align__(16) float  g_vpT[(long)Z_*D_*S_];// vp transposed per head
__device__ __align__(16) float  g_ctx[R_*E_];

// ---------------------------------------------------------------------------
// APoT tables (exact float emulation of the numpy construction)
// ---------------------------------------------------------------------------
__global__ void init_tables_kernel() {
    const float pos[15] = {0.03125f, 0.0625f, 0.09375f, 0.125f, 0.1875f,
                           0.25f, 0.28125f, 0.375f, 0.5f, 0.5625f,
                           0.75f, 1.0f, 1.03125f, 1.125f, 1.5f};
    const float G = (float)(1.0 / 1.5);
    for (int i = 0; i < 15; i++) {
        g_LN[i]      = (-pos[14 - i]) * G;
        g_LN[16 + i] = pos[i] * G;
    }
    g_LN[15] = 0.0f;
    for (int i = 0; i < 30; i++)
        g_MIDS[i] = (g_LN[i] + g_LN[i + 1]) * 0.5f;
    for (int i = 0; i < 31; i++)
        g_LN48[i] = (int)lrintf(g_LN[i] * 48.0f);
}

__device__ __forceinline__ int rcf_idx(float x, float alpha,
                                       const float* __restrict__ MD) {
    float xn = x / (alpha + EPSQ);
    float xc = fminf(1.0f, fmaxf(-1.0f, xn));
    int idx = 0;
#pragma unroll
    for (int i = 0; i < 30; i++) idx += (MD[i] < xc) ? 1 : 0;
    return idx;
}
__device__ __forceinline__ float rcf_dev(float x, float alpha,
                                         const float* __restrict__ LN,
                                         const float* __restrict__ MD) {
    return LN[rcf_idx(x, alpha, MD)] * alpha;
}

// ---------------------------------------------------------------------------
// Bias quantization: bi (3072) and bo (1024) in ONE launch (16 blocks).
// ---------------------------------------------------------------------------
__global__ void quant_bias_kernel(const float* __restrict__ bi,
                                  const float* __restrict__ bo,
                                  float* __restrict__ ybi,
                                  float* __restrict__ ybo,
                                  const float* __restrict__ abi,
                                  const float* __restrict__ abo) {
    __shared__ float LN[31], MD[30];
    if (threadIdx.x < 31) LN[threadIdx.x] = g_LN[threadIdx.x];
    if (threadIdx.x < 30) MD[threadIdx.x] = g_MIDS[threadIdx.x];
    __syncthreads();
    int b = blockIdx.x;
    if (b < 12) {
        int i = b * 256 + threadIdx.x;
        ybi[i] = rcf_dev(bi[i], abi[0], LN, MD);
    } else {
        int i = (b - 12) * 256 + threadIdx.x;
        ybo[i] = rcf_dev(bo[i], abo[0], LN, MD);
    }
}

// ---------------------------------------------------------------------------
// Activation quantization -> int8 k-values; q/k/v in one z-batched launch.
// ---------------------------------------------------------------------------
__global__ void quant_act_i8_kernel(const float* __restrict__ q,
                                    const float* __restrict__ k,
                                    const float* __restrict__ v,
                                    int8_t* __restrict__ y,
                                    const float* __restrict__ alpha_p) {
    __shared__ float MD[30];
    __shared__ int   L48[31];
    if (threadIdx.x < 30) MD[threadIdx.x] = g_MIDS[threadIdx.x];
    if (threadIdx.x < 31) L48[threadIdx.x] = g_LN48[threadIdx.x];
    __syncthreads();
    const float* x = (blockIdx.y == 0) ? q : (blockIdx.y == 1) ? k : v;
    int8_t* yy = y + (long)blockIdx.y * R_ * E_;
    float a = alpha_p[0];
    long i0 = ((long)blockIdx.x * blockDim.x + threadIdx.x) * 4;
    float4 vv = *reinterpret_cast<const float4*>(x + i0);
    char4 o;
    o.x = (int8_t)L48[rcf_idx(vv.x, a, MD)];
    o.y = (int8_t)L48[rcf_idx(vv.y, a, MD)];
    o.z = (int8_t)L48[rcf_idx(vv.z, a, MD)];
    o.w = (int8_t)L48[rcf_idx(vv.w, a, MD)];
    *reinterpret_cast<char4*>(yy + i0) = o;
}

// ---------------------------------------------------------------------------
// Per-row weight quantization -> int8 k-values (for Wi)
// ---------------------------------------------------------------------------
__global__ void quant_weight_rows_i8_kernel(const float* __restrict__ W,
                                            int8_t* __restrict__ Wq,
                                            const float* __restrict__ alpha_p) {
    __shared__ float MD[30];
    __shared__ int   L48[31];
    __shared__ double red[256];
    const int row = blockIdx.x, tid = threadIdx.x;
    if (tid < 30) MD[tid] = g_MIDS[tid];
    if (tid < 31) L48[tid] = g_LN48[tid];
    const float* w = W + (long)row * E_;

    double s = 0.0;
    for (int c = tid; c < E_; c += 256) s += (double)w[c];
    red[tid] = s; __syncthreads();
    for (int o = 128; o > 0; o >>= 1) {
        if (tid < o) red[tid] += red[tid + o];
        __syncthreads();
    }
    double mu = red[0] / (double)E_;
    __syncthreads();

    double s2 = 0.0;
    for (int c = tid; c < E_; c += 256) {
        double d = (double)w[c] - mu;
        s2 += d * d;
    }
    red[tid] = s2; __syncthreads();
    for (int o = 128; o > 0; o >>= 1) {
        if (tid < o) red[tid] += red[tid + o];
        __syncthreads();
    }
    double var = red[0] / (double)E_;

    float inv = 1.0f / sqrtf((float)var + EPSQ);
    float muf = (float)mu;
    float a = alpha_p[0];
    for (int c = tid; c < E_; c += 256) {
        float wn = (w[c] - muf) * inv;
        Wq[(long)row * E_ + c] = (int8_t)L48[rcf_idx(wn, a, MD)];
    }
}

// ---------------------------------------------------------------------------
// Per-row weight quantization -> fp16 k-values (for Wo; |k|<=48 is exact)
// ---------------------------------------------------------------------------
__global__ void quant_weight_rows_f16k_kernel(const float* __restrict__ W,
                                              __half* __restrict__ Wq,
                                              const float* __restrict__ alpha_p) {
    __shared__ float MD[30];
    __shared__ int   L48[31];
    __shared__ double red[256];
    const int row = blockIdx.x, tid = threadIdx.x;
    if (tid < 30) MD[tid] = g_MIDS[tid];
    if (tid < 31) L48[tid] = g_LN48[tid];
    const float* w = W + (long)row * E_;

    double s = 0.0;
    for (int c = tid; c < E_; c += 256) s += (double)w[c];
    red[tid] = s; __syncthreads();
    for (int o = 128; o > 0; o >>= 1) {
        if (tid < o) red[tid] += red[tid + o];
        __syncthreads();
    }
    double mu = red[0] / (double)E_;
    __syncthreads();

    double s2 = 0.0;
    for (int c = tid; c < E_; c += 256) {
        double d = (double)w[c] - mu;
        s2 += d * d;
    }
    red[tid] = s2; __syncthreads();
    for (int o = 128; o > 0; o >>= 1) {
        if (tid < o) red[tid] += red[tid + o];
        __syncthreads();
    }
    double var = red[0] / (double)E_;

    float inv = 1.0f / sqrtf((float)var + EPSQ);
    float muf = (float)mu;
    float a = alpha_p[0];
    for (int c = tid; c < E_; c += 256) {
        float wn = (w[c] - muf) * inv;
        Wq[(long)row * E_ + c] = __float2half((float)L48[rcf_idx(wn, a, MD)]);
    }
}

// ---------------------------------------------------------------------------
// int8 tensor-core projection GEMM, now with register-prefetch double buffer
// ---------------------------------------------------------------------------
__device__ __forceinline__ void mma_i8(int* d, const uint32_t* a,
                                       const uint32_t* b) {
    asm volatile(
        "mma.sync.aligned.m16n8k32.row.col.s32.s8.s8.s32 "
        "{%0,%1,%2,%3}, {%4,%5,%6,%7}, {%8,%9}, {%0,%1,%2,%3};\n"
        : "+r"(d[0]), "+r"(d[1]), "+r"(d[2]), "+r"(d[3])
        : "r"(a[0]), "r"(a[1]), "r"(a[2]), "r"(a[3]), "r"(b[0]), "r"(b[1]));
}

#define I8_STRIDE 80

__global__ __launch_bounds__(256) void gemm_i8_kernel(
    const int8_t* __restrict__ A, const int8_t* __restrict__ B,
    float* __restrict__ C, const float* __restrict__ bias,
    const float* __restrict__ aA, const float* __restrict__ aB,
    int K, int N) {
    __shared__ __align__(16) int8_t As[128 * I8_STRIDE];
    __shared__ __align__(16) int8_t Bs[128 * I8_STRIDE];

    const int tid  = threadIdx.x;
    const int warp = tid >> 5;
    const int lane = tid & 31;
    const int g    = lane >> 2;
    const int tig  = lane & 3;

    const long z = blockIdx.z;
    A += z * (long)R_ * K;
    B += z * (long)N * K;
    C += z * (long)R_ * N;
    bias += z * N;

    const int m0 = blockIdx.y * 128;
    const int n0 = blockIdx.x * 128;
    const int wm = (warp >> 2) * 64;
    const int wn = (warp & 3) * 32;

    int acc[4][4][4];
#pragma unroll
    for (int a_ = 0; a_ < 4; a_++)
#pragma unroll
        for (int b_ = 0; b_ < 4; b_++)
#pragma unroll
            for (int c_ = 0; c_ < 4; c_++) acc[a_][b_][c_] = 0;

    const uint32_t* Aw = reinterpret_cast<const uint32_t*>(As);
    const uint32_t* Bw = reinterpret_cast<const uint32_t*>(Bs);
    const int WSTR = I8_STRIDE / 4;

    // register prefetch buffers (2 int4 each for A and B)
    int4 pA[2], pB[2];
#pragma unroll
    for (int it = 0; it < 2; it++) {
        int idx = it * 256 + tid;
        int row = idx >> 2, c = idx & 3;
        pA[it] = *reinterpret_cast<const int4*>(A + (long)(m0 + row) * K + c * 16);
        pB[it] = *reinterpret_cast<const int4*>(B + (long)(n0 + row) * K + c * 16);
    }

    for (int k0 = 0; k0 < K; k0 += 64) {
#pragma unroll
        for (int it = 0; it < 2; it++) {
            int idx = it * 256 + tid;
            int row = idx >> 2, c = idx & 3;
            *reinterpret_cast<int4*>(&As[row * I8_STRIDE + c * 16]) = pA[it];
            *reinterpret_cast<int4*>(&Bs[row * I8_STRIDE + c * 16]) = pB[it];
        }
        __syncthreads();

        if (k0 + 64 < K) {
#pragma unroll
            for (int it = 0; it < 2; it++) {
                int idx = it * 256 + tid;
                int row = idx >> 2, c = idx & 3;
                pA[it] = *reinterpret_cast<const int4*>(
                    A + (long)(m0 + row) * K + k0 + 64 + c * 16);
                pB[it] = *reinterpret_cast<const int4*>(
                    B + (long)(n0 + row) * K + k0 + 64 + c * 16);
            }
        }

#pragma unroll
        for (int ks = 0; ks < 2; ks++) {
            uint32_t af[4][4], bf[4][2];
#pragma unroll
            for (int mt = 0; mt < 4; mt++) {
                int base = (wm + mt * 16 + g) * WSTR + ks * 8 + tig;
                af[mt][0] = Aw[base];
                af[mt][1] = Aw[base + 8 * WSTR];
                af[mt][2] = Aw[base + 4];
                af[mt][3] = Aw[base + 8 * WSTR + 4];
            }
#pragma unroll
            for (int nt = 0; nt < 4; nt++) {
                int base = (wn + nt * 8 + g) * WSTR + ks * 8 + tig;
                bf[nt][0] = Bw[base];
                bf[nt][1] = Bw[base + 4];
            }
#pragma unroll
            for (int mt = 0; mt < 4; mt++)
#pragma unroll
                for (int nt = 0; nt < 4; nt++)
                    mma_i8(acc[mt][nt], af[mt], bf[nt]);
        }
        __syncthreads();
    }

    const float scale = __ldg(aA) * __ldg(aB) * (1.0f / 2304.0f);
#pragma unroll
    for (int mt = 0; mt < 4; mt++) {
#pragma unroll
        for (int nt = 0; nt < 4; nt++) {
            int row = m0 + wm + mt * 16 + g;
            int col = n0 + wn + nt * 8 + tig * 2;
            float b0 = bias[col], b1 = bias[col + 1];
            float2 v0, v1;
            v0.x = (float)acc[mt][nt][0] * scale + b0;
            v0.y = (float)acc[mt][nt][1] * scale + b1;
            v1.x = (float)acc[mt][nt][2] * scale + b0;
            v1.y = (float)acc[mt][nt][3] * scale + b1;
            *reinterpret_cast<float2*>(C + (long)row * N + col) = v0;
            *reinterpret_cast<float2*>(C + (long)(row + 8) * N + col) = v1;
        }
    }
}

// ---------------------------------------------------------------------------
// Per-head transpose of vp: vpT[z][d][t] = vp[t*4096 + 64*z + d]
// ---------------------------------------------------------------------------
__global__ void transpose_v_kernel(const float* __restrict__ vp,
                                   float* __restrict__ vpT) {
    __shared__ float tile[32][33];
    const int z = blockIdx.z;
    const int t0 = blockIdx.x * 32;
    const int d0 = blockIdx.y * 32;
    const float* src = vp + 64L * z;
    float* dst = vpT + (long)z * D_ * S_;
    for (int r = threadIdx.y; r < 32; r += 8)
        tile[r][threadIdx.x] = src[(long)(t0 + r) * 4096 + d0 + threadIdx.x];
    __syncthreads();
    for (int r = threadIdx.y; r < 32; r += 8)
        dst[(long)(d0 + r) * S_ + t0 + threadIdx.x] = tile[threadIdx.x][r];
}

// ---------------------------------------------------------------------------
// fp16 helpers
// ---------------------------------------------------------------------------
__device__ __forceinline__ void mma_f16(float* d, const uint32_t* a,
                                        const uint32_t* b) {
    asm volatile(
        "mma.sync.aligned.m16n8k16.row.col.f32.f16.f16.f32 "
        "{%0,%1,%2,%3}, {%4,%5,%6,%7}, {%8,%9}, {%0,%1,%2,%3};\n"
        : "+f"(d[0]), "+f"(d[1]), "+f"(d[2]), "+f"(d[3])
        : "r"(a[0]), "r"(a[1]), "r"(a[2]), "r"(a[3]), "r"(b[0]), "r"(b[1]));
}

__device__ __forceinline__ void split4(const float4& v, uint2& hi, uint2& lo) {
    __half2 h01 = __floats2half2_rn(v.x, v.y);
    __half2 h23 = __floats2half2_rn(v.z, v.w);
    __half2 l01 = __floats2half2_rn(v.x - __low2float(h01),
                                    v.y - __high2float(h01));
    __half2 l23 = __floats2half2_rn(v.z - __low2float(h23),
                                    v.w - __high2float(h23));
    hi.x = *reinterpret_cast<uint32_t*>(&h01);
    hi.y = *reinterpret_cast<uint32_t*>(&h23);
    lo.x = *reinterpret_cast<uint32_t*>(&l01);
    lo.y = *reinterpret_cast<uint32_t*>(&l23);
}

__device__ __forceinline__ void split2(float a, float b, uint32_t& hi,
                                       uint32_t& lo) {
    __half2 h = __floats2half2_rn(a, b);
    __half2 l = __floats2half2_rn(a - __low2float(h), b - __high2float(h));
    hi = *reinterpret_cast<uint32_t*>(&h);
    lo = *reinterpret_cast<uint32_t*>(&l);
}

// ---------------------------------------------------------------------------
// Fused flash attention (proven round 10): scores + online softmax + PV.
// ---------------------------------------------------------------------------
#define KWORDS 36
#define VWORDS 68
#define SM_K   18432
#define SM_QVT 18432
#define SM_TOTAL_FLASH (2*SM_K + 2*SM_QVT)   // 73728

__global__ __launch_bounds__(256) void flash_attn_kernel(
    const float* __restrict__ Q, const float* __restrict__ Kp,
    const float* __restrict__ VT, float* __restrict__ O) {
    extern __shared__ char sm[];
    uint32_t* KH = reinterpret_cast<uint32_t*>(sm);
    uint32_t* KL = reinterpret_cast<uint32_t*>(sm + SM_K);
    uint32_t* PH = reinterpret_cast<uint32_t*>(sm + 2 * SM_K);
    uint32_t* PL = reinterpret_cast<uint32_t*>(sm + 2 * SM_K + SM_QVT);

    const int tid = threadIdx.x;
    const int warp = tid >> 5, lane = tid & 31;
    const int g = lane >> 2, tig = lane & 3;
    const int z = blockIdx.y;
    const int q0 = blockIdx.x * 128;

    const float* Qb = Q + (long)z * 64;
    const float* Kb = Kp + (long)z * 64;
    const float* Vb = VT + (long)z * D_ * S_;

#pragma unroll
    for (int it = 0; it < 8; it++) {
        int idx = it * 256 + tid;
        int row = idx >> 4, qd = idx & 15;
        float4 v = *reinterpret_cast<const float4*>(
            Qb + (long)(q0 + row) * 4096 + qd * 4);
        uint2 hi, lo;
        split4(v, hi, lo);
        reinterpret_cast<uint2*>(PH)[row * 18 + qd] = hi;
        reinterpret_cast<uint2*>(PL)[row * 18 + qd] = lo;
    }
    __syncthreads();
    uint32_t qh[4][4], ql[4][4];
#pragma unroll
    for (int ks = 0; ks < 4; ks++) {
        int base = (warp * 16 + g) * KWORDS + ks * 8 + tig;
        qh[ks][0] = PH[base];
        qh[ks][1] = PH[base + 8 * KWORDS];
        qh[ks][2] = PH[base + 4];
        qh[ks][3] = PH[base + 8 * KWORDS + 4];
        ql[ks][0] = PL[base];
        ql[ks][1] = PL[base + 8 * KWORDS];
        ql[ks][2] = PL[base + 4];
        ql[ks][3] = PL[base + 8 * KWORDS + 4];
    }
    __syncthreads();

    float ctx[8][4];
#pragma unroll
    for (int d8 = 0; d8 < 8; d8++)
#pragma unroll
        for (int c = 0; c < 4; c++) ctx[d8][c] = 0.0f;
    float M0 = -1e30f, M1 = -1e30f, T0 = 0.0f, T1 = 0.0f;

    for (int t0 = 0; t0 < S_; t0 += 128) {
#pragma unroll
        for (int it = 0; it < 8; it++) {
            int idx = it * 256 + tid;
            int row = idx >> 4, qd = idx & 15;
            float4 v = *reinterpret_cast<const float4*>(
                Kb + (long)(t0 + row) * 4096 + qd * 4);
            uint2 hi, lo;
            split4(v, hi, lo);
            reinterpret_cast<uint2*>(KH)[row * 18 + qd] = hi;
            reinterpret_cast<uint2*>(KL)[row * 18 + qd] = lo;
        }
#pragma unroll
        for (int it = 0; it < 8; it++) {
            int idx = it * 256 + tid;
            int row = idx >> 5, qd = idx & 31;
            float4 v = *reinterpret_cast<const float4*>(
                Vb + (long)row * 1024 + t0 + qd * 4);
            uint2 hi, lo;
            split4(v, hi, lo);
            reinterpret_cast<uint2*>(PH)[row * 34 + qd] = hi;
            reinterpret_cast<uint2*>(PL)[row * 34 + qd] = lo;
        }
        __syncthreads();

        float acc[16][4];
#pragma unroll
        for (int nt = 0; nt < 16; nt++)
#pragma unroll
            for (int c = 0; c < 4; c++) acc[nt][c] = 0.0f;
#pragma unroll
        for (int nt = 0; nt < 16; nt++) {
#pragma unroll
            for (int ks = 0; ks < 4; ks++) {
                int base = (nt * 8 + g) * KWORDS + ks * 8 + tig;
                uint32_t bh[2] = {KH[base], KH[base + 4]};
                uint32_t bl[2] = {KL[base], KL[base + 4]};
                mma_f16(acc[nt], qh[ks], bh);
                mma_f16(acc[nt], qh[ks], bl);
                mma_f16(acc[nt], ql[ks], bh);
            }
        }

        float m0 = -1e30f, m1 = -1e30f;
#pragma unroll
        for (int nt = 0; nt < 16; nt++) {
            acc[nt][0] *= 0.125f; acc[nt][1] *= 0.125f;
            acc[nt][2] *= 0.125f; acc[nt][3] *= 0.125f;
            m0 = fmaxf(m0, fmaxf(acc[nt][0], acc[nt][1]));
            m1 = fmaxf(m1, fmaxf(acc[nt][2], acc[nt][3]));
        }
        m0 = fmaxf(m0, __shfl_xor_sync(0xffffffffu, m0, 1));
        m0 = fmaxf(m0, __shfl_xor_sync(0xffffffffu, m0, 2));
        m1 = fmaxf(m1, __shfl_xor_sync(0xffffffffu, m1, 1));
        m1 = fmaxf(m1, __shfl_xor_sync(0xffffffffu, m1, 2));
        float Mn0 = fmaxf(M0, m0), Mn1 = fmaxf(M1, m1);
        float a0 = __expf(M0 - Mn0), a1 = __expf(M1 - Mn1);
        M0 = Mn0; M1 = Mn1;

        float s0 = 0.0f, s1 = 0.0f;
#pragma unroll
        for (int nt = 0; nt < 16; nt++) {
            acc[nt][0] = __expf(acc[nt][0] - M0);
            acc[nt][1] = __expf(acc[nt][1] - M0);
            acc[nt][2] = __expf(acc[nt][2] - M1);
            acc[nt][3] = __expf(acc[nt][3] - M1);
            s0 += acc[nt][0] + acc[nt][1];
            s1 += acc[nt][2] + acc[nt][3];
        }
        s0 += __shfl_xor_sync(0xffffffffu, s0, 1);
        s0 += __shfl_xor_sync(0xffffffffu, s0, 2);
        s1 += __shfl_xor_sync(0xffffffffu, s1, 1);
        s1 += __shfl_xor_sync(0xffffffffu, s1, 2);
        T0 = T0 * a0 + s0;
        T1 = T1 * a1 + s1;
#pragma unroll
        for (int d8 = 0; d8 < 8; d8++) {
            ctx[d8][0] *= a0; ctx[d8][1] *= a0;
            ctx[d8][2] *= a1; ctx[d8][3] *= a1;
        }

#pragma unroll
        for (int c = 0; c < 8; c++) {
            uint32_t ah[4], al[4];
            split2(acc[2 * c][0],     acc[2 * c][1],     ah[0], al[0]);
            split2(acc[2 * c][2],     acc[2 * c][3],     ah[1], al[1]);
            split2(acc[2 * c + 1][0], acc[2 * c + 1][1], ah[2], al[2]);
            split2(acc[2 * c + 1][2], acc[2 * c + 1][3], ah[3], al[3]);
#pragma unroll
            for (int d8 = 0; d8 < 8; d8++) {
                int base = (d8 * 8 + g) * VWORDS + c * 8 + tig;
                uint32_t bh[2] = {PH[base], PH[base + 4]};
                uint32_t bl[2] = {PL[base], PL[base + 4]};
                mma_f16(ctx[d8], ah, bh);
                mma_f16(ctx[d8], ah, bl);
                mma_f16(ctx[d8], al, bh);
            }
        }
        __syncthreads();
    }

    float i0 = 1.0f / T0, i1 = 1.0f / T1;
    const long r0 = q0 + warp * 16 + g;
#pragma unroll
    for (int d8 = 0; d8 < 8; d8++) {
        int col = z * 64 + d8 * 8 + tig * 2;
        float2 v0, v1;
        v0.x = ctx[d8][0] * i0; v0.y = ctx[d8][1] * i0;
        v1.x = ctx[d8][2] * i1; v1.y = ctx[d8][3] * i1;
        *reinterpret_cast<float2*>(O + r0 * 4096 + col) = v0;
        *reinterpret_cast<float2*>(O + (r0 + 8) * 4096 + col) = v1;
    }
}

// ---------------------------------------------------------------------------
// Output projection: ctx (fp32, split hi/lo) x Wo_k (exact fp16) — 2 passes.
//   out[m,n] = (sum_k ctx[m,k]*Wo_k[n,k]) * (a_wo/48) + bo[n]
// M=4096, N=1024, K=1024. BM=BN=128, BK=32, 256 thr.
// ---------------------------------------------------------------------------
__global__ __launch_bounds__(256) void gemm_ctx_wo_kernel(
    const float* __restrict__ A, const __half* __restrict__ B,
    float* __restrict__ C, const float* __restrict__ bias,
    const float* __restrict__ aB) {
    const int K = E_;
    __shared__ __align__(16) __half Ah[128 * 40];
    __shared__ __align__(16) __half Al[128 * 40];
    __shared__ __align__(16) __half Bs[128 * 40];

    const int tid  = threadIdx.x;
    const int warp = tid >> 5;
    const int lane = tid & 31;
    const int g    = lane >> 2;
    const int tig  = lane & 3;

    const int m0 = blockIdx.y * 128;
    const int n0 = blockIdx.x * 128;
    const int wm = (warp >> 2) * 64;
    const int wn = (warp & 3) * 32;

    float acc[4][4][4];
#pragma unroll
    for (int mt = 0; mt < 4; mt++)
#pragma unroll
        for (int nt = 0; nt < 4; nt++)
#pragma unroll
            for (int c = 0; c < 4; c++) acc[mt][nt][c] = 0.0f;

    const uint32_t* Ahw = reinterpret_cast<const uint32_t*>(Ah);
    const uint32_t* Alw = reinterpret_cast<const uint32_t*>(Al);
    const uint32_t* Bw  = reinterpret_cast<const uint32_t*>(Bs);
    const int WSTR = 20;

    // prefetch: A 4 float4/thread, B 2 int4/thread
    float4 pa[4];
    int4 pb[2];
#pragma unroll
    for (int it = 0; it < 4; it++) {
        int idx = it * 256 + tid;
        pa[it] = *reinterpret_cast<const float4*>(
            A + (long)(m0 + (idx >> 3)) * K + (idx & 7) * 4);
    }
#pragma unroll
    for (int it = 0; it < 2; it++) {
        int idx = it * 256 + tid;
        pb[it] = *reinterpret_cast<const int4*>(
            B + (long)(n0 + (idx >> 2)) * K + (idx & 3) * 8);
    }

    for (int k0 = 0; k0 < K; k0 += 32) {
#pragma unroll
        for (int it = 0; it < 4; it++) {
            int idx = it * 256 + tid;
            int row = idx >> 3, qd = idx & 7;
            uint2 hi, lo;
            split4(pa[it], hi, lo);
            reinterpret_cast<uint2*>(Ah)[row * 10 + qd] = hi;
            reinterpret_cast<uint2*>(Al)[row * 10 + qd] = lo;
        }
#pragma unroll
        for (int it = 0; it < 2; it++) {
            int idx = it * 256 + tid;
            int row = idx >> 2, qq = idx & 3;
            *reinterpret_cast<int4*>(&Bs[row * 40 + qq * 8]) = pb[it];
        }
        __syncthreads();

        if (k0 + 32 < K) {
#pragma unroll
            for (int it = 0; it < 4; it++) {
                int idx = it * 256 + tid;
                pa[it] = *reinterpret_cast<const float4*>(
                    A + (long)(m0 + (idx >> 3)) * K + k0 + 32 + (idx & 7) * 4);
            }
#pragma unroll
            for (int it = 0; it < 2; it++) {
                int idx = it * 256 + tid;
                pb[it] = *reinterpret_cast<const int4*>(
                    B + (long)(n0 + (idx >> 2)) * K + k0 + 32 + (idx & 3) * 8);
            }
        }

#pragma unroll
        for (int ks = 0; ks < 2; ks++) {
            uint32_t ah[4][4], al[4][4], bf[4][2];
#pragma unroll
            for (int mt = 0; mt < 4; mt++) {
                int base = (wm + mt * 16 + g) * WSTR + ks * 8 + tig;
                ah[mt][0] = Ahw[base];
                ah[mt][1] = Ahw[base + 8 * WSTR];
                ah[mt][2] = Ahw[base + 4];
                ah[mt][3] = Ahw[base + 8 * WSTR + 4];
                al[mt][0] = Alw[base];
                al[mt][1] = Alw[base + 8 * WSTR];
                al[mt][2] = Alw[base + 4];
                al[mt][3] = Alw[base + 8 * WSTR + 4];
            }
#pragma unroll
            for (int nt = 0; nt < 4; nt++) {
                int base = (wn + nt * 8 + g) * WSTR + ks * 8 + tig;
                bf[nt][0] = Bw[base];
                bf[nt][1] = Bw[base + 4];
            }
#pragma unroll
            for (int mt = 0; mt < 4; mt++)
#pragma unroll
                for (int nt = 0; nt < 4; nt++) {
                    mma_f16(acc[mt][nt], ah[mt], bf[nt]);
                    mma_f16(acc[mt][nt], al[mt], bf[nt]);
                }
        }
        __syncthreads();
    }

    const float scale = __ldg(aB) * (1.0f / 48.0f);
#pragma unroll
    for (int mt = 0; mt < 4; mt++) {
#pragma unroll
        for (int nt = 0; nt < 4; nt++) {
            long row = m0 + wm + mt * 16 + g;
            long col = n0 + wn + nt * 8 + tig * 2;
            float b0 = bias[col], b1 = bias[col + 1];
            float2 v0, v1;
            v0.x = acc[mt][nt][0] * scale + b0;
            v0.y = acc[mt][nt][1] * scale + b1;
            v1.x = acc[mt][nt][2] * scale + b0;
            v1.y = acc[mt][nt][3] * scale + b1;
            *reinterpret_cast<float2*>(C + row * (long)E_ + col) = v0;
            *reinterpret_cast<float2*>(C + (row + 8) * (long)E_ + col) = v1;
        }
    }
}

// ---------------------------------------------------------------------------
// Orchestration.
// ---------------------------------------------------------------------------
extern "C" void kernel_launch(void* const* d_in, const int* in_sizes, int n_in,
                              void* d_out, int out_size) {
    const float* q    = (const float*)d_in[0];
    const float* k    = (const float*)d_in[1];
    const float* v    = (const float*)d_in[2];
    const float* Wi   = (const float*)d_in[3];
    const float* bi   = (const float*)d_in[4];
    const float* Wo   = (const float*)d_in[5];
    const float* bo   = (const float*)d_in[6];
    const float* a_act = (const float*)d_in[7];
    const float* a_wi  = (const float*)d_in[8];
    const float* a_bi  = (const float*)d_in[9];
    const float* a_wo  = (const float*)d_in[10];
    const float* a_bo  = (const float*)d_in[11];
    float* out = (float*)d_out;

    int8_t *p_Wi8, *p_act8;
    __half* p_Woh;
    float *p_bi, *p_bo, *p_proj, *p_vpT, *p_ctx;
    cudaGetSymbolAddress((void**)&p_Wi8, g_Wi_i8);
    cudaGetSymbolAddress((void**)&p_act8, g_act_i8);
    cudaGetSymbolAddress((void**)&p_Woh, g_Wo_h);
    cudaGetSymbolAddress((void**)&p_bi, g_bi);
    cudaGetSymbolAddress((void**)&p_bo, g_bo);
    cudaGetSymbolAddress((void**)&p_proj, g_proj);
    cudaGetSymbolAddress((void**)&p_vpT, g_vpT);
    cudaGetSymbolAddress((void**)&p_ctx, g_ctx);

    const long RE = (long)R_ * E_;
    float* p_qp = p_proj;
    float* p_kp = p_proj + RE;
    float* p_vp = p_proj + 2 * RE;

    cudaFuncSetAttribute(flash_attn_kernel,
                         cudaFuncAttributeMaxDynamicSharedMemorySize,
                         SM_TOTAL_FLASH);

    init_tables_kernel<<<1, 1>>>();

    // Weight + bias quantization
    quant_weight_rows_i8_kernel<<<3 * E_, 256>>>(Wi, p_Wi8, a_wi);
    quant_weight_rows_f16k_kernel<<<E_, 256>>>(Wo, p_Woh, a_wo);
    quant_bias_kernel<<<16, 256>>>(bi, bo, p_bi, p_bo, a_bi, a_bo);

    // Activation quantization -> int8 k-values (one z-batched launch)
    quant_act_i8_kernel<<<dim3(RE / 1024, 3), 256>>>(q, k, v, p_act8, a_act);

    // Projections via int8 tensor cores (exact)
    gemm_i8_kernel<<<dim3(E_ / 128, R_ / 128, 3), 256>>>(
        p_act8, p_Wi8, p_proj, p_bi, a_act, a_wi, E_, E_);

    // Transpose vp per head (B-operand layout for PV inside flash kernel)
    transpose_v_kernel<<<dim3(S_ / 32, D_ / 32, Z_), dim3(32, 8)>>>(p_vp, p_vpT);

    // Fused attention: scores + online softmax + PV -> ctx
    flash_attn_kernel<<<dim3(S_ / 128, Z_), 256, SM_TOTAL_FLASH>>>(
        p_qp, p_kp, p_vpT, p_ctx);

    // Output projection: ctx x Wo_k (exact fp16, 2 passes) -> out
    gemm_ctx_wo_kernel<<<dim3(8, 32), 256>>>(p_ctx, p_Woh, out, p_bo, a_wo);
}

// round 12
// speedup vs baseline: 4.9892x; 1.0378x over previous
#include <cuda_runtime.h>
#include <cuda_fp16.h>
#include <math.h>
#include <stdint.h>

#define EPSQ 1e-5f

// Problem sizes (fixed by the reference setup_inputs)
#define S_ 1024
#define B_ 4
#define E_ 1024
#define H_ 16
#define D_ 64
#define R_ (S_*B_)   // 4096 flattened (s,b) rows
#define Z_ (B_*H_)   // 64 batched heads

// ---------------------------------------------------------------------------
// Static device scratch (no runtime allocation allowed)
// ---------------------------------------------------------------------------
__device__ float g_LN[31];
__device__ float g_MIDS[30];
__device__ int   g_LN48[31];

__device__ __align__(16) int8_t g_Wi_i8[3*E_*E_];
__device__ __align__(16) __half g_Wo_h[E_*E_];         // Wo k-values (exact fp16)
__device__ __align__(16) float  g_bi[3*E_];
__device__ __align__(16) float  g_bo[E_];
__device__ __align__(16) int8_t g_act_i8[3L*R_*E_];
__device__ __align__(16) __half g_proj_h[3L*R_*E_];    // qp,kp,vp hi plane
__device__ __align__(16) __half g_proj_l[3L*R_*E_];    // qp,kp,vp lo plane
__device__ __align__(16) __half g_vpT_h[(long)Z_*D_*S_];
__device__ __align__(16) __half g_vpT_l[(long)Z_*D_*S_];
__device__ __align__(16) __half g_ctx_h[(long)R_*E_];
__device__ __align__(16) __half g_ctx_l[(long)R_*E_];

// ---------------------------------------------------------------------------
// APoT tables (exact float emulation of the numpy construction)
// ---------------------------------------------------------------------------
__global__ void init_tables_kernel() {
    const float pos[15] = {0.03125f, 0.0625f, 0.09375f, 0.125f, 0.1875f,
                           0.25f, 0.28125f, 0.375f, 0.5f, 0.5625f,
                           0.75f, 1.0f, 1.03125f, 1.125f, 1.5f};
    const float G = (float)(1.0 / 1.5);
    for (int i = 0; i < 15; i++) {
        g_LN[i]      = (-pos[14 - i]) * G;
        g_LN[16 + i] = pos[i] * G;
    }
    g_LN[15] = 0.0f;
    for (int i = 0; i < 30; i++)
        g_MIDS[i] = (g_LN[i] + g_LN[i + 1]) * 0.5f;
    for (int i = 0; i < 31; i++)
        g_LN48[i] = (int)lrintf(g_LN[i] * 48.0f);
}

// Binary-search count(MD[i] < xc) over 30 sorted mids (== searchsorted left).
__device__ __forceinline__ int rcf_idx(float x, float alpha,
                                       const float* __restrict__ MD) {
    float xn = x / (alpha + EPSQ);
    float xc = fminf(1.0f, fmaxf(-1.0f, xn));
    int c = 0;
    if (MD[15] < xc) c = 16;
    if (c + 8 <= 30 && MD[c + 7] < xc) c += 8;
    if (c + 4 <= 30 && MD[c + 3] < xc) c += 4;
    if (c + 2 <= 30 && MD[c + 1] < xc) c += 2;
    if (c + 1 <= 30 && MD[c] < xc) c += 1;
    return c;
}
__device__ __forceinline__ float rcf_dev(float x, float alpha,
                                         const float* __restrict__ LN,
                                         const float* __restrict__ MD) {
    return LN[rcf_idx(x, alpha, MD)] * alpha;
}

// ---------------------------------------------------------------------------
// Bias quantization: bi (3072) and bo (1024) in ONE launch (16 blocks).
// ---------------------------------------------------------------------------
__global__ void quant_bias_kernel(const float* __restrict__ bi,
                                  const float* __restrict__ bo,
                                  float* __restrict__ ybi,
                                  float* __restrict__ ybo,
                                  const float* __restrict__ abi,
                                  const float* __restrict__ abo) {
    __shared__ float LN[31], MD[30];
    if (threadIdx.x < 31) LN[threadIdx.x] = g_LN[threadIdx.x];
    if (threadIdx.x < 30) MD[threadIdx.x] = g_MIDS[threadIdx.x];
    __syncthreads();
    int b = blockIdx.x;
    if (b < 12) {
        int i = b * 256 + threadIdx.x;
        ybi[i] = rcf_dev(bi[i], abi[0], LN, MD);
    } else {
        int i = (b - 12) * 256 + threadIdx.x;
        ybo[i] = rcf_dev(bo[i], abo[0], LN, MD);
    }
}

// ---------------------------------------------------------------------------
// Activation quantization -> int8 k-values; q/k/v in one z-batched launch.
// ---------------------------------------------------------------------------
__global__ void quant_act_i8_kernel(const float* __restrict__ q,
                                    const float* __restrict__ k,
                                    const float* __restrict__ v,
                                    int8_t* __restrict__ y,
                                    const float* __restrict__ alpha_p) {
    __shared__ float MD[30];
    __shared__ int   L48[31];
    if (threadIdx.x < 30) MD[threadIdx.x] = g_MIDS[threadIdx.x];
    if (threadIdx.x < 31) L48[threadIdx.x] = g_LN48[threadIdx.x];
    __syncthreads();
    const float* x = (blockIdx.y == 0) ? q : (blockIdx.y == 1) ? k : v;
    int8_t* yy = y + (long)blockIdx.y * R_ * E_;
    float a = alpha_p[0];
    long i0 = ((long)blockIdx.x * blockDim.x + threadIdx.x) * 4;
    float4 vv = *reinterpret_cast<const float4*>(x + i0);
    char4 o;
    o.x = (int8_t)L48[rcf_idx(vv.x, a, MD)];
    o.y = (int8_t)L48[rcf_idx(vv.y, a, MD)];
    o.z = (int8_t)L48[rcf_idx(vv.z, a, MD)];
    o.w = (int8_t)L48[rcf_idx(vv.w, a, MD)];
    *reinterpret_cast<char4*>(yy + i0) = o;
}

// ---------------------------------------------------------------------------
// Weight quantization: one block per row, single global read, float warp
// reductions (2 syncs). OUT==0 -> int8 k-values; OUT==1 -> fp16 k-values.
// ---------------------------------------------------------------------------
template <int OUT>
__global__ void quant_weight_rows_kernel(const float* __restrict__ W,
                                         int8_t* __restrict__ Wq8,
                                         __half* __restrict__ Wqh,
                                         const float* __restrict__ alpha_p) {
    __shared__ float MD[30];
    __shared__ int   L48[31];
    __shared__ float red[8];
    const int row = blockIdx.x, tid = threadIdx.x;
    const int lane = tid & 31, warp = tid >> 5;
    if (tid < 30) MD[tid] = g_MIDS[tid];
    if (tid < 31) L48[tid] = g_LN48[tid];
    const float* w = W + (long)row * E_;

    float4 w4 = *reinterpret_cast<const float4*>(w + tid * 4);

    float s = w4.x + w4.y + w4.z + w4.w;
#pragma unroll
    for (int o = 16; o > 0; o >>= 1) s += __shfl_xor_sync(0xffffffffu, s, o);
    if (lane == 0) red[warp] = s;
    __syncthreads();
    float tot = red[0];
#pragma unroll
    for (int i = 1; i < 8; i++) tot += red[i];
    float mu = tot * (1.0f / E_);

    float dx = w4.x - mu, dy = w4.y - mu, dz = w4.z - mu, dw = w4.w - mu;
    float s2 = dx * dx + dy * dy + dz * dz + dw * dw;
#pragma unroll
    for (int o = 16; o > 0; o >>= 1) s2 += __shfl_xor_sync(0xffffffffu, s2, o);
    __syncthreads();
    if (lane == 0) red[warp] = s2;
    __syncthreads();
    float tot2 = red[0];
#pragma unroll
    for (int i = 1; i < 8; i++) tot2 += red[i];
    float var = tot2 * (1.0f / E_);

    float inv = 1.0f / sqrtf(var + EPSQ);
    float a = alpha_p[0];
    int k0 = L48[rcf_idx(dx * inv, a, MD)];
    int k1 = L48[rcf_idx(dy * inv, a, MD)];
    int k2 = L48[rcf_idx(dz * inv, a, MD)];
    int k3 = L48[rcf_idx(dw * inv, a, MD)];
    if (OUT == 0) {
        char4 o;
        o.x = (int8_t)k0; o.y = (int8_t)k1; o.z = (int8_t)k2; o.w = (int8_t)k3;
        *reinterpret_cast<char4*>(Wq8 + (long)row * E_ + tid * 4) = o;
    } else {
        __half2 h01 = __floats2half2_rn((float)k0, (float)k1);
        __half2 h23 = __floats2half2_rn((float)k2, (float)k3);
        uint2 pk;
        pk.x = *reinterpret_cast<uint32_t*>(&h01);
        pk.y = *reinterpret_cast<uint32_t*>(&h23);
        *reinterpret_cast<uint2*>(Wqh + (long)row * E_ + tid * 4) = pk;
    }
}

// ---------------------------------------------------------------------------
// fp16 split helpers
// ---------------------------------------------------------------------------
__device__ __forceinline__ void split2(float a, float b, uint32_t& hi,
                                       uint32_t& lo) {
    __half2 h = __floats2half2_rn(a, b);
    __half2 l = __floats2half2_rn(a - __low2float(h), b - __high2float(h));
    hi = *reinterpret_cast<uint32_t*>(&h);
    lo = *reinterpret_cast<uint32_t*>(&l);
}

// ---------------------------------------------------------------------------
// int8 tensor-core projection GEMM; epilogue writes fp16 hi/lo planes.
// q-section (z==0) additionally folds the exact 0.125 score scale.
// ---------------------------------------------------------------------------
__device__ __forceinline__ void mma_i8(int* d, const uint32_t* a,
                                       const uint32_t* b) {
    asm volatile(
        "mma.sync.aligned.m16n8k32.row.col.s32.s8.s8.s32 "
        "{%0,%1,%2,%3}, {%4,%5,%6,%7}, {%8,%9}, {%0,%1,%2,%3};\n"
        : "+r"(d[0]), "+r"(d[1]), "+r"(d[2]), "+r"(d[3])
        : "r"(a[0]), "r"(a[1]), "r"(a[2]), "r"(a[3]), "r"(b[0]), "r"(b[1]));
}

#define I8_STRIDE 80

__global__ __launch_bounds__(256) void gemm_i8_kernel(
    const int8_t* __restrict__ A, const int8_t* __restrict__ B,
    __half* __restrict__ Ch, __half* __restrict__ Cl,
    const float* __restrict__ bias,
    const float* __restrict__ aA, const float* __restrict__ aB,
    int K, int N) {
    __shared__ __align__(16) int8_t As[128 * I8_STRIDE];
    __shared__ __align__(16) int8_t Bs[128 * I8_STRIDE];

    const int tid  = threadIdx.x;
    const int warp = tid >> 5;
    const int lane = tid & 31;
    const int g    = lane >> 2;
    const int tig  = lane & 3;

    const long z = blockIdx.z;
    A += z * (long)R_ * K;
    B += z * (long)N * K;
    Ch += z * (long)R_ * N;
    Cl += z * (long)R_ * N;
    bias += z * N;

    const int m0 = blockIdx.y * 128;
    const int n0 = blockIdx.x * 128;
    const int wm = (warp >> 2) * 64;
    const int wn = (warp & 3) * 32;

    int acc[4][4][4];
#pragma unroll
    for (int a_ = 0; a_ < 4; a_++)
#pragma unroll
        for (int b_ = 0; b_ < 4; b_++)
#pragma unroll
            for (int c_ = 0; c_ < 4; c_++) acc[a_][b_][c_] = 0;

    const uint32_t* Aw = reinterpret_cast<const uint32_t*>(As);
    const uint32_t* Bw = reinterpret_cast<const uint32_t*>(Bs);
    const int WSTR = I8_STRIDE / 4;

    int4 pA[2], pB[2];
#pragma unroll
    for (int it = 0; it < 2; it++) {
        int idx = it * 256 + tid;
        int row = idx >> 2, c = idx & 3;
        pA[it] = *reinterpret_cast<const int4*>(A + (long)(m0 + row) * K + c * 16);
        pB[it] = *reinterpret_cast<const int4*>(B + (long)(n0 + row) * K + c * 16);
    }

    for (int k0 = 0; k0 < K; k0 += 64) {
#pragma unroll
        for (int it = 0; it < 2; it++) {
            int idx = it * 256 + tid;
            int row = idx >> 2, c = idx & 3;
            *reinterpret_cast<int4*>(&As[row * I8_STRIDE + c * 16]) = pA[it];
            *reinterpret_cast<int4*>(&Bs[row * I8_STRIDE + c * 16]) = pB[it];
        }
        __syncthreads();

        if (k0 + 64 < K) {
#pragma unroll
            for (int it = 0; it < 2; it++) {
                int idx = it * 256 + tid;
                int row = idx >> 2, c = idx & 3;
                pA[it] = *reinterpret_cast<const int4*>(
                    A + (long)(m0 + row) * K + k0 + 64 + c * 16);
                pB[it] = *reinterpret_cast<const int4*>(
                    B + (long)(n0 + row) * K + k0 + 64 + c * 16);
            }
        }

#pragma unroll
        for (int ks = 0; ks < 2; ks++) {
            uint32_t af[4][4], bf[4][2];
#pragma unroll
            for (int mt = 0; mt < 4; mt++) {
                int base = (wm + mt * 16 + g) * WSTR + ks * 8 + tig;
                af[mt][0] = Aw[base];
                af[mt][1] = Aw[base + 8 * WSTR];
                af[mt][2] = Aw[base + 4];
                af[mt][3] = Aw[base + 8 * WSTR + 4];
            }
#pragma unroll
            for (int nt = 0; nt < 4; nt++) {
                int base = (wn + nt * 8 + g) * WSTR + ks * 8 + tig;
                bf[nt][0] = Bw[base];
                bf[nt][1] = Bw[base + 4];
            }
#pragma unroll
            for (int mt = 0; mt < 4; mt++)
#pragma unroll
                for (int nt = 0; nt < 4; nt++)
                    mma_i8(acc[mt][nt], af[mt], bf[nt]);
        }
        __syncthreads();
    }

    // fold exact 1/8 score scale into the q section (z==0)
    const float f = (z == 0) ? 0.125f : 1.0f;
    const float scale = __ldg(aA) * __ldg(aB) * (1.0f / 2304.0f) * f;
#pragma unroll
    for (int mt = 0; mt < 4; mt++) {
#pragma unroll
        for (int nt = 0; nt < 4; nt++) {
            long row = m0 + wm + mt * 16 + g;
            long col = n0 + wn + nt * 8 + tig * 2;
            float b0 = bias[col] * f, b1 = bias[col + 1] * f;
            float v00 = (float)acc[mt][nt][0] * scale + b0;
            float v01 = (float)acc[mt][nt][1] * scale + b1;
            float v10 = (float)acc[mt][nt][2] * scale + b0;
            float v11 = (float)acc[mt][nt][3] * scale + b1;
            uint32_t h, l;
            split2(v00, v01, h, l);
            *reinterpret_cast<uint32_t*>(Ch + row * N + col) = h;
            *reinterpret_cast<uint32_t*>(Cl + row * N + col) = l;
            split2(v10, v11, h, l);
            *reinterpret_cast<uint32_t*>(Ch + (row + 8) * N + col) = h;
            *reinterpret_cast<uint32_t*>(Cl + (row + 8) * N + col) = l;
        }
    }
}

// ---------------------------------------------------------------------------
// Per-head transpose of vp planes: vpT[z][d][t] = vp[t*4096 + 64*z + d]
// Processes hi and lo planes (ushort payloads).
// ---------------------------------------------------------------------------
__global__ void transpose_v_kernel(const __half* __restrict__ vph,
                                   const __half* __restrict__ vpl,
                                   __half* __restrict__ vpTh,
                                   __half* __restrict__ vpTl) {
    __shared__ ushort tile[32][33];
    const int z = blockIdx.z;
    const int t0 = blockIdx.x * 32;
    const int d0 = blockIdx.y * 32;
#pragma unroll
    for (int p = 0; p < 2; p++) {
        const ushort* src = reinterpret_cast<const ushort*>(p ? vpl : vph) + 64L * z;
        ushort* dst = reinterpret_cast<ushort*>(p ? vpTl : vpTh) + (long)z * D_ * S_;
        for (int r = threadIdx.y; r < 32; r += 8)
            tile[r][threadIdx.x] = src[(long)(t0 + r) * 4096 + d0 + threadIdx.x];
        __syncthreads();
        for (int r = threadIdx.y; r < 32; r += 8)
            dst[(long)(d0 + r) * S_ + t0 + threadIdx.x] = tile[threadIdx.x][r];
        __syncthreads();
    }
}

// ---------------------------------------------------------------------------
// fp16 mma helper
// ---------------------------------------------------------------------------
__device__ __forceinline__ void mma_f16(float* d, const uint32_t* a,
                                        const uint32_t* b) {
    asm volatile(
        "mma.sync.aligned.m16n8k16.row.col.f32.f16.f16.f32 "
        "{%0,%1,%2,%3}, {%4,%5,%6,%7}, {%8,%9}, {%0,%1,%2,%3};\n"
        : "+f"(d[0]), "+f"(d[1]), "+f"(d[2]), "+f"(d[3])
        : "r"(a[0]), "r"(a[1]), "r"(a[2]), "r"(a[3]), "r"(b[0]), "r"(b[1]));
}

// ---------------------------------------------------------------------------
// Fused flash attention: scores + online softmax + PV (inputs/outputs are
// fp16 hi/lo planes; staging is pure uint4 copies).
// ---------------------------------------------------------------------------
#define KWORDS 36
#define VWORDS 68
#define SM_K   18432
#define SM_QVT 18432
#define SM_TOTAL_FLASH (2*SM_K + 2*SM_QVT)   // 73728

__global__ __launch_bounds__(256) void flash_attn_kernel(
    const __half* __restrict__ Qh, const __half* __restrict__ Ql,
    const __half* __restrict__ Kh_, const __half* __restrict__ Kl_,
    const __half* __restrict__ Vh, const __half* __restrict__ Vl,
    __half* __restrict__ Oh, __half* __restrict__ Ol) {
    extern __shared__ char sm[];
    uint32_t* KH = reinterpret_cast<uint32_t*>(sm);
    uint32_t* KL = reinterpret_cast<uint32_t*>(sm + SM_K);
    uint32_t* PH = reinterpret_cast<uint32_t*>(sm + 2 * SM_K);
    uint32_t* PL = reinterpret_cast<uint32_t*>(sm + 2 * SM_K + SM_QVT);

    const int tid = threadIdx.x;
    const int warp = tid >> 5, lane = tid & 31;
    const int g = lane >> 2, tig = lane & 3;
    const int z = blockIdx.y;
    const int q0 = blockIdx.x * 128;

    const __half* Qbh = Qh + (long)z * 64;     // s-stride 4096 halves
    const __half* Qbl = Ql + (long)z * 64;
    const __half* Kbh = Kh_ + (long)z * 64;
    const __half* Kbl = Kl_ + (long)z * 64;
    const __half* Vbh = Vh + (long)z * D_ * S_;
    const __half* Vbl = Vl + (long)z * D_ * S_;

    // ---- stage Q tile (128 rows x 64 halves = 8 uint4/row per plane)
#pragma unroll
    for (int it = 0; it < 4; it++) {
        int idx = it * 256 + tid;          // 1024 uint4 per plane
        int row = idx >> 3, qd = idx & 7;
        long go = (long)(q0 + row) * 4096 + qd * 8;
        reinterpret_cast<uint4*>(PH)[row * 9 + qd] =
            *reinterpret_cast<const uint4*>(Qbh + go);
        reinterpret_cast<uint4*>(PL)[row * 9 + qd] =
            *reinterpret_cast<const uint4*>(Qbl + go);
    }
    __syncthreads();
    uint32_t qh[4][4], ql[4][4];
#pragma unroll
    for (int ks = 0; ks < 4; ks++) {
        int base = (warp * 16 + g) * KWORDS + ks * 8 + tig;
        qh[ks][0] = PH[base];
        qh[ks][1] = PH[base + 8 * KWORDS];
        qh[ks][2] = PH[base + 4];
        qh[ks][3] = PH[base + 8 * KWORDS + 4];
        ql[ks][0] = PL[base];
        ql[ks][1] = PL[base + 8 * KWORDS];
        ql[ks][2] = PL[base + 4];
        ql[ks][3] = PL[base + 8 * KWORDS + 4];
    }
    __syncthreads();

    float ctx[8][4];
#pragma unroll
    for (int d8 = 0; d8 < 8; d8++)
#pragma unroll
        for (int c = 0; c < 4; c++) ctx[d8][c] = 0.0f;
    float M0 = -1e30f, M1 = -1e30f, T0 = 0.0f, T1 = 0.0f;

    for (int t0 = 0; t0 < S_; t0 += 128) {
        // ---- stage K tile (128 x 64 halves)
#pragma unroll
        for (int it = 0; it < 4; it++) {
            int idx = it * 256 + tid;
            int row = idx >> 3, qd = idx & 7;
            long go = (long)(t0 + row) * 4096 + qd * 8;
            reinterpret_cast<uint4*>(KH)[row * 9 + qd] =
                *reinterpret_cast<const uint4*>(Kbh + go);
            reinterpret_cast<uint4*>(KL)[row * 9 + qd] =
                *reinterpret_cast<const uint4*>(Kbl + go);
        }
        // ---- stage VT tile (64 rows x 128 halves = 16 uint4/row per plane)
#pragma unroll
        for (int it = 0; it < 4; it++) {
            int idx = it * 256 + tid;
            int row = idx >> 4, c = idx & 15;
            long go = (long)row * 1024 + t0 + c * 8;
            reinterpret_cast<uint4*>(PH)[row * 17 + c] =
                *reinterpret_cast<const uint4*>(Vbh + go);
            reinterpret_cast<uint4*>(PL)[row * 17 + c] =
                *reinterpret_cast<const uint4*>(Vbl + go);
        }
        __syncthreads();

        // ---- S = Q K^T (f16x3); 0.125 already folded into Q
        float acc[16][4];
#pragma unroll
        for (int nt = 0; nt < 16; nt++)
#pragma unroll
            for (int c = 0; c < 4; c++) acc[nt][c] = 0.0f;
#pragma unroll
        for (int nt = 0; nt < 16; nt++) {
#pragma unroll
            for (int ks = 0; ks < 4; ks++) {
                int base = (nt * 8 + g) * KWORDS + ks * 8 + tig;
                uint32_t bh[2] = {KH[base], KH[base + 4]};
                uint32_t bl[2] = {KL[base], KL[base + 4]};
                mma_f16(acc[nt], qh[ks], bh);
                mma_f16(acc[nt], qh[ks], bl);
                mma_f16(acc[nt], ql[ks], bh);
            }
        }

        // ---- online softmax stats (rows g and g+8, quad shuffles)
        float m0 = -1e30f, m1 = -1e30f;
#pragma unroll
        for (int nt = 0; nt < 16; nt++) {
            m0 = fmaxf(m0, fmaxf(acc[nt][0], acc[nt][1]));
            m1 = fmaxf(m1, fmaxf(acc[nt][2], acc[nt][3]));
        }
        m0 = fmaxf(m0, __shfl_xor_sync(0xffffffffu, m0, 1));
        m0 = fmaxf(m0, __shfl_xor_sync(0xffffffffu, m0, 2));
        m1 = fmaxf(m1, __shfl_xor_sync(0xffffffffu, m1, 1));
        m1 = fmaxf(m1, __shfl_xor_sync(0xffffffffu, m1, 2));
        float Mn0 = fmaxf(M0, m0), Mn1 = fmaxf(M1, m1);
        float a0 = __expf(M0 - Mn0), a1 = __expf(M1 - Mn1);
        M0 = Mn0; M1 = Mn1;

        float s0 = 0.0f, s1 = 0.0f;
#pragma unroll
        for (int nt = 0; nt < 16; nt++) {
            acc[nt][0] = __expf(acc[nt][0] - M0);
            acc[nt][1] = __expf(acc[nt][1] - M0);
            acc[nt][2] = __expf(acc[nt][2] - M1);
            acc[nt][3] = __expf(acc[nt][3] - M1);
            s0 += acc[nt][0] + acc[nt][1];
            s1 += acc[nt][2] + acc[nt][3];
        }
        s0 += __shfl_xor_sync(0xffffffffu, s0, 1);
        s0 += __shfl_xor_sync(0xffffffffu, s0, 2);
        s1 += __shfl_xor_sync(0xffffffffu, s1, 1);
        s1 += __shfl_xor_sync(0xffffffffu, s1, 2);
        T0 = T0 * a0 + s0;
        T1 = T1 * a1 + s1;
#pragma unroll
        for (int d8 = 0; d8 < 8; d8++) {
            ctx[d8][0] *= a0; ctx[d8][1] *= a0;
            ctx[d8][2] *= a1; ctx[d8][3] *= a1;
        }

        // ---- PV: P (register score fragments, split on the fly) x VT
#pragma unroll
        for (int c = 0; c < 8; c++) {
            uint32_t ah[4], al[4];
            split2(acc[2 * c][0],     acc[2 * c][1],     ah[0], al[0]);
            split2(acc[2 * c][2],     acc[2 * c][3],     ah[1], al[1]);
            split2(acc[2 * c + 1][0], acc[2 * c + 1][1], ah[2], al[2]);
            split2(acc[2 * c + 1][2], acc[2 * c + 1][3], ah[3], al[3]);
#pragma unroll
            for (int d8 = 0; d8 < 8; d8++) {
                int base = (d8 * 8 + g) * VWORDS + c * 8 + tig;
                uint32_t bh[2] = {PH[base], PH[base + 4]};
                uint32_t bl[2] = {PL[base], PL[base + 4]};
                mma_f16(ctx[d8], ah, bh);
                mma_f16(ctx[d8], ah, bl);
                mma_f16(ctx[d8], al, bh);
            }
        }
        __syncthreads();
    }

    // ---- normalize and write ctx hi/lo planes
    float i0 = 1.0f / T0, i1 = 1.0f / T1;
    const long r0 = q0 + warp * 16 + g;
#pragma unroll
    for (int d8 = 0; d8 < 8; d8++) {
        long col = (long)z * 64 + d8 * 8 + tig * 2;
        uint32_t h, l;
        split2(ctx[d8][0] * i0, ctx[d8][1] * i0, h, l);
        *reinterpret_cast<uint32_t*>(Oh + r0 * 4096 + col) = h;
        *reinterpret_cast<uint32_t*>(Ol + r0 * 4096 + col) = l;
        split2(ctx[d8][2] * i1, ctx[d8][3] * i1, h, l);
        *reinterpret_cast<uint32_t*>(Oh + (r0 + 8) * 4096 + col) = h;
        *reinterpret_cast<uint32_t*>(Ol + (r0 + 8) * 4096 + col) = l;
    }
}

// ---------------------------------------------------------------------------
// Output projection: ctx hi/lo planes x Wo_k (exact fp16) — 2 passes.
//   out[m,n] = (sum_k ctx[m,k]*Wo_k[n,k]) * (a_wo/48) + bo[n]
// ---------------------------------------------------------------------------
__global__ __launch_bounds__(256) void gemm_ctx_wo_kernel(
    const __half* __restrict__ Ahp, const __half* __restrict__ Alp,
    const __half* __restrict__ B,
    float* __restrict__ C, const float* __restrict__ bias,
    const float* __restrict__ aB) {
    const int K = E_;
    __shared__ __align__(16) __half Ah[128 * 40];
    __shared__ __align__(16) __half Al[128 * 40];
    __shared__ __align__(16) __half Bs[128 * 40];

    const int tid  = threadIdx.x;
    const int warp = tid >> 5;
    const int lane = tid & 31;
    const int g    = lane >> 2;
    const int tig  = lane & 3;

    const int m0 = blockIdx.y * 128;
    const int n0 = blockIdx.x * 128;
    const int wm = (warp >> 2) * 64;
    const int wn = (warp & 3) * 32;

    float acc[4][4][4];
#pragma unroll
    for (int mt = 0; mt < 4; mt++)
#pragma unroll
        for (int nt = 0; nt < 4; nt++)
#pragma unroll
            for (int c = 0; c < 4; c++) acc[mt][nt][c] = 0.0f;

    const uint32_t* Ahw = reinterpret_cast<const uint32_t*>(Ah);
    const uint32_t* Alw = reinterpret_cast<const uint32_t*>(Al);
    const uint32_t* Bw  = reinterpret_cast<const uint32_t*>(Bs);
    const int WSTR = 20;

    // prefetch: A planes 2 uint4/thread each, B 2 int4/thread
    int4 pah[2], pal[2], pb[2];
#pragma unroll
    for (int it = 0; it < 2; it++) {
        int idx = it * 256 + tid;          // 512 uint4 per plane per chunk
        int row = idx >> 2, qd = idx & 3;  // 128 rows x 4 uint4 (32 halves)
        long go = (long)(m0 + row) * K + qd * 8;
        pah[it] = *reinterpret_cast<const int4*>(Ahp + go);
        pal[it] = *reinterpret_cast<const int4*>(Alp + go);
        pb[it] = *reinterpret_cast<const int4*>(
            B + (long)(n0 + (idx >> 2)) * K + (idx & 3) * 8);
    }

    for (int k0 = 0; k0 < K; k0 += 32) {
#pragma unroll
        for (int it = 0; it < 2; it++) {
            int idx = it * 256 + tid;
            int row = idx >> 2, qd = idx & 3;
            reinterpret_cast<int4*>(Ah)[row * 5 + qd] = pah[it];
            reinterpret_cast<int4*>(Al)[row * 5 + qd] = pal[it];
            reinterpret_cast<int4*>(Bs)[row * 5 + qd] = pb[it];
        }
        __syncthreads();

        if (k0 + 32 < K) {
#pragma unroll
            for (int it = 0; it < 2; it++) {
                int idx = it * 256 + tid;
                int row = idx >> 2, qd = idx & 3;
                long goA = (long)(m0 + row) * K + k0 + 32 + qd * 8;
                pah[it] = *reinterpret_cast<const int4*>(Ahp + goA);
                pal[it] = *reinterpret_cast<const int4*>(Alp + goA);
                pb[it] = *reinterpret_cast<const int4*>(
                    B + (long)(n0 + row) * K + k0 + 32 + qd * 8);
            }
        }

#pragma unroll
        for (int ks = 0; ks < 2; ks++) {
            uint32_t ah[4][4], al[4][4], bf[4][2];
#pragma unroll
            for (int mt = 0; mt < 4; mt++) {
                int base = (wm + mt * 16 + g) * WSTR + ks * 8 + tig;
                ah[mt][0] = Ahw[base];
                ah[mt][1] = Ahw[base + 8 * WSTR];
                ah[mt][2] = Ahw[base + 4];
                ah[mt][3] = Ahw[base + 8 * WSTR + 4];
                al[mt][0] = Alw[base];
                al[mt][1] = Alw[base + 8 * WSTR];
                al[mt][2] = Alw[base + 4];
                al[mt][3] = Alw[base + 8 * WSTR + 4];
            }
#pragma unroll
            for (int nt = 0; nt < 4; nt++) {
                int base = (wn + nt * 8 + g) * WSTR + ks * 8 + tig;
                bf[nt][0] = Bw[base];
                bf[nt][1] = Bw[base + 4];
            }
#pragma unroll
            for (int mt = 0; mt < 4; mt++)
#pragma unroll
                for (int nt = 0; nt < 4; nt++) {
                    mma_f16(acc[mt][nt], ah[mt], bf[nt]);
                    mma_f16(acc[mt][nt], al[mt], bf[nt]);
                }
        }
        __syncthreads();
    }

    const float scale = __ldg(aB) * (1.0f / 48.0f);
#pragma unroll
    for (int mt = 0; mt < 4; mt++) {
#pragma unroll
        for (int nt = 0; nt < 4; nt++) {
            long row = m0 + wm + mt * 16 + g;
            long col = n0 + wn + nt * 8 + tig * 2;
            float b0 = bias[col], b1 = bias[col + 1];
            float2 v0, v1;
            v0.x = acc[mt][nt][0] * scale + b0;
            v0.y = acc[mt][nt][1] * scale + b1;
            v1.x = acc[mt][nt][2] * scale + b0;
            v1.y = acc[mt][nt][3] * scale + b1;
            *reinterpret_cast<float2*>(C + row * (long)E_ + col) = v0;
            *reinterpret_cast<float2*>(C + (row + 8) * (long)E_ + col) = v1;
        }
    }
}

// ---------------------------------------------------------------------------
// Orchestration.
// ---------------------------------------------------------------------------
extern "C" void kernel_launch(void* const* d_in, const int* in_sizes, int n_in,
                              void* d_out, int out_size) {
    const float* q    = (const float*)d_in[0];
    const float* k    = (const float*)d_in[1];
    const float* v    = (const float*)d_in[2];
    const float* Wi   = (const float*)d_in[3];
    const float* bi   = (const float*)d_in[4];
    const float* Wo   = (const float*)d_in[5];
    const float* bo   = (const float*)d_in[6];
    const float* a_act = (const float*)d_in[7];
    const float* a_wi  = (const float*)d_in[8];
    const float* a_bi  = (const float*)d_in[9];
    const float* a_wo  = (const float*)d_in[10];
    const float* a_bo  = (const float*)d_in[11];
    float* out = (float*)d_out;

    int8_t *p_Wi8, *p_act8;
    __half *p_Woh, *p_ph, *p_pl, *p_vTh, *p_vTl, *p_cxh, *p_cxl;
    float *p_bi, *p_bo;
    cudaGetSymbolAddress((void**)&p_Wi8, g_Wi_i8);
    cudaGetSymbolAddress((void**)&p_act8, g_act_i8);
    cudaGetSymbolAddress((void**)&p_Woh, g_Wo_h);
    cudaGetSymbolAddress((void**)&p_bi, g_bi);
    cudaGetSymbolAddress((void**)&p_bo, g_bo);
    cudaGetSymbolAddress((void**)&p_ph, g_proj_h);
    cudaGetSymbolAddress((void**)&p_pl, g_proj_l);
    cudaGetSymbolAddress((void**)&p_vTh, g_vpT_h);
    cudaGetSymbolAddress((void**)&p_vTl, g_vpT_l);
    cudaGetSymbolAddress((void**)&p_cxh, g_ctx_h);
    cudaGetSymbolAddress((void**)&p_cxl, g_ctx_l);

    const long RE = (long)R_ * E_;

    cudaFuncSetAttribute(flash_attn_kernel,
                         cudaFuncAttributeMaxDynamicSharedMemorySize,
                         SM_TOTAL_FLASH);

    init_tables_kernel<<<1, 1>>>();

    // Weight + bias quantization
    quant_weight_rows_kernel<0><<<3 * E_, 256>>>(Wi, p_Wi8, nullptr, a_wi);
    quant_weight_rows_kernel<1><<<E_, 256>>>(Wo, nullptr, p_Woh, a_wo);
    quant_bias_kernel<<<16, 256>>>(bi, bo, p_bi, p_bo, a_bi, a_bo);

    // Activation quantization -> int8 k-values (one z-batched launch)
    quant_act_i8_kernel<<<dim3(RE / 1024, 3), 256>>>(q, k, v, p_act8, a_act);

    // Projections via int8 tensor cores (exact) -> fp16 hi/lo planes
    gemm_i8_kernel<<<dim3(E_ / 128, R_ / 128, 3), 256>>>(
        p_act8, p_Wi8, p_ph, p_pl, p_bi, a_act, a_wi, E_, E_);

    // Transpose vp planes per head (B-operand layout for PV)
    transpose_v_kernel<<<dim3(S_ / 32, D_ / 32, Z_), dim3(32, 8)>>>(
        p_ph + 2 * RE, p_pl + 2 * RE, p_vTh, p_vTl);

    // Fused attention: scores + online softmax + PV -> ctx planes
    flash_attn_kernel<<<dim3(S_ / 128, Z_), 256, SM_TOTAL_FLASH>>>(
        p_ph, p_pl, p_ph + RE, p_pl + RE, p_vTh, p_vTl, p_cxh, p_cxl);

    // Output projection: ctx planes x Wo_k (exact fp16, 2 passes) -> out
    gemm_ctx_wo_kernel<<<dim3(8, 32), 256>>>(p_cxh, p_cxl, p_Woh, out, p_bo,
                                             a_wo);
}

// round 13
// speedup vs baseline: 5.3587x; 1.0740x over previous
#include <cuda_runtime.h>
#include <cuda_fp16.h>
#include <math.h>
#include <stdint.h>

#define EPSQ 1e-5f

// Problem sizes (fixed by the reference setup_inputs)
#define S_ 1024
#define B_ 4
#define E_ 1024
#define H_ 16
#define D_ 64
#define R_ (S_*B_)   // 4096 flattened (s,b) rows
#define Z_ (B_*H_)   // 64 batched heads

// ---------------------------------------------------------------------------
// Static device scratch (no runtime allocation allowed)
// ---------------------------------------------------------------------------
__device__ float g_LN[31];
__device__ float g_MIDS[30];
__device__ int   g_LN48[31];

__device__ __align__(16) int8_t g_Wi_i8[3*E_*E_];
__device__ __align__(16) __half g_Wo_h[E_*E_];         // Wo k-values (exact fp16)
__device__ __align__(16) float  g_bi[3*E_];
__device__ __align__(16) float  g_bo[E_];
__device__ __align__(16) int8_t g_act_i8[3L*R_*E_];
__device__ __align__(16) __half g_proj_h[3L*R_*E_];    // qp,kp,vp hi plane
__device__ __align__(16) __half g_proj_l[3L*R_*E_];    // qp,kp,vp lo plane
__device__ __align__(16) __half g_vpT_h[(long)Z_*D_*S_];
__device__ __align__(16) __half g_vpT_l[(long)Z_*D_*S_];
__device__ __align__(16) __half g_ctx_h[(long)R_*E_];
__device__ __align__(16) __half g_ctx_l[(long)R_*E_];

// ---------------------------------------------------------------------------
// cp.async helpers
// ---------------------------------------------------------------------------
__device__ __forceinline__ void cp_async16(void* smem_ptr, const void* gptr) {
    uint32_t a = (uint32_t)__cvta_generic_to_shared(smem_ptr);
    asm volatile("cp.async.cg.shared.global [%0], [%1], 16;"
                 :: "r"(a), "l"(gptr));
}
#define CP_COMMIT() asm volatile("cp.async.commit_group;" ::: "memory")
#define CP_WAIT0()  asm volatile("cp.async.wait_group 0;" ::: "memory")

// ---------------------------------------------------------------------------
// APoT tables (exact float emulation of the numpy construction)
// ---------------------------------------------------------------------------
__global__ void init_tables_kernel() {
    const float pos[15] = {0.03125f, 0.0625f, 0.09375f, 0.125f, 0.1875f,
                           0.25f, 0.28125f, 0.375f, 0.5f, 0.5625f,
                           0.75f, 1.0f, 1.03125f, 1.125f, 1.5f};
    const float G = (float)(1.0 / 1.5);
    for (int i = 0; i < 15; i++) {
        g_LN[i]      = (-pos[14 - i]) * G;
        g_LN[16 + i] = pos[i] * G;
    }
    g_LN[15] = 0.0f;
    for (int i = 0; i < 30; i++)
        g_MIDS[i] = (g_LN[i] + g_LN[i + 1]) * 0.5f;
    for (int i = 0; i < 31; i++)
        g_LN48[i] = (int)lrintf(g_LN[i] * 48.0f);
}

// Binary-search count(MD[i] < xc) over 30 sorted mids (== searchsorted left).
__device__ __forceinline__ int rcf_idx(float x, float alpha,
                                       const float* __restrict__ MD) {
    float xn = x / (alpha + EPSQ);
    float xc = fminf(1.0f, fmaxf(-1.0f, xn));
    int c = 0;
    if (MD[15] < xc) c = 16;
    if (c + 8 <= 30 && MD[c + 7] < xc) c += 8;
    if (c + 4 <= 30 && MD[c + 3] < xc) c += 4;
    if (c + 2 <= 30 && MD[c + 1] < xc) c += 2;
    if (c + 1 <= 30 && MD[c] < xc) c += 1;
    return c;
}
__device__ __forceinline__ float rcf_dev(float x, float alpha,
                                         const float* __restrict__ LN,
                                         const float* __restrict__ MD) {
    return LN[rcf_idx(x, alpha, MD)] * alpha;
}

// ---------------------------------------------------------------------------
// Bias quantization: bi (3072) and bo (1024) in ONE launch (16 blocks).
// ---------------------------------------------------------------------------
__global__ void quant_bias_kernel(const float* __restrict__ bi,
                                  const float* __restrict__ bo,
                                  float* __restrict__ ybi,
                                  float* __restrict__ ybo,
                                  const float* __restrict__ abi,
                                  const float* __restrict__ abo) {
    __shared__ float LN[31], MD[30];
    if (threadIdx.x < 31) LN[threadIdx.x] = g_LN[threadIdx.x];
    if (threadIdx.x < 30) MD[threadIdx.x] = g_MIDS[threadIdx.x];
    __syncthreads();
    int b = blockIdx.x;
    if (b < 12) {
        int i = b * 256 + threadIdx.x;
        ybi[i] = rcf_dev(bi[i], abi[0], LN, MD);
    } else {
        int i = (b - 12) * 256 + threadIdx.x;
        ybo[i] = rcf_dev(bo[i], abo[0], LN, MD);
    }
}

// ---------------------------------------------------------------------------
// Activation quantization -> int8 k-values; q/k/v in one z-batched launch.
// ---------------------------------------------------------------------------
__global__ void quant_act_i8_kernel(const float* __restrict__ q,
                                    const float* __restrict__ k,
                                    const float* __restrict__ v,
                                    int8_t* __restrict__ y,
                                    const float* __restrict__ alpha_p) {
    __shared__ float MD[30];
    __shared__ int   L48[31];
    if (threadIdx.x < 30) MD[threadIdx.x] = g_MIDS[threadIdx.x];
    if (threadIdx.x < 31) L48[threadIdx.x] = g_LN48[threadIdx.x];
    __syncthreads();
    const float* x = (blockIdx.y == 0) ? q : (blockIdx.y == 1) ? k : v;
    int8_t* yy = y + (long)blockIdx.y * R_ * E_;
    float a = alpha_p[0];
    long i0 = ((long)blockIdx.x * blockDim.x + threadIdx.x) * 4;
    float4 vv = *reinterpret_cast<const float4*>(x + i0);
    char4 o;
    o.x = (int8_t)L48[rcf_idx(vv.x, a, MD)];
    o.y = (int8_t)L48[rcf_idx(vv.y, a, MD)];
    o.z = (int8_t)L48[rcf_idx(vv.z, a, MD)];
    o.w = (int8_t)L48[rcf_idx(vv.w, a, MD)];
    *reinterpret_cast<char4*>(yy + i0) = o;
}

// ---------------------------------------------------------------------------
// Weight quantization: one block per row, single global read, float warp
// reductions (2 syncs). OUT==0 -> int8 k-values; OUT==1 -> fp16 k-values.
// ---------------------------------------------------------------------------
template <int OUT>
__global__ void quant_weight_rows_kernel(const float* __restrict__ W,
                                         int8_t* __restrict__ Wq8,
                                         __half* __restrict__ Wqh,
                                         const float* __restrict__ alpha_p) {
    __shared__ float MD[30];
    __shared__ int   L48[31];
    __shared__ float red[8];
    const int row = blockIdx.x, tid = threadIdx.x;
    const int lane = tid & 31, warp = tid >> 5;
    if (tid < 30) MD[tid] = g_MIDS[tid];
    if (tid < 31) L48[tid] = g_LN48[tid];
    const float* w = W + (long)row * E_;

    float4 w4 = *reinterpret_cast<const float4*>(w + tid * 4);

    float s = w4.x + w4.y + w4.z + w4.w;
#pragma unroll
    for (int o = 16; o > 0; o >>= 1) s += __shfl_xor_sync(0xffffffffu, s, o);
    if (lane == 0) red[warp] = s;
    __syncthreads();
    float tot = red[0];
#pragma unroll
    for (int i = 1; i < 8; i++) tot += red[i];
    float mu = tot * (1.0f / E_);

    float dx = w4.x - mu, dy = w4.y - mu, dz = w4.z - mu, dw = w4.w - mu;
    float s2 = dx * dx + dy * dy + dz * dz + dw * dw;
#pragma unroll
    for (int o = 16; o > 0; o >>= 1) s2 += __shfl_xor_sync(0xffffffffu, s2, o);
    __syncthreads();
    if (lane == 0) red[warp] = s2;
    __syncthreads();
    float tot2 = red[0];
#pragma unroll
    for (int i = 1; i < 8; i++) tot2 += red[i];
    float var = tot2 * (1.0f / E_);

    float inv = 1.0f / sqrtf(var + EPSQ);
    float a = alpha_p[0];
    int k0 = L48[rcf_idx(dx * inv, a, MD)];
    int k1 = L48[rcf_idx(dy * inv, a, MD)];
    int k2 = L48[rcf_idx(dz * inv, a, MD)];
    int k3 = L48[rcf_idx(dw * inv, a, MD)];
    if (OUT == 0) {
        char4 o;
        o.x = (int8_t)k0; o.y = (int8_t)k1; o.z = (int8_t)k2; o.w = (int8_t)k3;
        *reinterpret_cast<char4*>(Wq8 + (long)row * E_ + tid * 4) = o;
    } else {
        __half2 h01 = __floats2half2_rn((float)k0, (float)k1);
        __half2 h23 = __floats2half2_rn((float)k2, (float)k3);
        uint2 pk;
        pk.x = *reinterpret_cast<uint32_t*>(&h01);
        pk.y = *reinterpret_cast<uint32_t*>(&h23);
        *reinterpret_cast<uint2*>(Wqh + (long)row * E_ + tid * 4) = pk;
    }
}

// ---------------------------------------------------------------------------
// fp16 split helper
// ---------------------------------------------------------------------------
__device__ __forceinline__ void split2(float a, float b, uint32_t& hi,
                                       uint32_t& lo) {
    __half2 h = __floats2half2_rn(a, b);
    __half2 l = __floats2half2_rn(a - __low2float(h), b - __high2float(h));
    hi = *reinterpret_cast<uint32_t*>(&h);
    lo = *reinterpret_cast<uint32_t*>(&l);
}

// ---------------------------------------------------------------------------
// int8 tensor-core projection GEMM with cp.async smem ping-pong.
// Epilogue writes fp16 hi/lo planes; q-section (z==0) folds the 0.125 scale.
// ---------------------------------------------------------------------------
__device__ __forceinline__ void mma_i8(int* d, const uint32_t* a,
                                       const uint32_t* b) {
    asm volatile(
        "mma.sync.aligned.m16n8k32.row.col.s32.s8.s8.s32 "
        "{%0,%1,%2,%3}, {%4,%5,%6,%7}, {%8,%9}, {%0,%1,%2,%3};\n"
        : "+r"(d[0]), "+r"(d[1]), "+r"(d[2]), "+r"(d[3])
        : "r"(a[0]), "r"(a[1]), "r"(a[2]), "r"(a[3]), "r"(b[0]), "r"(b[1]));
}

#define I8_STRIDE 80

__global__ __launch_bounds__(256) void gemm_i8_kernel(
    const int8_t* __restrict__ A, const int8_t* __restrict__ B,
    __half* __restrict__ Ch, __half* __restrict__ Cl,
    const float* __restrict__ bias,
    const float* __restrict__ aA, const float* __restrict__ aB,
    int K, int N) {
    __shared__ __align__(16) int8_t As[2][128 * I8_STRIDE];
    __shared__ __align__(16) int8_t Bs[2][128 * I8_STRIDE];

    const int tid  = threadIdx.x;
    const int warp = tid >> 5;
    const int lane = tid & 31;
    const int g    = lane >> 2;
    const int tig  = lane & 3;

    const long z = blockIdx.z;
    A += z * (long)R_ * K;
    B += z * (long)N * K;
    Ch += z * (long)R_ * N;
    Cl += z * (long)R_ * N;
    bias += z * N;

    const int m0 = blockIdx.y * 128;
    const int n0 = blockIdx.x * 128;
    const int wm = (warp >> 2) * 64;
    const int wn = (warp & 3) * 32;

    int acc[4][4][4];
#pragma unroll
    for (int a_ = 0; a_ < 4; a_++)
#pragma unroll
        for (int b_ = 0; b_ < 4; b_++)
#pragma unroll
            for (int c_ = 0; c_ < 4; c_++) acc[a_][b_][c_] = 0;

    const int WSTR = I8_STRIDE / 4;

    // prologue: chunk 0 -> stage 0
#pragma unroll
    for (int it = 0; it < 2; it++) {
        int idx = it * 256 + tid;
        int row = idx >> 2, c = idx & 3;
        cp_async16(&As[0][row * I8_STRIDE + c * 16],
                   A + (long)(m0 + row) * K + c * 16);
        cp_async16(&Bs[0][row * I8_STRIDE + c * 16],
                   B + (long)(n0 + row) * K + c * 16);
    }
    CP_COMMIT();

    int stage = 0;
    for (int k0 = 0; k0 < K; k0 += 64) {
        CP_WAIT0();
        __syncthreads();
        if (k0 + 64 < K) {
#pragma unroll
            for (int it = 0; it < 2; it++) {
                int idx = it * 256 + tid;
                int row = idx >> 2, c = idx & 3;
                cp_async16(&As[stage ^ 1][row * I8_STRIDE + c * 16],
                           A + (long)(m0 + row) * K + k0 + 64 + c * 16);
                cp_async16(&Bs[stage ^ 1][row * I8_STRIDE + c * 16],
                           B + (long)(n0 + row) * K + k0 + 64 + c * 16);
            }
            CP_COMMIT();
        }

        const uint32_t* Aw = reinterpret_cast<const uint32_t*>(As[stage]);
        const uint32_t* Bw = reinterpret_cast<const uint32_t*>(Bs[stage]);
#pragma unroll
        for (int ks = 0; ks < 2; ks++) {
            uint32_t af[4][4], bf[4][2];
#pragma unroll
            for (int mt = 0; mt < 4; mt++) {
                int base = (wm + mt * 16 + g) * WSTR + ks * 8 + tig;
                af[mt][0] = Aw[base];
                af[mt][1] = Aw[base + 8 * WSTR];
                af[mt][2] = Aw[base + 4];
                af[mt][3] = Aw[base + 8 * WSTR + 4];
            }
#pragma unroll
            for (int nt = 0; nt < 4; nt++) {
                int base = (wn + nt * 8 + g) * WSTR + ks * 8 + tig;
                bf[nt][0] = Bw[base];
                bf[nt][1] = Bw[base + 4];
            }
#pragma unroll
            for (int mt = 0; mt < 4; mt++)
#pragma unroll
                for (int nt = 0; nt < 4; nt++)
                    mma_i8(acc[mt][nt], af[mt], bf[nt]);
        }
        stage ^= 1;
    }

    // fold exact 1/8 score scale into the q section (z==0)
    const float f = (z == 0) ? 0.125f : 1.0f;
    const float scale = __ldg(aA) * __ldg(aB) * (1.0f / 2304.0f) * f;
#pragma unroll
    for (int mt = 0; mt < 4; mt++) {
#pragma unroll
        for (int nt = 0; nt < 4; nt++) {
            long row = m0 + wm + mt * 16 + g;
            long col = n0 + wn + nt * 8 + tig * 2;
            float b0 = bias[col] * f, b1 = bias[col + 1] * f;
            float v00 = (float)acc[mt][nt][0] * scale + b0;
            float v01 = (float)acc[mt][nt][1] * scale + b1;
            float v10 = (float)acc[mt][nt][2] * scale + b0;
            float v11 = (float)acc[mt][nt][3] * scale + b1;
            uint32_t h, l;
            split2(v00, v01, h, l);
            *reinterpret_cast<uint32_t*>(Ch + row * N + col) = h;
            *reinterpret_cast<uint32_t*>(Cl + row * N + col) = l;
            split2(v10, v11, h, l);
            *reinterpret_cast<uint32_t*>(Ch + (row + 8) * N + col) = h;
            *reinterpret_cast<uint32_t*>(Cl + (row + 8) * N + col) = l;
        }
    }
}

// ---------------------------------------------------------------------------
// Per-head transpose of vp planes: vpT[z][d][t] = vp[t*4096 + 64*z + d]
// ---------------------------------------------------------------------------
__global__ void transpose_v_kernel(const __half* __restrict__ vph,
                                   const __half* __restrict__ vpl,
                                   __half* __restrict__ vpTh,
                                   __half* __restrict__ vpTl) {
    __shared__ ushort tile[32][33];
    const int z = blockIdx.z;
    const int t0 = blockIdx.x * 32;
    const int d0 = blockIdx.y * 32;
#pragma unroll
    for (int p = 0; p < 2; p++) {
        const ushort* src = reinterpret_cast<const ushort*>(p ? vpl : vph) + 64L * z;
        ushort* dst = reinterpret_cast<ushort*>(p ? vpTl : vpTh) + (long)z * D_ * S_;
        for (int r = threadIdx.y; r < 32; r += 8)
            tile[r][threadIdx.x] = src[(long)(t0 + r) * 4096 + d0 + threadIdx.x];
        __syncthreads();
        for (int r = threadIdx.y; r < 32; r += 8)
            dst[(long)(d0 + r) * S_ + t0 + threadIdx.x] = tile[threadIdx.x][r];
        __syncthreads();
    }
}

// ---------------------------------------------------------------------------
// fp16 mma helper
// ---------------------------------------------------------------------------
__device__ __forceinline__ void mma_f16(float* d, const uint32_t* a,
                                        const uint32_t* b) {
    asm volatile(
        "mma.sync.aligned.m16n8k16.row.col.f32.f16.f16.f32 "
        "{%0,%1,%2,%3}, {%4,%5,%6,%7}, {%8,%9}, {%0,%1,%2,%3};\n"
        : "+f"(d[0]), "+f"(d[1]), "+f"(d[2]), "+f"(d[3])
        : "r"(a[0]), "r"(a[1]), "r"(a[2]), "r"(a[3]), "r"(b[0]), "r"(b[1]));
}

// ---------------------------------------------------------------------------
// Fused flash attention with cp.async 2-stage K/V pipeline.
// Stage layout (bytes): KH @0, KL @STG_K, VH @2*STG_K, VL @2*STG_K+STG_V.
// ---------------------------------------------------------------------------
#define KWORDS 36
#define VWORDS 68
#define STG_K  18432
#define STG_V  17408
#define STG_SZ (2*STG_K + 2*STG_V)      // 71680
#define SM_TOTAL_FLASH (2 * STG_SZ)     // 143360

__global__ __launch_bounds__(256) void flash_attn_kernel(
    const __half* __restrict__ Qh, const __half* __restrict__ Ql,
    const __half* __restrict__ Kh_, const __half* __restrict__ Kl_,
    const __half* __restrict__ Vh, const __half* __restrict__ Vl,
    __half* __restrict__ Oh, __half* __restrict__ Ol) {
    extern __shared__ char sm[];

    const int tid = threadIdx.x;
    const int warp = tid >> 5, lane = tid & 31;
    const int g = lane >> 2, tig = lane & 3;
    const int z = blockIdx.y;
    const int q0 = blockIdx.x * 128;

    const __half* Qbh = Qh + (long)z * 64;     // s-stride 4096 halves
    const __half* Qbl = Ql + (long)z * 64;
    const __half* Kbh = Kh_ + (long)z * 64;
    const __half* Kbl = Kl_ + (long)z * 64;
    const __half* Vbh = Vh + (long)z * D_ * S_;
    const __half* Vbl = Vl + (long)z * D_ * S_;

    // ---- prologue: Q -> stage1 K-region; tile0 K,V -> stage0 (all cp.async)
#pragma unroll
    for (int it = 0; it < 4; it++) {
        int idx = it * 256 + tid;
        int row = idx >> 3, qd = idx & 7;           // K/Q: 128 rows x 8 uint4
        long gq = (long)(q0 + row) * 4096 + qd * 8;
        cp_async16(sm + STG_SZ + (row * 9 + qd) * 16, Qbh + gq);
        cp_async16(sm + STG_SZ + STG_K + (row * 9 + qd) * 16, Qbl + gq);
        long gk = (long)row * 4096 + qd * 8;        // t0 = 0
        cp_async16(sm + (row * 9 + qd) * 16, Kbh + gk);
        cp_async16(sm + STG_K + (row * 9 + qd) * 16, Kbl + gk);
        int vr = idx >> 4, vc = idx & 15;           // V: 64 rows x 16 uint4
        long gv = (long)vr * 1024 + vc * 8;         // t0 = 0
        cp_async16(sm + 2 * STG_K + (vr * 17 + vc) * 16, Vbh + gv);
        cp_async16(sm + 2 * STG_K + STG_V + (vr * 17 + vc) * 16, Vbl + gv);
    }
    CP_COMMIT();
    CP_WAIT0();
    __syncthreads();

    // ---- extract Q fragments from stage1 K-region
    uint32_t qh[4][4], ql[4][4];
    {
        const uint32_t* QH = reinterpret_cast<const uint32_t*>(sm + STG_SZ);
        const uint32_t* QL = reinterpret_cast<const uint32_t*>(sm + STG_SZ + STG_K);
#pragma unroll
        for (int ks = 0; ks < 4; ks++) {
            int base = (warp * 16 + g) * KWORDS + ks * 8 + tig;
            qh[ks][0] = QH[base];
            qh[ks][1] = QH[base + 8 * KWORDS];
            qh[ks][2] = QH[base + 4];
            qh[ks][3] = QH[base + 8 * KWORDS + 4];
            ql[ks][0] = QL[base];
            ql[ks][1] = QL[base + 8 * KWORDS];
            ql[ks][2] = QL[base + 4];
            ql[ks][3] = QL[base + 8 * KWORDS + 4];
        }
    }
    __syncthreads();   // stage1 free for tile1 copies

    float ctx[8][4];
#pragma unroll
    for (int d8 = 0; d8 < 8; d8++)
#pragma unroll
        for (int c = 0; c < 4; c++) ctx[d8][c] = 0.0f;
    float M0 = -1e30f, M1 = -1e30f, T0 = 0.0f, T1 = 0.0f;

    int stage = 0;
    for (int t0 = 0; t0 < S_; t0 += 128) {
        // ---- issue next tile into the other stage (overlaps compute)
        if (t0 + 128 < S_) {
            char* d = sm + (stage ^ 1) * STG_SZ;
#pragma unroll
            for (int it = 0; it < 4; it++) {
                int idx = it * 256 + tid;
                int row = idx >> 3, qd = idx & 7;
                long gk = (long)(t0 + 128 + row) * 4096 + qd * 8;
                cp_async16(d + (row * 9 + qd) * 16, Kbh + gk);
                cp_async16(d + STG_K + (row * 9 + qd) * 16, Kbl + gk);
                int vr = idx >> 4, vc = idx & 15;
                long gv = (long)vr * 1024 + t0 + 128 + vc * 8;
                cp_async16(d + 2 * STG_K + (vr * 17 + vc) * 16, Vbh + gv);
                cp_async16(d + 2 * STG_K + STG_V + (vr * 17 + vc) * 16, Vbl + gv);
            }
            CP_COMMIT();
        }

        const uint32_t* KH = reinterpret_cast<const uint32_t*>(sm + stage * STG_SZ);
        const uint32_t* KL = reinterpret_cast<const uint32_t*>(sm + stage * STG_SZ + STG_K);
        const uint32_t* PH = reinterpret_cast<const uint32_t*>(sm + stage * STG_SZ + 2 * STG_K);
        const uint32_t* PL = reinterpret_cast<const uint32_t*>(sm + stage * STG_SZ + 2 * STG_K + STG_V);

        // ---- S = Q K^T (f16x3); 0.125 already folded into Q
        float acc[16][4];
#pragma unroll
        for (int nt = 0; nt < 16; nt++)
#pragma unroll
            for (int c = 0; c < 4; c++) acc[nt][c] = 0.0f;
#pragma unroll
        for (int nt = 0; nt < 16; nt++) {
#pragma unroll
            for (int ks = 0; ks < 4; ks++) {
                int base = (nt * 8 + g) * KWORDS + ks * 8 + tig;
                uint32_t bh[2] = {KH[base], KH[base + 4]};
                uint32_t bl[2] = {KL[base], KL[base + 4]};
                mma_f16(acc[nt], qh[ks], bh);
                mma_f16(acc[nt], qh[ks], bl);
                mma_f16(acc[nt], ql[ks], bh);
            }
        }

        // ---- online softmax stats (rows g and g+8, quad shuffles)
        float m0 = -1e30f, m1 = -1e30f;
#pragma unroll
        for (int nt = 0; nt < 16; nt++) {
            m0 = fmaxf(m0, fmaxf(acc[nt][0], acc[nt][1]));
            m1 = fmaxf(m1, fmaxf(acc[nt][2], acc[nt][3]));
        }
        m0 = fmaxf(m0, __shfl_xor_sync(0xffffffffu, m0, 1));
        m0 = fmaxf(m0, __shfl_xor_sync(0xffffffffu, m0, 2));
        m1 = fmaxf(m1, __shfl_xor_sync(0xffffffffu, m1, 1));
        m1 = fmaxf(m1, __shfl_xor_sync(0xffffffffu, m1, 2));
        float Mn0 = fmaxf(M0, m0), Mn1 = fmaxf(M1, m1);
        float a0 = __expf(M0 - Mn0), a1 = __expf(M1 - Mn1);
        M0 = Mn0; M1 = Mn1;

        float s0 = 0.0f, s1 = 0.0f;
#pragma unroll
        for (int nt = 0; nt < 16; nt++) {
            acc[nt][0] = __expf(acc[nt][0] - M0);
            acc[nt][1] = __expf(acc[nt][1] - M0);
            acc[nt][2] = __expf(acc[nt][2] - M1);
            acc[nt][3] = __expf(acc[nt][3] - M1);
            s0 += acc[nt][0] + acc[nt][1];
            s1 += acc[nt][2] + acc[nt][3];
        }
        s0 += __shfl_xor_sync(0xffffffffu, s0, 1);
        s0 += __shfl_xor_sync(0xffffffffu, s0, 2);
        s1 += __shfl_xor_sync(0xffffffffu, s1, 1);
        s1 += __shfl_xor_sync(0xffffffffu, s1, 2);
        T0 = T0 * a0 + s0;
        T1 = T1 * a1 + s1;
#pragma unroll
        for (int d8 = 0; d8 < 8; d8++) {
            ctx[d8][0] *= a0; ctx[d8][1] *= a0;
            ctx[d8][2] *= a1; ctx[d8][3] *= a1;
        }

        // ---- PV: P (register score fragments, split on the fly) x VT
#pragma unroll
        for (int c = 0; c < 8; c++) {
            uint32_t ah[4], al[4];
            split2(acc[2 * c][0],     acc[2 * c][1],     ah[0], al[0]);
            split2(acc[2 * c][2],     acc[2 * c][3],     ah[1], al[1]);
            split2(acc[2 * c + 1][0], acc[2 * c + 1][1], ah[2], al[2]);
            split2(acc[2 * c + 1][2], acc[2 * c + 1][3], ah[3], al[3]);
#pragma unroll
            for (int d8 = 0; d8 < 8; d8++) {
                int base = (d8 * 8 + g) * VWORDS + c * 8 + tig;
                uint32_t bh[2] = {PH[base], PH[base + 4]};
                uint32_t bl[2] = {PL[base], PL[base + 4]};
                mma_f16(ctx[d8], ah, bh);
                mma_f16(ctx[d8], ah, bl);
                mma_f16(ctx[d8], al, bh);
            }
        }

        CP_WAIT0();
        __syncthreads();
        stage ^= 1;
    }

    // ---- normalize and write ctx hi/lo planes
    float i0 = 1.0f / T0, i1 = 1.0f / T1;
    const long r0 = q0 + warp * 16 + g;
#pragma unroll
    for (int d8 = 0; d8 < 8; d8++) {
        long col = (long)z * 64 + d8 * 8 + tig * 2;
        uint32_t h, l;
        split2(ctx[d8][0] * i0, ctx[d8][1] * i0, h, l);
        *reinterpret_cast<uint32_t*>(Oh + r0 * 4096 + col) = h;
        *reinterpret_cast<uint32_t*>(Ol + r0 * 4096 + col) = l;
        split2(ctx[d8][2] * i1, ctx[d8][3] * i1, h, l);
        *reinterpret_cast<uint32_t*>(Oh + (r0 + 8) * 4096 + col) = h;
        *reinterpret_cast<uint32_t*>(Ol + (r0 + 8) * 4096 + col) = l;
    }
}

// ---------------------------------------------------------------------------
// Output projection: ctx hi/lo planes x Wo_k (exact fp16) — 2 passes.
//   out[m,n] = (sum_k ctx[m,k]*Wo_k[n,k]) * (a_wo/48) + bo[n]
// ---------------------------------------------------------------------------
__global__ __launch_bounds__(256) void gemm_ctx_wo_kernel(
    const __half* __restrict__ Ahp, const __half* __restrict__ Alp,
    const __half* __restrict__ B,
    float* __restrict__ C, const float* __restrict__ bias,
    const float* __restrict__ aB) {
    const int K = E_;
    __shared__ __align__(16) __half Ah[128 * 40];
    __shared__ __align__(16) __half Al[128 * 40];
    __shared__ __align__(16) __half Bs[128 * 40];

    const int tid  = threadIdx.x;
    const int warp = tid >> 5;
    const int lane = tid & 31;
    const int g    = lane >> 2;
    const int tig  = lane & 3;

    const int m0 = blockIdx.y * 128;
    const int n0 = blockIdx.x * 128;
    const int wm = (warp >> 2) * 64;
    const int wn = (warp & 3) * 32;

    float acc[4][4][4];
#pragma unroll
    for (int mt = 0; mt < 4; mt++)
#pragma unroll
        for (int nt = 0; nt < 4; nt++)
#pragma unroll
            for (int c = 0; c < 4; c++) acc[mt][nt][c] = 0.0f;

    const uint32_t* Ahw = reinterpret_cast<const uint32_t*>(Ah);
    const uint32_t* Alw = reinterpret_cast<const uint32_t*>(Al);
    const uint32_t* Bw  = reinterpret_cast<const uint32_t*>(Bs);
    const int WSTR = 20;

    int4 pah[2], pal[2], pb[2];
#pragma unroll
    for (int it = 0; it < 2; it++) {
        int idx = it * 256 + tid;
        int row = idx >> 2, qd = idx & 3;
        long go = (long)(m0 + row) * K + qd * 8;
        pah[it] = *reinterpret_cast<const int4*>(Ahp + go);
        pal[it] = *reinterpret_cast<const int4*>(Alp + go);
        pb[it] = *reinterpret_cast<const int4*>(
            B + (long)(n0 + row) * K + qd * 8);
    }

    for (int k0 = 0; k0 < K; k0 += 32) {
#pragma unroll
        for (int it = 0; it < 2; it++) {
            int idx = it * 256 + tid;
            int row = idx >> 2, qd = idx & 3;
            reinterpret_cast<int4*>(Ah)[row * 5 + qd] = pah[it];
            reinterpret_cast<int4*>(Al)[row * 5 + qd] = pal[it];
            reinterpret_cast<int4*>(Bs)[row * 5 + qd] = pb[it];
        }
        __syncthreads();

        if (k0 + 32 < K) {
#pragma unroll
            for (int it = 0; it < 2; it++) {
                int idx = it * 256 + tid;
                int row = idx >> 2, qd = idx & 3;
                long goA = (long)(m0 + row) * K + k0 + 32 + qd * 8;
                pah[it] = *reinterpret_cast<const int4*>(Ahp + goA);
                pal[it] = *reinterpret_cast<const int4*>(Alp + goA);
                pb[it] = *reinterpret_cast<const int4*>(
                    B + (long)(n0 + row) * K + k0 + 32 + qd * 8);
            }
        }

#pragma unroll
        for (int ks = 0; ks < 2; ks++) {
            uint32_t ah[4][4], al[4][4], bf[4][2];
#pragma unroll
            for (int mt = 0; mt < 4; mt++) {
                int base = (wm + mt * 16 + g) * WSTR + ks * 8 + tig;
                ah[mt][0] = Ahw[base];
                ah[mt][1] = Ahw[base + 8 * WSTR];
                ah[mt][2] = Ahw[base + 4];
                ah[mt][3] = Ahw[base + 8 * WSTR + 4];
                al[mt][0] = Alw[base];
                al[mt][1] = Alw[base + 8 * WSTR];
                al[mt][2] = Alw[base + 4];
                al[mt][3] = Alw[base + 8 * WSTR + 4];
            }
#pragma unroll
            for (int nt = 0; nt < 4; nt++) {
                int base = (wn + nt * 8 + g) * WSTR + ks * 8 + tig;
                bf[nt][0] = Bw[base];
                bf[nt][1] = Bw[base + 4];
            }
#pragma unroll
            for (int mt = 0; mt < 4; mt++)
#pragma unroll
                for (int nt = 0; nt < 4; nt++) {
                    mma_f16(acc[mt][nt], ah[mt], bf[nt]);
                    mma_f16(acc[mt][nt], al[mt], bf[nt]);
                }
        }
        __syncthreads();
    }

    const float scale = __ldg(aB) * (1.0f / 48.0f);
#pragma unroll
    for (int mt = 0; mt < 4; mt++) {
#pragma unroll
        for (int nt = 0; nt < 4; nt++) {
            long row = m0 + wm + mt * 16 + g;
            long col = n0 + wn + nt * 8 + tig * 2;
            float b0 = bias[col], b1 = bias[col + 1];
            float2 v0, v1;
            v0.x = acc[mt][nt][0] * scale + b0;
            v0.y = acc[mt][nt][1] * scale + b1;
            v1.x = acc[mt][nt][2] * scale + b0;
            v1.y = acc[mt][nt][3] * scale + b1;
            *reinterpret_cast<float2*>(C + row * (long)E_ + col) = v0;
            *reinterpret_cast<float2*>(C + (row + 8) * (long)E_ + col) = v1;
        }
    }
}

// ---------------------------------------------------------------------------
// Orchestration.
// ---------------------------------------------------------------------------
extern "C" void kernel_launch(void* const* d_in, const int* in_sizes, int n_in,
                              void* d_out, int out_size) {
    const float* q    = (const float*)d_in[0];
    const float* k    = (const float*)d_in[1];
    const float* v    = (const float*)d_in[2];
    const float* Wi   = (const float*)d_in[3];
    const float* bi   = (const float*)d_in[4];
    const float* Wo   = (const float*)d_in[5];
    const float* bo   = (const float*)d_in[6];
    const float* a_act = (const float*)d_in[7];
    const float* a_wi  = (const float*)d_in[8];
    const float* a_bi  = (const float*)d_in[9];
    const float* a_wo  = (const float*)d_in[10];
    const float* a_bo  = (const float*)d_in[11];
    float* out = (float*)d_out;

    int8_t *p_Wi8, *p_act8;
    __half *p_Woh, *p_ph, *p_pl, *p_vTh, *p_vTl, *p_cxh, *p_cxl;
    float *p_bi, *p_bo;
    cudaGetSymbolAddress((void**)&p_Wi8, g_Wi_i8);
    cudaGetSymbolAddress((void**)&p_act8, g_act_i8);
    cudaGetSymbolAddress((void**)&p_Woh, g_Wo_h);
    cudaGetSymbolAddress((void**)&p_bi, g_bi);
    cudaGetSymbolAddress((void**)&p_bo, g_bo);
    cudaGetSymbolAddress((void**)&p_ph, g_proj_h);
    cudaGetSymbolAddress((void**)&p_pl, g_proj_l);
    cudaGetSymbolAddress((void**)&p_vTh, g_vpT_h);
    cudaGetSymbolAddress((void**)&p_vTl, g_vpT_l);
    cudaGetSymbolAddress((void**)&p_cxh, g_ctx_h);
    cudaGetSymbolAddress((void**)&p_cxl, g_ctx_l);

    const long RE = (long)R_ * E_;

    cudaFuncSetAttribute(flash_attn_kernel,
                         cudaFuncAttributeMaxDynamicSharedMemorySize,
                         SM_TOTAL_FLASH);

    init_tables_kernel<<<1, 1>>>();

    // Weight + bias quantization
    quant_weight_rows_kernel<0><<<3 * E_, 256>>>(Wi, p_Wi8, nullptr, a_wi);
    quant_weight_rows_kernel<1><<<E_, 256>>>(Wo, nullptr, p_Woh, a_wo);
    quant_bias_kernel<<<16, 256>>>(bi, bo, p_bi, p_bo, a_bi, a_bo);

    // Activation quantization -> int8 k-values (one z-batched launch)
    quant_act_i8_kernel<<<dim3(RE / 1024, 3), 256>>>(q, k, v, p_act8, a_act);

    // Projections via int8 tensor cores (exact) -> fp16 hi/lo planes
    gemm_i8_kernel<<<dim3(E_ / 128, R_ / 128, 3), 256>>>(
        p_act8, p_Wi8, p_ph, p_pl, p_bi, a_act, a_wi, E_, E_);

    // Transpose vp planes per head (B-operand layout for PV)
    transpose_v_kernel<<<dim3(S_ / 32, D_ / 32, Z_), dim3(32, 8)>>>(
        p_ph + 2 * RE, p_pl + 2 * RE, p_vTh, p_vTl);

    // Fused attention: scores + online softmax + PV -> ctx planes
    flash_attn_kernel<<<dim3(S_ / 128, Z_), 256, SM_TOTAL_FLASH>>>(
        p_ph, p_pl, p_ph + RE, p_pl + RE, p_vTh, p_vTl, p_cxh, p_cxl);

    // Output projection: ctx planes x Wo_k (exact fp16, 2 passes) -> out
    gemm_ctx_wo_kernel<<<dim3(8, 32), 256>>>(p_cxh, p_cxl, p_Woh, out, p_bo,
                                             a_wo);
}

// round 14
// speedup vs baseline: 5.4827x; 1.0231x over previous
#include <cuda_runtime.h>
#include <cuda_fp16.h>
#include <math.h>
#include <stdint.h>

#define EPSQ 1e-5f

// Problem sizes (fixed by the reference setup_inputs)
#define S_ 1024
#define B_ 4
#define E_ 1024
#define H_ 16
#define D_ 64
#define R_ (S_*B_)   // 4096 flattened (s,b) rows
#define Z_ (B_*H_)   // 64 batched heads

// ---------------------------------------------------------------------------
// Static device scratch (no runtime allocation allowed)
// ---------------------------------------------------------------------------
__device__ float g_LN[31];
__device__ float g_MIDS[30];
__device__ int   g_LN48[31];

__device__ __align__(16) int8_t g_Wi_i8[3*E_*E_];
__device__ __align__(16) __half g_Wo_h[E_*E_];         // Wo k-values (exact fp16)
__device__ __align__(16) float  g_bi[3*E_];
__device__ __align__(16) float  g_bo[E_];
__device__ __align__(16) int8_t g_act_i8[3L*R_*E_];
__device__ __align__(16) __half g_proj_h[3L*R_*E_];    // qp,kp,vp hi plane
__device__ __align__(16) __half g_proj_l[3L*R_*E_];    // qp,kp,vp lo plane
__device__ __align__(16) __half g_vpT_h[(long)Z_*D_*S_];
__device__ __align__(16) __half g_vpT_l[(long)Z_*D_*S_];
__device__ __align__(16) __half g_ctx_h[(long)R_*E_];
__device__ __align__(16) __half g_ctx_l[(long)R_*E_];

// ---------------------------------------------------------------------------
// cp.async helpers
// ---------------------------------------------------------------------------
__device__ __forceinline__ void cp_async16(void* smem_ptr, const void* gptr) {
    uint32_t a = (uint32_t)__cvta_generic_to_shared(smem_ptr);
    asm volatile("cp.async.cg.shared.global [%0], [%1], 16;"
                 :: "r"(a), "l"(gptr));
}
#define CP_COMMIT() asm volatile("cp.async.commit_group;" ::: "memory")
#define CP_WAIT0()  asm volatile("cp.async.wait_group 0;" ::: "memory")

// ---------------------------------------------------------------------------
// APoT tables (exact float emulation of the numpy construction)
// ---------------------------------------------------------------------------
__global__ void init_tables_kernel() {
    const float pos[15] = {0.03125f, 0.0625f, 0.09375f, 0.125f, 0.1875f,
                           0.25f, 0.28125f, 0.375f, 0.5f, 0.5625f,
                           0.75f, 1.0f, 1.03125f, 1.125f, 1.5f};
    const float G = (float)(1.0 / 1.5);
    for (int i = 0; i < 15; i++) {
        g_LN[i]      = (-pos[14 - i]) * G;
        g_LN[16 + i] = pos[i] * G;
    }
    g_LN[15] = 0.0f;
    for (int i = 0; i < 30; i++)
        g_MIDS[i] = (g_LN[i] + g_LN[i + 1]) * 0.5f;
    for (int i = 0; i < 31; i++)
        g_LN48[i] = (int)lrintf(g_LN[i] * 48.0f);
}

// Binary-search count(MD[i] < xc) over 30 sorted mids (== searchsorted left).
__device__ __forceinline__ int rcf_idx(float x, float alpha,
                                       const float* __restrict__ MD) {
    float xn = x / (alpha + EPSQ);
    float xc = fminf(1.0f, fmaxf(-1.0f, xn));
    int c = 0;
    if (MD[15] < xc) c = 16;
    if (c + 8 <= 30 && MD[c + 7] < xc) c += 8;
    if (c + 4 <= 30 && MD[c + 3] < xc) c += 4;
    if (c + 2 <= 30 && MD[c + 1] < xc) c += 2;
    if (c + 1 <= 30 && MD[c] < xc) c += 1;
    return c;
}
__device__ __forceinline__ float rcf_dev(float x, float alpha,
                                         const float* __restrict__ LN,
                                         const float* __restrict__ MD) {
    return LN[rcf_idx(x, alpha, MD)] * alpha;
}

// ---------------------------------------------------------------------------
// Bias quantization: bi (3072) and bo (1024) in ONE launch (16 blocks).
// ---------------------------------------------------------------------------
__global__ void quant_bias_kernel(const float* __restrict__ bi,
                                  const float* __restrict__ bo,
                                  float* __restrict__ ybi,
                                  float* __restrict__ ybo,
                                  const float* __restrict__ abi,
                                  const float* __restrict__ abo) {
    __shared__ float LN[31], MD[30];
    if (threadIdx.x < 31) LN[threadIdx.x] = g_LN[threadIdx.x];
    if (threadIdx.x < 30) MD[threadIdx.x] = g_MIDS[threadIdx.x];
    __syncthreads();
    int b = blockIdx.x;
    if (b < 12) {
        int i = b * 256 + threadIdx.x;
        ybi[i] = rcf_dev(bi[i], abi[0], LN, MD);
    } else {
        int i = (b - 12) * 256 + threadIdx.x;
        ybo[i] = rcf_dev(bo[i], abo[0], LN, MD);
    }
}

// ---------------------------------------------------------------------------
// Activation quantization -> int8 k-values; q/k/v in one z-batched launch.
// ---------------------------------------------------------------------------
__global__ void quant_act_i8_kernel(const float* __restrict__ q,
                                    const float* __restrict__ k,
                                    const float* __restrict__ v,
                                    int8_t* __restrict__ y,
                                    const float* __restrict__ alpha_p) {
    __shared__ float MD[30];
    __shared__ int   L48[31];
    if (threadIdx.x < 30) MD[threadIdx.x] = g_MIDS[threadIdx.x];
    if (threadIdx.x < 31) L48[threadIdx.x] = g_LN48[threadIdx.x];
    __syncthreads();
    const float* x = (blockIdx.y == 0) ? q : (blockIdx.y == 1) ? k : v;
    int8_t* yy = y + (long)blockIdx.y * R_ * E_;
    float a = alpha_p[0];
    long i0 = ((long)blockIdx.x * blockDim.x + threadIdx.x) * 4;
    float4 vv = *reinterpret_cast<const float4*>(x + i0);
    char4 o;
    o.x = (int8_t)L48[rcf_idx(vv.x, a, MD)];
    o.y = (int8_t)L48[rcf_idx(vv.y, a, MD)];
    o.z = (int8_t)L48[rcf_idx(vv.z, a, MD)];
    o.w = (int8_t)L48[rcf_idx(vv.w, a, MD)];
    *reinterpret_cast<char4*>(yy + i0) = o;
}

// ---------------------------------------------------------------------------
// Weight quantization: one block per row, single global read, float warp
// reductions (2 syncs). OUT==0 -> int8 k-values; OUT==1 -> fp16 k-values.
// ---------------------------------------------------------------------------
template <int OUT>
__global__ void quant_weight_rows_kernel(const float* __restrict__ W,
                                         int8_t* __restrict__ Wq8,
                                         __half* __restrict__ Wqh,
                                         const float* __restrict__ alpha_p) {
    __shared__ float MD[30];
    __shared__ int   L48[31];
    __shared__ float red[8];
    const int row = blockIdx.x, tid = threadIdx.x;
    const int lane = tid & 31, warp = tid >> 5;
    if (tid < 30) MD[tid] = g_MIDS[tid];
    if (tid < 31) L48[tid] = g_LN48[tid];
    const float* w = W + (long)row * E_;

    float4 w4 = *reinterpret_cast<const float4*>(w + tid * 4);

    float s = w4.x + w4.y + w4.z + w4.w;
#pragma unroll
    for (int o = 16; o > 0; o >>= 1) s += __shfl_xor_sync(0xffffffffu, s, o);
    if (lane == 0) red[warp] = s;
    __syncthreads();
    float tot = red[0];
#pragma unroll
    for (int i = 1; i < 8; i++) tot += red[i];
    float mu = tot * (1.0f / E_);

    float dx = w4.x - mu, dy = w4.y - mu, dz = w4.z - mu, dw = w4.w - mu;
    float s2 = dx * dx + dy * dy + dz * dz + dw * dw;
#pragma unroll
    for (int o = 16; o > 0; o >>= 1) s2 += __shfl_xor_sync(0xffffffffu, s2, o);
    __syncthreads();
    if (lane == 0) red[warp] = s2;
    __syncthreads();
    float tot2 = red[0];
#pragma unroll
    for (int i = 1; i < 8; i++) tot2 += red[i];
    float var = tot2 * (1.0f / E_);

    float inv = 1.0f / sqrtf(var + EPSQ);
    float a = alpha_p[0];
    int k0 = L48[rcf_idx(dx * inv, a, MD)];
    int k1 = L48[rcf_idx(dy * inv, a, MD)];
    int k2 = L48[rcf_idx(dz * inv, a, MD)];
    int k3 = L48[rcf_idx(dw * inv, a, MD)];
    if (OUT == 0) {
        char4 o;
        o.x = (int8_t)k0; o.y = (int8_t)k1; o.z = (int8_t)k2; o.w = (int8_t)k3;
        *reinterpret_cast<char4*>(Wq8 + (long)row * E_ + tid * 4) = o;
    } else {
        __half2 h01 = __floats2half2_rn((float)k0, (float)k1);
        __half2 h23 = __floats2half2_rn((float)k2, (float)k3);
        uint2 pk;
        pk.x = *reinterpret_cast<uint32_t*>(&h01);
        pk.y = *reinterpret_cast<uint32_t*>(&h23);
        *reinterpret_cast<uint2*>(Wqh + (long)row * E_ + tid * 4) = pk;
    }
}

// ---------------------------------------------------------------------------
// fp16 split helper
// ---------------------------------------------------------------------------
__device__ __forceinline__ void split2(float a, float b, uint32_t& hi,
                                       uint32_t& lo) {
    __half2 h = __floats2half2_rn(a, b);
    __half2 l = __floats2half2_rn(a - __low2float(h), b - __high2float(h));
    hi = *reinterpret_cast<uint32_t*>(&h);
    lo = *reinterpret_cast<uint32_t*>(&l);
}

// ---------------------------------------------------------------------------
// int8 tensor-core projection GEMM with cp.async smem ping-pong.
// Epilogue writes fp16 hi/lo planes; q-section (z==0) folds the 0.125 scale.
// ---------------------------------------------------------------------------
__device__ __forceinline__ void mma_i8(int* d, const uint32_t* a,
                                       const uint32_t* b) {
    asm volatile(
        "mma.sync.aligned.m16n8k32.row.col.s32.s8.s8.s32 "
        "{%0,%1,%2,%3}, {%4,%5,%6,%7}, {%8,%9}, {%0,%1,%2,%3};\n"
        : "+r"(d[0]), "+r"(d[1]), "+r"(d[2]), "+r"(d[3])
        : "r"(a[0]), "r"(a[1]), "r"(a[2]), "r"(a[3]), "r"(b[0]), "r"(b[1]));
}

#define I8_STRIDE 80

__global__ __launch_bounds__(256) void gemm_i8_kernel(
    const int8_t* __restrict__ A, const int8_t* __restrict__ B,
    __half* __restrict__ Ch, __half* __restrict__ Cl,
    const float* __restrict__ bias,
    const float* __restrict__ aA, const float* __restrict__ aB,
    int K, int N) {
    __shared__ __align__(16) int8_t As[2][128 * I8_STRIDE];
    __shared__ __align__(16) int8_t Bs[2][128 * I8_STRIDE];

    const int tid  = threadIdx.x;
    const int warp = tid >> 5;
    const int lane = tid & 31;
    const int g    = lane >> 2;
    const int tig  = lane & 3;

    const long z = blockIdx.z;
    A += z * (long)R_ * K;
    B += z * (long)N * K;
    Ch += z * (long)R_ * N;
    Cl += z * (long)R_ * N;
    bias += z * N;

    const int m0 = blockIdx.y * 128;
    const int n0 = blockIdx.x * 128;
    const int wm = (warp >> 2) * 64;
    const int wn = (warp & 3) * 32;

    int acc[4][4][4];
#pragma unroll
    for (int a_ = 0; a_ < 4; a_++)
#pragma unroll
        for (int b_ = 0; b_ < 4; b_++)
#pragma unroll
            for (int c_ = 0; c_ < 4; c_++) acc[a_][b_][c_] = 0;

    const int WSTR = I8_STRIDE / 4;

    // prologue: chunk 0 -> stage 0
#pragma unroll
    for (int it = 0; it < 2; it++) {
        int idx = it * 256 + tid;
        int row = idx >> 2, c = idx & 3;
        cp_async16(&As[0][row * I8_STRIDE + c * 16],
                   A + (long)(m0 + row) * K + c * 16);
        cp_async16(&Bs[0][row * I8_STRIDE + c * 16],
                   B + (long)(n0 + row) * K + c * 16);
    }
    CP_COMMIT();

    int stage = 0;
    for (int k0 = 0; k0 < K; k0 += 64) {
        CP_WAIT0();
        __syncthreads();
        if (k0 + 64 < K) {
#pragma unroll
            for (int it = 0; it < 2; it++) {
                int idx = it * 256 + tid;
                int row = idx >> 2, c = idx & 3;
                cp_async16(&As[stage ^ 1][row * I8_STRIDE + c * 16],
                           A + (long)(m0 + row) * K + k0 + 64 + c * 16);
                cp_async16(&Bs[stage ^ 1][row * I8_STRIDE + c * 16],
                           B + (long)(n0 + row) * K + k0 + 64 + c * 16);
            }
            CP_COMMIT();
        }

        const uint32_t* Aw = reinterpret_cast<const uint32_t*>(As[stage]);
        const uint32_t* Bw = reinterpret_cast<const uint32_t*>(Bs[stage]);
#pragma unroll
        for (int ks = 0; ks < 2; ks++) {
            uint32_t af[4][4], bf[4][2];
#pragma unroll
            for (int mt = 0; mt < 4; mt++) {
                int base = (wm + mt * 16 + g) * WSTR + ks * 8 + tig;
                af[mt][0] = Aw[base];
                af[mt][1] = Aw[base + 8 * WSTR];
                af[mt][2] = Aw[base + 4];
                af[mt][3] = Aw[base + 8 * WSTR + 4];
            }
#pragma unroll
            for (int nt = 0; nt < 4; nt++) {
                int base = (wn + nt * 8 + g) * WSTR + ks * 8 + tig;
                bf[nt][0] = Bw[base];
                bf[nt][1] = Bw[base + 4];
            }
#pragma unroll
            for (int mt = 0; mt < 4; mt++)
#pragma unroll
                for (int nt = 0; nt < 4; nt++)
                    mma_i8(acc[mt][nt], af[mt], bf[nt]);
        }
        stage ^= 1;
    }

    // fold exact 1/8 score scale into the q section (z==0)
    const float f = (z == 0) ? 0.125f : 1.0f;
    const float scale = __ldg(aA) * __ldg(aB) * (1.0f / 2304.0f) * f;
#pragma unroll
    for (int mt = 0; mt < 4; mt++) {
#pragma unroll
        for (int nt = 0; nt < 4; nt++) {
            long row = m0 + wm + mt * 16 + g;
            long col = n0 + wn + nt * 8 + tig * 2;
            float b0 = bias[col] * f, b1 = bias[col + 1] * f;
            float v00 = (float)acc[mt][nt][0] * scale + b0;
            float v01 = (float)acc[mt][nt][1] * scale + b1;
            float v10 = (float)acc[mt][nt][2] * scale + b0;
            float v11 = (float)acc[mt][nt][3] * scale + b1;
            uint32_t h, l;
            split2(v00, v01, h, l);
            *reinterpret_cast<uint32_t*>(Ch + row * N + col) = h;
            *reinterpret_cast<uint32_t*>(Cl + row * N + col) = l;
            split2(v10, v11, h, l);
            *reinterpret_cast<uint32_t*>(Ch + (row + 8) * N + col) = h;
            *reinterpret_cast<uint32_t*>(Cl + (row + 8) * N + col) = l;
        }
    }
}

// ---------------------------------------------------------------------------
// Per-head transpose of vp planes: vpT[z][d][t] = vp[t*4096 + 64*z + d]
// ---------------------------------------------------------------------------
__global__ void transpose_v_kernel(const __half* __restrict__ vph,
                                   const __half* __restrict__ vpl,
                                   __half* __restrict__ vpTh,
                                   __half* __restrict__ vpTl) {
    __shared__ ushort tile[32][33];
    const int z = blockIdx.z;
    const int t0 = blockIdx.x * 32;
    const int d0 = blockIdx.y * 32;
#pragma unroll
    for (int p = 0; p < 2; p++) {
        const ushort* src = reinterpret_cast<const ushort*>(p ? vpl : vph) + 64L * z;
        ushort* dst = reinterpret_cast<ushort*>(p ? vpTl : vpTh) + (long)z * D_ * S_;
        for (int r = threadIdx.y; r < 32; r += 8)
            tile[r][threadIdx.x] = src[(long)(t0 + r) * 4096 + d0 + threadIdx.x];
        __syncthreads();
        for (int r = threadIdx.y; r < 32; r += 8)
            dst[(long)(d0 + r) * S_ + t0 + threadIdx.x] = tile[threadIdx.x][r];
        __syncthreads();
    }
}

// ---------------------------------------------------------------------------
// fp16 mma helper
// ---------------------------------------------------------------------------
__device__ __forceinline__ void mma_f16(float* d, const uint32_t* a,
                                        const uint32_t* b) {
    asm volatile(
        "mma.sync.aligned.m16n8k16.row.col.f32.f16.f16.f32 "
        "{%0,%1,%2,%3}, {%4,%5,%6,%7}, {%8,%9}, {%0,%1,%2,%3};\n"
        : "+f"(d[0]), "+f"(d[1]), "+f"(d[2]), "+f"(d[3])
        : "r"(a[0]), "r"(a[1]), "r"(a[2]), "r"(a[3]), "r"(b[0]), "r"(b[1]));
}

// ---------------------------------------------------------------------------
// Fused flash attention with cp.async 2-stage K/V pipeline.
// Stage layout (bytes): KH @0, KL @STG_K, VH @2*STG_K, VL @2*STG_K+STG_V.
// ---------------------------------------------------------------------------
#define KWORDS 36
#define VWORDS 68
#define STG_K  18432
#define STG_V  17408
#define STG_SZ (2*STG_K + 2*STG_V)      // 71680
#define SM_TOTAL_FLASH (2 * STG_SZ)     // 143360

__global__ __launch_bounds__(256) void flash_attn_kernel(
    const __half* __restrict__ Qh, const __half* __restrict__ Ql,
    const __half* __restrict__ Kh_, const __half* __restrict__ Kl_,
    const __half* __restrict__ Vh, const __half* __restrict__ Vl,
    __half* __restrict__ Oh, __half* __restrict__ Ol) {
    extern __shared__ char sm[];

    const int tid = threadIdx.x;
    const int warp = tid >> 5, lane = tid & 31;
    const int g = lane >> 2, tig = lane & 3;
    const int z = blockIdx.y;
    const int q0 = blockIdx.x * 128;

    const __half* Qbh = Qh + (long)z * 64;     // s-stride 4096 halves
    const __half* Qbl = Ql + (long)z * 64;
    const __half* Kbh = Kh_ + (long)z * 64;
    const __half* Kbl = Kl_ + (long)z * 64;
    const __half* Vbh = Vh + (long)z * D_ * S_;
    const __half* Vbl = Vl + (long)z * D_ * S_;

    // ---- prologue: Q -> stage1 K-region; tile0 K,V -> stage0 (all cp.async)
#pragma unroll
    for (int it = 0; it < 4; it++) {
        int idx = it * 256 + tid;
        int row = idx >> 3, qd = idx & 7;           // K/Q: 128 rows x 8 uint4
        long gq = (long)(q0 + row) * 4096 + qd * 8;
        cp_async16(sm + STG_SZ + (row * 9 + qd) * 16, Qbh + gq);
        cp_async16(sm + STG_SZ + STG_K + (row * 9 + qd) * 16, Qbl + gq);
        long gk = (long)row * 4096 + qd * 8;        // t0 = 0
        cp_async16(sm + (row * 9 + qd) * 16, Kbh + gk);
        cp_async16(sm + STG_K + (row * 9 + qd) * 16, Kbl + gk);
        int vr = idx >> 4, vc = idx & 15;           // V: 64 rows x 16 uint4
        long gv = (long)vr * 1024 + vc * 8;         // t0 = 0
        cp_async16(sm + 2 * STG_K + (vr * 17 + vc) * 16, Vbh + gv);
        cp_async16(sm + 2 * STG_K + STG_V + (vr * 17 + vc) * 16, Vbl + gv);
    }
    CP_COMMIT();
    CP_WAIT0();
    __syncthreads();

    // ---- extract Q fragments from stage1 K-region
    uint32_t qh[4][4], ql[4][4];
    {
        const uint32_t* QH = reinterpret_cast<const uint32_t*>(sm + STG_SZ);
        const uint32_t* QL = reinterpret_cast<const uint32_t*>(sm + STG_SZ + STG_K);
#pragma unroll
        for (int ks = 0; ks < 4; ks++) {
            int base = (warp * 16 + g) * KWORDS + ks * 8 + tig;
            qh[ks][0] = QH[base];
            qh[ks][1] = QH[base + 8 * KWORDS];
            qh[ks][2] = QH[base + 4];
            qh[ks][3] = QH[base + 8 * KWORDS + 4];
            ql[ks][0] = QL[base];
            ql[ks][1] = QL[base + 8 * KWORDS];
            ql[ks][2] = QL[base + 4];
            ql[ks][3] = QL[base + 8 * KWORDS + 4];
        }
    }
    __syncthreads();   // stage1 free for tile1 copies

    float ctx[8][4];
#pragma unroll
    for (int d8 = 0; d8 < 8; d8++)
#pragma unroll
        for (int c = 0; c < 4; c++) ctx[d8][c] = 0.0f;
    float M0 = -1e30f, M1 = -1e30f, T0 = 0.0f, T1 = 0.0f;

    int stage = 0;
    for (int t0 = 0; t0 < S_; t0 += 128) {
        // ---- issue next tile into the other stage (overlaps compute)
        if (t0 + 128 < S_) {
            char* d = sm + (stage ^ 1) * STG_SZ;
#pragma unroll
            for (int it = 0; it < 4; it++) {
                int idx = it * 256 + tid;
                int row = idx >> 3, qd = idx & 7;
                long gk = (long)(t0 + 128 + row) * 4096 + qd * 8;
                cp_async16(d + (row * 9 + qd) * 16, Kbh + gk);
                cp_async16(d + STG_K + (row * 9 + qd) * 16, Kbl + gk);
                int vr = idx >> 4, vc = idx & 15;
                long gv = (long)vr * 1024 + t0 + 128 + vc * 8;
                cp_async16(d + 2 * STG_K + (vr * 17 + vc) * 16, Vbh + gv);
                cp_async16(d + 2 * STG_K + STG_V + (vr * 17 + vc) * 16, Vbl + gv);
            }
            CP_COMMIT();
        }

        const uint32_t* KH = reinterpret_cast<const uint32_t*>(sm + stage * STG_SZ);
        const uint32_t* KL = reinterpret_cast<const uint32_t*>(sm + stage * STG_SZ + STG_K);
        const uint32_t* PH = reinterpret_cast<const uint32_t*>(sm + stage * STG_SZ + 2 * STG_K);
        const uint32_t* PL = reinterpret_cast<const uint32_t*>(sm + stage * STG_SZ + 2 * STG_K + STG_V);

        // ---- S = Q K^T (f16x3); 0.125 already folded into Q
        float acc[16][4];
#pragma unroll
        for (int nt = 0; nt < 16; nt++)
#pragma unroll
            for (int c = 0; c < 4; c++) acc[nt][c] = 0.0f;
#pragma unroll
        for (int nt = 0; nt < 16; nt++) {
#pragma unroll
            for (int ks = 0; ks < 4; ks++) {
                int base = (nt * 8 + g) * KWORDS + ks * 8 + tig;
                uint32_t bh[2] = {KH[base], KH[base + 4]};
                uint32_t bl[2] = {KL[base], KL[base + 4]};
                mma_f16(acc[nt], qh[ks], bh);
                mma_f16(acc[nt], qh[ks], bl);
                mma_f16(acc[nt], ql[ks], bh);
            }
        }

        // ---- online softmax stats (rows g and g+8, quad shuffles)
        float m0 = -1e30f, m1 = -1e30f;
#pragma unroll
        for (int nt = 0; nt < 16; nt++) {
            m0 = fmaxf(m0, fmaxf(acc[nt][0], acc[nt][1]));
            m1 = fmaxf(m1, fmaxf(acc[nt][2], acc[nt][3]));
        }
        m0 = fmaxf(m0, __shfl_xor_sync(0xffffffffu, m0, 1));
        m0 = fmaxf(m0, __shfl_xor_sync(0xffffffffu, m0, 2));
        m1 = fmaxf(m1, __shfl_xor_sync(0xffffffffu, m1, 1));
        m1 = fmaxf(m1, __shfl_xor_sync(0xffffffffu, m1, 2));
        float Mn0 = fmaxf(M0, m0), Mn1 = fmaxf(M1, m1);
        float a0 = __expf(M0 - Mn0), a1 = __expf(M1 - Mn1);
        M0 = Mn0; M1 = Mn1;

        float s0 = 0.0f, s1 = 0.0f;
#pragma unroll
        for (int nt = 0; nt < 16; nt++) {
            acc[nt][0] = __expf(acc[nt][0] - M0);
            acc[nt][1] = __expf(acc[nt][1] - M0);
            acc[nt][2] = __expf(acc[nt][2] - M1);
            acc[nt][3] = __expf(acc[nt][3] - M1);
            s0 += acc[nt][0] + acc[nt][1];
            s1 += acc[nt][2] + acc[nt][3];
        }
        s0 += __shfl_xor_sync(0xffffffffu, s0, 1);
        s0 += __shfl_xor_sync(0xffffffffu, s0, 2);
        s1 += __shfl_xor_sync(0xffffffffu, s1, 1);
        s1 += __shfl_xor_sync(0xffffffffu, s1, 2);
        T0 = T0 * a0 + s0;
        T1 = T1 * a1 + s1;
#pragma unroll
        for (int d8 = 0; d8 < 8; d8++) {
            ctx[d8][0] *= a0; ctx[d8][1] *= a0;
            ctx[d8][2] *= a1; ctx[d8][3] *= a1;
        }

        // ---- PV: P (register score fragments, split on the fly) x VT
#pragma unroll
        for (int c = 0; c < 8; c++) {
            uint32_t ah[4], al[4];
            split2(acc[2 * c][0],     acc[2 * c][1],     ah[0], al[0]);
            split2(acc[2 * c][2],     acc[2 * c][3],     ah[1], al[1]);
            split2(acc[2 * c + 1][0], acc[2 * c + 1][1], ah[2], al[2]);
            split2(acc[2 * c + 1][2], acc[2 * c + 1][3], ah[3], al[3]);
#pragma unroll
            for (int d8 = 0; d8 < 8; d8++) {
                int base = (d8 * 8 + g) * VWORDS + c * 8 + tig;
                uint32_t bh[2] = {PH[base], PH[base + 4]};
                uint32_t bl[2] = {PL[base], PL[base + 4]};
                mma_f16(ctx[d8], ah, bh);
                mma_f16(ctx[d8], ah, bl);
                mma_f16(ctx[d8], al, bh);
            }
        }

        CP_WAIT0();
        __syncthreads();
        stage ^= 1;
    }

    // ---- normalize and write ctx hi/lo planes
    float i0 = 1.0f / T0, i1 = 1.0f / T1;
    const long r0 = q0 + warp * 16 + g;
#pragma unroll
    for (int d8 = 0; d8 < 8; d8++) {
        long col = (long)z * 64 + d8 * 8 + tig * 2;
        uint32_t h, l;
        split2(ctx[d8][0] * i0, ctx[d8][1] * i0, h, l);
        *reinterpret_cast<uint32_t*>(Oh + r0 * 4096 + col) = h;
        *reinterpret_cast<uint32_t*>(Ol + r0 * 4096 + col) = l;
        split2(ctx[d8][2] * i1, ctx[d8][3] * i1, h, l);
        *reinterpret_cast<uint32_t*>(Oh + (r0 + 8) * 4096 + col) = h;
        *reinterpret_cast<uint32_t*>(Ol + (r0 + 8) * 4096 + col) = l;
    }
}

// ---------------------------------------------------------------------------
// Output projection: ctx hi/lo planes x Wo_k (exact fp16) — 2 passes, with
// cp.async 2-stage ping-pong (dynamic smem: 2 stages x 3 buffers x 10240 B).
//   out[m,n] = (sum_k ctx[m,k]*Wo_k[n,k]) * (a_wo/48) + bo[n]
// ---------------------------------------------------------------------------
#define WO_BUF   10240                  // 128 rows x 40 halves
#define WO_STAGE (3 * WO_BUF)           // Ah, Al, Bs
#define SM_TOTAL_WO (2 * WO_STAGE)      // 61440

__global__ __launch_bounds__(256) void gemm_ctx_wo_kernel(
    const __half* __restrict__ Ahp, const __half* __restrict__ Alp,
    const __half* __restrict__ B,
    float* __restrict__ C, const float* __restrict__ bias,
    const float* __restrict__ aB) {
    const int K = E_;
    extern __shared__ char smw[];

    const int tid  = threadIdx.x;
    const int warp = tid >> 5;
    const int lane = tid & 31;
    const int g    = lane >> 2;
    const int tig  = lane & 3;

    const int m0 = blockIdx.y * 128;
    const int n0 = blockIdx.x * 128;
    const int wm = (warp >> 2) * 64;
    const int wn = (warp & 3) * 32;

    float acc[4][4][4];
#pragma unroll
    for (int mt = 0; mt < 4; mt++)
#pragma unroll
        for (int nt = 0; nt < 4; nt++)
#pragma unroll
            for (int c = 0; c < 4; c++) acc[mt][nt][c] = 0.0f;

    const int WSTR = 20;

    // prologue: chunk 0 -> stage 0 (each buffer: 128 rows x 5 uint4, 80B rows)
#pragma unroll
    for (int it = 0; it < 2; it++) {
        int idx = it * 256 + tid;
        int row = idx >> 2, qd = idx & 3;
        long goA = (long)(m0 + row) * K + qd * 8;
        cp_async16(smw + (row * 5 + qd) * 16, Ahp + goA);
        cp_async16(smw + WO_BUF + (row * 5 + qd) * 16, Alp + goA);
        cp_async16(smw + 2 * WO_BUF + (row * 5 + qd) * 16,
                   B + (long)(n0 + row) * K + qd * 8);
    }
    CP_COMMIT();

    int stage = 0;
    for (int k0 = 0; k0 < K; k0 += 32) {
        CP_WAIT0();
        __syncthreads();
        if (k0 + 32 < K) {
            char* d = smw + (stage ^ 1) * WO_STAGE;
#pragma unroll
            for (int it = 0; it < 2; it++) {
                int idx = it * 256 + tid;
                int row = idx >> 2, qd = idx & 3;
                long goA = (long)(m0 + row) * K + k0 + 32 + qd * 8;
                cp_async16(d + (row * 5 + qd) * 16, Ahp + goA);
                cp_async16(d + WO_BUF + (row * 5 + qd) * 16, Alp + goA);
                cp_async16(d + 2 * WO_BUF + (row * 5 + qd) * 16,
                           B + (long)(n0 + row) * K + k0 + 32 + qd * 8);
            }
            CP_COMMIT();
        }

        const uint32_t* Ahw = reinterpret_cast<const uint32_t*>(smw + stage * WO_STAGE);
        const uint32_t* Alw = reinterpret_cast<const uint32_t*>(smw + stage * WO_STAGE + WO_BUF);
        const uint32_t* Bw  = reinterpret_cast<const uint32_t*>(smw + stage * WO_STAGE + 2 * WO_BUF);
#pragma unroll
        for (int ks = 0; ks < 2; ks++) {
            uint32_t ah[4][4], al[4][4], bf[4][2];
#pragma unroll
            for (int mt = 0; mt < 4; mt++) {
                int base = (wm + mt * 16 + g) * WSTR + ks * 8 + tig;
                ah[mt][0] = Ahw[base];
                ah[mt][1] = Ahw[base + 8 * WSTR];
                ah[mt][2] = Ahw[base + 4];
                ah[mt][3] = Ahw[base + 8 * WSTR + 4];
                al[mt][0] = Alw[base];
                al[mt][1] = Alw[base + 8 * WSTR];
                al[mt][2] = Alw[base + 4];
                al[mt][3] = Alw[base + 8 * WSTR + 4];
            }
#pragma unroll
            for (int nt = 0; nt < 4; nt++) {
                int base = (wn + nt * 8 + g) * WSTR + ks * 8 + tig;
                bf[nt][0] = Bw[base];
                bf[nt][1] = Bw[base + 4];
            }
#pragma unroll
            for (int mt = 0; mt < 4; mt++)
#pragma unroll
                for (int nt = 0; nt < 4; nt++) {
                    mma_f16(acc[mt][nt], ah[mt], bf[nt]);
                    mma_f16(acc[mt][nt], al[mt], bf[nt]);
                }
        }
        stage ^= 1;
    }

    const float scale = __ldg(aB) * (1.0f / 48.0f);
#pragma unroll
    for (int mt = 0; mt < 4; mt++) {
#pragma unroll
        for (int nt = 0; nt < 4; nt++) {
            long row = m0 + wm + mt * 16 + g;
            long col = n0 + wn + nt * 8 + tig * 2;
            float b0 = bias[col], b1 = bias[col + 1];
            float2 v0, v1;
            v0.x = acc[mt][nt][0] * scale + b0;
            v0.y = acc[mt][nt][1] * scale + b1;
            v1.x = acc[mt][nt][2] * scale + b0;
            v1.y = acc[mt][nt][3] * scale + b1;
            *reinterpret_cast<float2*>(C + row * (long)E_ + col) = v0;
            *reinterpret_cast<float2*>(C + (row + 8) * (long)E_ + col) = v1;
        }
    }
}

// ---------------------------------------------------------------------------
// Orchestration.
// ---------------------------------------------------------------------------
extern "C" void kernel_launch(void* const* d_in, const int* in_sizes, int n_in,
                              void* d_out, int out_size) {
    const float* q    = (const float*)d_in[0];
    const float* k    = (const float*)d_in[1];
    const float* v    = (const float*)d_in[2];
    const float* Wi   = (const float*)d_in[3];
    const float* bi   = (const float*)d_in[4];
    const float* Wo   = (const float*)d_in[5];
    const float* bo   = (const float*)d_in[6];
    const float* a_act = (const float*)d_in[7];
    const float* a_wi  = (const float*)d_in[8];
    const float* a_bi  = (const float*)d_in[9];
    const float* a_wo  = (const float*)d_in[10];
    const float* a_bo  = (const float*)d_in[11];
    float* out = (float*)d_out;

    int8_t *p_Wi8, *p_act8;
    __half *p_Woh, *p_ph, *p_pl, *p_vTh, *p_vTl, *p_cxh, *p_cxl;
    float *p_bi, *p_bo;
    cudaGetSymbolAddress((void**)&p_Wi8, g_Wi_i8);
    cudaGetSymbolAddress((void**)&p_act8, g_act_i8);
    cudaGetSymbolAddress((void**)&p_Woh, g_Wo_h);
    cudaGetSymbolAddress((void**)&p_bi, g_bi);
    cudaGetSymbolAddress((void**)&p_bo, g_bo);
    cudaGetSymbolAddress((void**)&p_ph, g_proj_h);
    cudaGetSymbolAddress((void**)&p_pl, g_proj_l);
    cudaGetSymbolAddress((void**)&p_vTh, g_vpT_h);
    cudaGetSymbolAddress((void**)&p_vTl, g_vpT_l);
    cudaGetSymbolAddress((void**)&p_cxh, g_ctx_h);
    cudaGetSymbolAddress((void**)&p_cxl, g_ctx_l);

    const long RE = (long)R_ * E_;

    cudaFuncSetAttribute(flash_attn_kernel,
                         cudaFuncAttributeMaxDynamicSharedMemorySize,
                         SM_TOTAL_FLASH);
    cudaFuncSetAttribute(gemm_ctx_wo_kernel,
                         cudaFuncAttributeMaxDynamicSharedMemorySize,
                         SM_TOTAL_WO);

    init_tables_kernel<<<1, 1>>>();

    // Weight + bias quantization
    quant_weight_rows_kernel<0><<<3 * E_, 256>>>(Wi, p_Wi8, nullptr, a_wi);
    quant_weight_rows_kernel<1><<<E_, 256>>>(Wo, nullptr, p_Woh, a_wo);
    quant_bias_kernel<<<16, 256>>>(bi, bo, p_bi, p_bo, a_bi, a_bo);

    // Activation quantization -> int8 k-values (one z-batched launch)
    quant_act_i8_kernel<<<dim3(RE / 1024, 3), 256>>>(q, k, v, p_act8, a_act);

    // Projections via int8 tensor cores (exact) -> fp16 hi/lo planes
    gemm_i8_kernel<<<dim3(E_ / 128, R_ / 128, 3), 256>>>(
        p_act8, p_Wi8, p_ph, p_pl, p_bi, a_act, a_wi, E_, E_);

    // Transpose vp planes per head (B-operand layout for PV)
    transpose_v_kernel<<<dim3(S_ / 32, D_ / 32, Z_), dim3(32, 8)>>>(
        p_ph + 2 * RE, p_pl + 2 * RE, p_vTh, p_vTl);

    // Fused attention: scores + online softmax + PV -> ctx planes
    flash_attn_kernel<<<dim3(S_ / 128, Z_), 256, SM_TOTAL_FLASH>>>(
        p_ph, p_pl, p_ph + RE, p_pl + RE, p_vTh, p_vTl, p_cxh, p_cxl);

    // Output projection: ctx planes x Wo_k (exact fp16, 2 passes) -> out
    gemm_ctx_wo_kernel<<<dim3(8, 32), 256, SM_TOTAL_WO>>>(
        p_cxh, p_cxl, p_Woh, out, p_bo, a_wo);
}

// round 15
// speedup vs baseline: 5.8630x; 1.0694x over previous
#include <cuda_runtime.h>
#include <cuda_fp16.h>
#include <math.h>
#include <stdint.h>

#define EPSQ 1e-5f

// Problem sizes (fixed by the reference setup_inputs)
#define S_ 1024
#define B_ 4
#define E_ 1024
#define H_ 16
#define D_ 64
#define R_ (S_*B_)   // 4096 flattened (s,b) rows
#define Z_ (B_*H_)   // 64 batched heads

// ---------------------------------------------------------------------------
// Static device scratch (no runtime allocation allowed)
// ---------------------------------------------------------------------------
__device__ float g_LN[31];
__device__ float g_MIDS[30];
__device__ int   g_LN48[31];

__device__ __align__(16) int8_t g_Wi_i8[3*E_*E_];
__device__ __align__(16) __half g_Wo_h[E_*E_];         // Wo k-values (exact fp16)
__device__ __align__(16) float  g_bi[3*E_];
__device__ __align__(16) float  g_bo[E_];
__device__ __align__(16) int8_t g_act_i8[3L*R_*E_];
__device__ __align__(16) __half g_proj_h[3L*R_*E_];    // qp,kp,vp hi plane
__device__ __align__(16) __half g_proj_l[3L*R_*E_];    // qp,kp,vp lo plane
__device__ __align__(16) __half g_vpT_h[(long)Z_*D_*S_];
__device__ __align__(16) __half g_vpT_l[(long)Z_*D_*S_];
__device__ __align__(16) __half g_ctx_h[(long)R_*E_];
__device__ __align__(16) __half g_ctx_l[(long)R_*E_];

// ---------------------------------------------------------------------------
// cp.async helpers
// ---------------------------------------------------------------------------
__device__ __forceinline__ void cp_async16(void* smem_ptr, const void* gptr) {
    uint32_t a = (uint32_t)__cvta_generic_to_shared(smem_ptr);
    asm volatile("cp.async.cg.shared.global [%0], [%1], 16;"
                 :: "r"(a), "l"(gptr));
}
#define CP_COMMIT() asm volatile("cp.async.commit_group;" ::: "memory")
#define CP_WAIT0()  asm volatile("cp.async.wait_group 0;" ::: "memory")

// ---------------------------------------------------------------------------
// APoT tables (exact float emulation of the numpy construction)
// ---------------------------------------------------------------------------
__global__ void init_tables_kernel() {
    const float pos[15] = {0.03125f, 0.0625f, 0.09375f, 0.125f, 0.1875f,
                           0.25f, 0.28125f, 0.375f, 0.5f, 0.5625f,
                           0.75f, 1.0f, 1.03125f, 1.125f, 1.5f};
    const float G = (float)(1.0 / 1.5);
    for (int i = 0; i < 15; i++) {
        g_LN[i]      = (-pos[14 - i]) * G;
        g_LN[16 + i] = pos[i] * G;
    }
    g_LN[15] = 0.0f;
    for (int i = 0; i < 30; i++)
        g_MIDS[i] = (g_LN[i] + g_LN[i + 1]) * 0.5f;
    for (int i = 0; i < 31; i++)
        g_LN48[i] = (int)lrintf(g_LN[i] * 48.0f);
}

// Binary-search count(MD[i] < xc) over 30 sorted mids (== searchsorted left).
__device__ __forceinline__ int rcf_idx(float x, float alpha,
                                       const float* __restrict__ MD) {
    float xn = x / (alpha + EPSQ);
    float xc = fminf(1.0f, fmaxf(-1.0f, xn));
    int c = 0;
    if (MD[15] < xc) c = 16;
    if (c + 8 <= 30 && MD[c + 7] < xc) c += 8;
    if (c + 4 <= 30 && MD[c + 3] < xc) c += 4;
    if (c + 2 <= 30 && MD[c + 1] < xc) c += 2;
    if (c + 1 <= 30 && MD[c] < xc) c += 1;
    return c;
}
__device__ __forceinline__ float rcf_dev(float x, float alpha,
                                         const float* __restrict__ LN,
                                         const float* __restrict__ MD) {
    return LN[rcf_idx(x, alpha, MD)] * alpha;
}

// ---------------------------------------------------------------------------
// Fused quantization kernel: one launch handles
//   blocks [0, 3072)       : Wi row quant -> int8 k-values
//   blocks [3072, 4096)    : Wo row quant -> fp16 k-values (exact)
//   blocks [4096, 4112)    : bi / bo elementwise quant (fp32)
//   blocks [4112, 16400)   : q/k/v activation quant -> int8 k-values
// All paths use 256 threads.
// ---------------------------------------------------------------------------
#define QB_WI   3072
#define QB_WO   4096
#define QB_BIAS 4112
#define QB_TOT  16400

__global__ __launch_bounds__(256) void quant_all_kernel(
    const float* __restrict__ Wi, const float* __restrict__ Wo,
    const float* __restrict__ bi, const float* __restrict__ bo,
    const float* __restrict__ q, const float* __restrict__ k,
    const float* __restrict__ v,
    int8_t* __restrict__ Wq8, __half* __restrict__ Wqh,
    float* __restrict__ ybi, float* __restrict__ ybo,
    int8_t* __restrict__ yact,
    const float* __restrict__ a_wi, const float* __restrict__ a_wo,
    const float* __restrict__ a_bi, const float* __restrict__ a_bo,
    const float* __restrict__ a_act) {
    __shared__ float LN[31], MD[30];
    __shared__ int   L48[31];
    __shared__ float red[8];
    const int tid = threadIdx.x;
    const int lane = tid & 31, warp = tid >> 5;
    if (tid < 31) { LN[tid] = g_LN[tid]; L48[tid] = g_LN48[tid]; }
    if (tid < 30) MD[tid] = g_MIDS[tid];
    __syncthreads();

    const int b = blockIdx.x;
    if (b < QB_WO) {
        // ---- weight row quant (Wi -> i8 for b<3072, Wo -> f16 otherwise)
        const bool isWi = (b < QB_WI);
        const int row = isWi ? b : (b - QB_WI);
        const float* w = (isWi ? Wi : Wo) + (long)row * E_;
        float4 w4 = *reinterpret_cast<const float4*>(w + tid * 4);

        float s = w4.x + w4.y + w4.z + w4.w;
#pragma unroll
        for (int o = 16; o > 0; o >>= 1) s += __shfl_xor_sync(0xffffffffu, s, o);
        if (lane == 0) red[warp] = s;
        __syncthreads();
        float tot = red[0];
#pragma unroll
        for (int i = 1; i < 8; i++) tot += red[i];
        float mu = tot * (1.0f / E_);

        float dx = w4.x - mu, dy = w4.y - mu, dz = w4.z - mu, dw = w4.w - mu;
        float s2 = dx * dx + dy * dy + dz * dz + dw * dw;
#pragma unroll
        for (int o = 16; o > 0; o >>= 1) s2 += __shfl_xor_sync(0xffffffffu, s2, o);
        __syncthreads();
        if (lane == 0) red[warp] = s2;
        __syncthreads();
        float tot2 = red[0];
#pragma unroll
        for (int i = 1; i < 8; i++) tot2 += red[i];
        float var = tot2 * (1.0f / E_);

        float inv = 1.0f / sqrtf(var + EPSQ);
        float a = isWi ? a_wi[0] : a_wo[0];
        int k0 = L48[rcf_idx(dx * inv, a, MD)];
        int k1 = L48[rcf_idx(dy * inv, a, MD)];
        int k2 = L48[rcf_idx(dz * inv, a, MD)];
        int k3 = L48[rcf_idx(dw * inv, a, MD)];
        if (isWi) {
            char4 o;
            o.x = (int8_t)k0; o.y = (int8_t)k1;
            o.z = (int8_t)k2; o.w = (int8_t)k3;
            *reinterpret_cast<char4*>(Wq8 + (long)row * E_ + tid * 4) = o;
        } else {
            __half2 h01 = __floats2half2_rn((float)k0, (float)k1);
            __half2 h23 = __floats2half2_rn((float)k2, (float)k3);
            uint2 pk;
            pk.x = *reinterpret_cast<uint32_t*>(&h01);
            pk.y = *reinterpret_cast<uint32_t*>(&h23);
            *reinterpret_cast<uint2*>(Wqh + (long)row * E_ + tid * 4) = pk;
        }
    } else if (b < QB_BIAS) {
        // ---- bias quant
        int bb = b - QB_WO;
        if (bb < 12) {
            int i = bb * 256 + tid;
            ybi[i] = rcf_dev(bi[i], a_bi[0], LN, MD);
        } else {
            int i = (bb - 12) * 256 + tid;
            ybo[i] = rcf_dev(bo[i], a_bo[0], LN, MD);
        }
    } else {
        // ---- activation quant -> int8
        int bb = b - QB_BIAS;
        int sel = bb >> 12;        // / 4096
        int blk = bb & 4095;
        const float* x = (sel == 0) ? q : (sel == 1) ? k : v;
        int8_t* yy = yact + (long)sel * R_ * E_;
        float a = a_act[0];
        long i0 = ((long)blk * 256 + tid) * 4;
        float4 vv = *reinterpret_cast<const float4*>(x + i0);
        char4 o;
        o.x = (int8_t)L48[rcf_idx(vv.x, a, MD)];
        o.y = (int8_t)L48[rcf_idx(vv.y, a, MD)];
        o.z = (int8_t)L48[rcf_idx(vv.z, a, MD)];
        o.w = (int8_t)L48[rcf_idx(vv.w, a, MD)];
        *reinterpret_cast<char4*>(yy + i0) = o;
    }
}

// ---------------------------------------------------------------------------
// fp16 split helper
// ---------------------------------------------------------------------------
__device__ __forceinline__ void split2(float a, float b, uint32_t& hi,
                                       uint32_t& lo) {
    __half2 h = __floats2half2_rn(a, b);
    __half2 l = __floats2half2_rn(a - __low2float(h), b - __high2float(h));
    hi = *reinterpret_cast<uint32_t*>(&h);
    lo = *reinterpret_cast<uint32_t*>(&l);
}

// ---------------------------------------------------------------------------
// int8 tensor-core projection GEMM, BK=128, cp.async ping-pong (dyn smem).
// Epilogue writes fp16 hi/lo planes; q-section (z==0) folds the 0.125 scale.
// ---------------------------------------------------------------------------
__device__ __forceinline__ void mma_i8(int* d, const uint32_t* a,
                                       const uint32_t* b) {
    asm volatile(
        "mma.sync.aligned.m16n8k32.row.col.s32.s8.s8.s32 "
        "{%0,%1,%2,%3}, {%4,%5,%6,%7}, {%8,%9}, {%0,%1,%2,%3};\n"
        : "+r"(d[0]), "+r"(d[1]), "+r"(d[2]), "+r"(d[3])
        : "r"(a[0]), "r"(a[1]), "r"(a[2]), "r"(a[3]), "r"(b[0]), "r"(b[1]));
}

#define I8_STRIDE 144                 // 128 data bytes + 16 pad
#define I8_BUF    (128 * I8_STRIDE)   // 18432
#define I8_STAGE  (2 * I8_BUF)        // A buf + B buf
#define SM_TOTAL_I8 (2 * I8_STAGE)    // 73728

__global__ __launch_bounds__(256) void gemm_i8_kernel(
    const int8_t* __restrict__ A, const int8_t* __restrict__ B,
    __half* __restrict__ Ch, __half* __restrict__ Cl,
    const float* __restrict__ bias,
    const float* __restrict__ aA, const float* __restrict__ aB,
    int K, int N) {
    extern __shared__ char smi[];

    const int tid  = threadIdx.x;
    const int warp = tid >> 5;
    const int lane = tid & 31;
    const int g    = lane >> 2;
    const int tig  = lane & 3;

    const long z = blockIdx.z;
    A += z * (long)R_ * K;
    B += z * (long)N * K;
    Ch += z * (long)R_ * N;
    Cl += z * (long)R_ * N;
    bias += z * N;

    const int m0 = blockIdx.y * 128;
    const int n0 = blockIdx.x * 128;
    const int wm = (warp >> 2) * 64;
    const int wn = (warp & 3) * 32;

    int acc[4][4][4];
#pragma unroll
    for (int a_ = 0; a_ < 4; a_++)
#pragma unroll
        for (int b_ = 0; b_ < 4; b_++)
#pragma unroll
            for (int c_ = 0; c_ < 4; c_++) acc[a_][b_][c_] = 0;

    const int WSTR = I8_STRIDE / 4;   // 36 words

    // prologue: chunk 0 -> stage 0 (128 rows x 8 int4 per operand)
#pragma unroll
    for (int it = 0; it < 4; it++) {
        int idx = it * 256 + tid;
        int row = idx >> 3, c = idx & 7;
        cp_async16(smi + row * I8_STRIDE + c * 16,
                   A + (long)(m0 + row) * K + c * 16);
        cp_async16(smi + I8_BUF + row * I8_STRIDE + c * 16,
                   B + (long)(n0 + row) * K + c * 16);
    }
    CP_COMMIT();

    int stage = 0;
    for (int k0 = 0; k0 < K; k0 += 128) {
        CP_WAIT0();
        __syncthreads();
        if (k0 + 128 < K) {
            char* d = smi + (stage ^ 1) * I8_STAGE;
#pragma unroll
            for (int it = 0; it < 4; it++) {
                int idx = it * 256 + tid;
                int row = idx >> 3, c = idx & 7;
                cp_async16(d + row * I8_STRIDE + c * 16,
                           A + (long)(m0 + row) * K + k0 + 128 + c * 16);
                cp_async16(d + I8_BUF + row * I8_STRIDE + c * 16,
                           B + (long)(n0 + row) * K + k0 + 128 + c * 16);
            }
            CP_COMMIT();
        }

        const uint32_t* Aw = reinterpret_cast<const uint32_t*>(smi + stage * I8_STAGE);
        const uint32_t* Bw = reinterpret_cast<const uint32_t*>(smi + stage * I8_STAGE + I8_BUF);
#pragma unroll
        for (int ks = 0; ks < 4; ks++) {
            uint32_t af[4][4], bf[4][2];
#pragma unroll
            for (int mt = 0; mt < 4; mt++) {
                int base = (wm + mt * 16 + g) * WSTR + ks * 8 + tig;
                af[mt][0] = Aw[base];
                af[mt][1] = Aw[base + 8 * WSTR];
                af[mt][2] = Aw[base + 4];
                af[mt][3] = Aw[base + 8 * WSTR + 4];
            }
#pragma unroll
            for (int nt = 0; nt < 4; nt++) {
                int base = (wn + nt * 8 + g) * WSTR + ks * 8 + tig;
                bf[nt][0] = Bw[base];
                bf[nt][1] = Bw[base + 4];
            }
#pragma unroll
            for (int mt = 0; mt < 4; mt++)
#pragma unroll
                for (int nt = 0; nt < 4; nt++)
                    mma_i8(acc[mt][nt], af[mt], bf[nt]);
        }
        stage ^= 1;
    }

    // fold exact 1/8 score scale into the q section (z==0)
    const float f = (z == 0) ? 0.125f : 1.0f;
    const float scale = __ldg(aA) * __ldg(aB) * (1.0f / 2304.0f) * f;
#pragma unroll
    for (int mt = 0; mt < 4; mt++) {
#pragma unroll
        for (int nt = 0; nt < 4; nt++) {
            long row = m0 + wm + mt * 16 + g;
            long col = n0 + wn + nt * 8 + tig * 2;
            float b0 = bias[col] * f, b1 = bias[col + 1] * f;
            float v00 = (float)acc[mt][nt][0] * scale + b0;
            float v01 = (float)acc[mt][nt][1] * scale + b1;
            float v10 = (float)acc[mt][nt][2] * scale + b0;
            float v11 = (float)acc[mt][nt][3] * scale + b1;
            uint32_t h, l;
            split2(v00, v01, h, l);
            *reinterpret_cast<uint32_t*>(Ch + row * N + col) = h;
            *reinterpret_cast<uint32_t*>(Cl + row * N + col) = l;
            split2(v10, v11, h, l);
            *reinterpret_cast<uint32_t*>(Ch + (row + 8) * N + col) = h;
            *reinterpret_cast<uint32_t*>(Cl + (row + 8) * N + col) = l;
        }
    }
}

// ---------------------------------------------------------------------------
// Per-head transpose of vp planes: vpT[z][d][t] = vp[t*4096 + 64*z + d]
// ---------------------------------------------------------------------------
__global__ void transpose_v_kernel(const __half* __restrict__ vph,
                                   const __half* __restrict__ vpl,
                                   __half* __restrict__ vpTh,
                                   __half* __restrict__ vpTl) {
    __shared__ ushort tile[32][33];
    const int z = blockIdx.z;
    const int t0 = blockIdx.x * 32;
    const int d0 = blockIdx.y * 32;
#pragma unroll
    for (int p = 0; p < 2; p++) {
        const ushort* src = reinterpret_cast<const ushort*>(p ? vpl : vph) + 64L * z;
        ushort* dst = reinterpret_cast<ushort*>(p ? vpTl : vpTh) + (long)z * D_ * S_;
        for (int r = threadIdx.y; r < 32; r += 8)
            tile[r][threadIdx.x] = src[(long)(t0 + r) * 4096 + d0 + threadIdx.x];
        __syncthreads();
        for (int r = threadIdx.y; r < 32; r += 8)
            dst[(long)(d0 + r) * S_ + t0 + threadIdx.x] = tile[threadIdx.x][r];
        __syncthreads();
    }
}

// ---------------------------------------------------------------------------
// fp16 mma helper
// ---------------------------------------------------------------------------
__device__ __forceinline__ void mma_f16(float* d, const uint32_t* a,
                                        const uint32_t* b) {
    asm volatile(
        "mma.sync.aligned.m16n8k16.row.col.f32.f16.f16.f32 "
        "{%0,%1,%2,%3}, {%4,%5,%6,%7}, {%8,%9}, {%0,%1,%2,%3};\n"
        : "+f"(d[0]), "+f"(d[1]), "+f"(d[2]), "+f"(d[3])
        : "r"(a[0]), "r"(a[1]), "r"(a[2]), "r"(a[3]), "r"(b[0]), "r"(b[1]));
}

// ---------------------------------------------------------------------------
// Fused flash attention with cp.async 2-stage K/V pipeline (unchanged r14).
// ---------------------------------------------------------------------------
#define KWORDS 36
#define VWORDS 68
#define STG_K  18432
#define STG_V  17408
#define STG_SZ (2*STG_K + 2*STG_V)      // 71680
#define SM_TOTAL_FLASH (2 * STG_SZ)     // 143360

__global__ __launch_bounds__(256) void flash_attn_kernel(
    const __half* __restrict__ Qh, const __half* __restrict__ Ql,
    const __half* __restrict__ Kh_, const __half* __restrict__ Kl_,
    const __half* __restrict__ Vh, const __half* __restrict__ Vl,
    __half* __restrict__ Oh, __half* __restrict__ Ol) {
    extern __shared__ char sm[];

    const int tid = threadIdx.x;
    const int warp = tid >> 5, lane = tid & 31;
    const int g = lane >> 2, tig = lane & 3;
    const int z = blockIdx.y;
    const int q0 = blockIdx.x * 128;

    const __half* Qbh = Qh + (long)z * 64;     // s-stride 4096 halves
    const __half* Qbl = Ql + (long)z * 64;
    const __half* Kbh = Kh_ + (long)z * 64;
    const __half* Kbl = Kl_ + (long)z * 64;
    const __half* Vbh = Vh + (long)z * D_ * S_;
    const __half* Vbl = Vl + (long)z * D_ * S_;

    // ---- prologue: Q -> stage1 K-region; tile0 K,V -> stage0 (all cp.async)
#pragma unroll
    for (int it = 0; it < 4; it++) {
        int idx = it * 256 + tid;
        int row = idx >> 3, qd = idx & 7;           // K/Q: 128 rows x 8 uint4
        long gq = (long)(q0 + row) * 4096 + qd * 8;
        cp_async16(sm + STG_SZ + (row * 9 + qd) * 16, Qbh + gq);
        cp_async16(sm + STG_SZ + STG_K + (row * 9 + qd) * 16, Qbl + gq);
        long gk = (long)row * 4096 + qd * 8;        // t0 = 0
        cp_async16(sm + (row * 9 + qd) * 16, Kbh + gk);
        cp_async16(sm + STG_K + (row * 9 + qd) * 16, Kbl + gk);
        int vr = idx >> 4, vc = idx & 15;           // V: 64 rows x 16 uint4
        long gv = (long)vr * 1024 + vc * 8;         // t0 = 0
        cp_async16(sm + 2 * STG_K + (vr * 17 + vc) * 16, Vbh + gv);
        cp_async16(sm + 2 * STG_K + STG_V + (vr * 17 + vc) * 16, Vbl + gv);
    }
    CP_COMMIT();
    CP_WAIT0();
    __syncthreads();

    // ---- extract Q fragments from stage1 K-region
    uint32_t qh[4][4], ql[4][4];
    {
        const uint32_t* QH = reinterpret_cast<const uint32_t*>(sm + STG_SZ);
        const uint32_t* QL = reinterpret_cast<const uint32_t*>(sm + STG_SZ + STG_K);
#pragma unroll
        for (int ks = 0; ks < 4; ks++) {
            int base = (warp * 16 + g) * KWORDS + ks * 8 + tig;
            qh[ks][0] = QH[base];
            qh[ks][1] = QH[base + 8 * KWORDS];
            qh[ks][2] = QH[base + 4];
            qh[ks][3] = QH[base + 8 * KWORDS + 4];
            ql[ks][0] = QL[base];
            ql[ks][1] = QL[base + 8 * KWORDS];
            ql[ks][2] = QL[base + 4];
            ql[ks][3] = QL[base + 8 * KWORDS + 4];
        }
    }
    __syncthreads();   // stage1 free for tile1 copies

    float ctx[8][4];
#pragma unroll
    for (int d8 = 0; d8 < 8; d8++)
#pragma unroll
        for (int c = 0; c < 4; c++) ctx[d8][c] = 0.0f;
    float M0 = -1e30f, M1 = -1e30f, T0 = 0.0f, T1 = 0.0f;

    int stage = 0;
    for (int t0 = 0; t0 < S_; t0 += 128) {
        // ---- issue next tile into the other stage (overlaps compute)
        if (t0 + 128 < S_) {
            char* d = sm + (stage ^ 1) * STG_SZ;
#pragma unroll
            for (int it = 0; it < 4; it++) {
                int idx = it * 256 + tid;
                int row = idx >> 3, qd = idx & 7;
                long gk = (long)(t0 + 128 + row) * 4096 + qd * 8;
                cp_async16(d + (row * 9 + qd) * 16, Kbh + gk);
                cp_async16(d + STG_K + (row * 9 + qd) * 16, Kbl + gk);
                int vr = idx >> 4, vc = idx & 15;
                long gv = (long)vr * 1024 + t0 + 128 + vc * 8;
                cp_async16(d + 2 * STG_K + (vr * 17 + vc) * 16, Vbh + gv);
                cp_async16(d + 2 * STG_K + STG_V + (vr * 17 + vc) * 16, Vbl + gv);
            }
            CP_COMMIT();
        }

        const uint32_t* KH = reinterpret_cast<const uint32_t*>(sm + stage * STG_SZ);
        const uint32_t* KL = reinterpret_cast<const uint32_t*>(sm + stage * STG_SZ + STG_K);
        const uint32_t* PH = reinterpret_cast<const uint32_t*>(sm + stage * STG_SZ + 2 * STG_K);
        const uint32_t* PL = reinterpret_cast<const uint32_t*>(sm + stage * STG_SZ + 2 * STG_K + STG_V);

        // ---- S = Q K^T (f16x3); 0.125 already folded into Q
        float acc[16][4];
#pragma unroll
        for (int nt = 0; nt < 16; nt++)
#pragma unroll
            for (int c = 0; c < 4; c++) acc[nt][c] = 0.0f;
#pragma unroll
        for (int nt = 0; nt < 16; nt++) {
#pragma unroll
            for (int ks = 0; ks < 4; ks++) {
                int base = (nt * 8 + g) * KWORDS + ks * 8 + tig;
                uint32_t bh[2] = {KH[base], KH[base + 4]};
                uint32_t bl[2] = {KL[base], KL[base + 4]};
                mma_f16(acc[nt], qh[ks], bh);
                mma_f16(acc[nt], qh[ks], bl);
                mma_f16(acc[nt], ql[ks], bh);
            }
        }

        // ---- online softmax stats (rows g and g+8, quad shuffles)
        float m0 = -1e30f, m1 = -1e30f;
#pragma unroll
        for (int nt = 0; nt < 16; nt++) {
            m0 = fmaxf(m0, fmaxf(acc[nt][0], acc[nt][1]));
            m1 = fmaxf(m1, fmaxf(acc[nt][2], acc[nt][3]));
        }
        m0 = fmaxf(m0, __shfl_xor_sync(0xffffffffu, m0, 1));
        m0 = fmaxf(m0, __shfl_xor_sync(0xffffffffu, m0, 2));
        m1 = fmaxf(m1, __shfl_xor_sync(0xffffffffu, m1, 1));
        m1 = fmaxf(m1, __shfl_xor_sync(0xffffffffu, m1, 2));
        float Mn0 = fmaxf(M0, m0), Mn1 = fmaxf(M1, m1);
        float a0 = __expf(M0 - Mn0), a1 = __expf(M1 - Mn1);
        M0 = Mn0; M1 = Mn1;

        float s0 = 0.0f, s1 = 0.0f;
#pragma unroll
        for (int nt = 0; nt < 16; nt++) {
            acc[nt][0] = __expf(acc[nt][0] - M0);
            acc[nt][1] = __expf(acc[nt][1] - M0);
            acc[nt][2] = __expf(acc[nt][2] - M1);
            acc[nt][3] = __expf(acc[nt][3] - M1);
            s0 += acc[nt][0] + acc[nt][1];
            s1 += acc[nt][2] + acc[nt][3];
        }
        s0 += __shfl_xor_sync(0xffffffffu, s0, 1);
        s0 += __shfl_xor_sync(0xffffffffu, s0, 2);
        s1 += __shfl_xor_sync(0xffffffffu, s1, 1);
        s1 += __shfl_xor_sync(0xffffffffu, s1, 2);
        T0 = T0 * a0 + s0;
        T1 = T1 * a1 + s1;
#pragma unroll
        for (int d8 = 0; d8 < 8; d8++) {
            ctx[d8][0] *= a0; ctx[d8][1] *= a0;
            ctx[d8][2] *= a1; ctx[d8][3] *= a1;
        }

        // ---- PV: P (register score fragments, split on the fly) x VT
#pragma unroll
        for (int c = 0; c < 8; c++) {
            uint32_t ah[4], al[4];
            split2(acc[2 * c][0],     acc[2 * c][1],     ah[0], al[0]);
            split2(acc[2 * c][2],     acc[2 * c][3],     ah[1], al[1]);
            split2(acc[2 * c + 1][0], acc[2 * c + 1][1], ah[2], al[2]);
            split2(acc[2 * c + 1][2], acc[2 * c + 1][3], ah[3], al[3]);
#pragma unroll
            for (int d8 = 0; d8 < 8; d8++) {
                int base = (d8 * 8 + g) * VWORDS + c * 8 + tig;
                uint32_t bh[2] = {PH[base], PH[base + 4]};
                uint32_t bl[2] = {PL[base], PL[base + 4]};
                mma_f16(ctx[d8], ah, bh);
                mma_f16(ctx[d8], ah, bl);
                mma_f16(ctx[d8], al, bh);
            }
        }

        CP_WAIT0();
        __syncthreads();
        stage ^= 1;
    }

    // ---- normalize and write ctx hi/lo planes
    float i0 = 1.0f / T0, i1 = 1.0f / T1;
    const long r0 = q0 + warp * 16 + g;
#pragma unroll
    for (int d8 = 0; d8 < 8; d8++) {
        long col = (long)z * 64 + d8 * 8 + tig * 2;
        uint32_t h, l;
        split2(ctx[d8][0] * i0, ctx[d8][1] * i0, h, l);
        *reinterpret_cast<uint32_t*>(Oh + r0 * 4096 + col) = h;
        *reinterpret_cast<uint32_t*>(Ol + r0 * 4096 + col) = l;
        split2(ctx[d8][2] * i1, ctx[d8][3] * i1, h, l);
        *reinterpret_cast<uint32_t*>(Oh + (r0 + 8) * 4096 + col) = h;
        *reinterpret_cast<uint32_t*>(Ol + (r0 + 8) * 4096 + col) = l;
    }
}

// ---------------------------------------------------------------------------
// Output projection: ctx hi/lo planes x Wo_k (exact fp16) — 2 passes, BK=64,
// cp.async 2-stage ping-pong (dynamic smem: 2 stages x 3 buffers x 18432 B).
// ---------------------------------------------------------------------------
#define WO_STRIDE 144                 // bytes per smem row (64 halves + pad)
#define WO_BUF    (128 * WO_STRIDE)   // 18432
#define WO_STAGE  (3 * WO_BUF)        // Ah, Al, Bs
#define SM_TOTAL_WO (2 * WO_STAGE)    // 110592

__global__ __launch_bounds__(256) void gemm_ctx_wo_kernel(
    const __half* __restrict__ Ahp, const __half* __restrict__ Alp,
    const __half* __restrict__ B,
    float* __restrict__ C, const float* __restrict__ bias,
    const float* __restrict__ aB) {
    const int K = E_;
    extern __shared__ char smw[];

    const int tid  = threadIdx.x;
    const int warp = tid >> 5;
    const int lane = tid & 31;
    const int g    = lane >> 2;
    const int tig  = lane & 3;

    const int m0 = blockIdx.y * 128;
    const int n0 = blockIdx.x * 128;
    const int wm = (warp >> 2) * 64;
    const int wn = (warp & 3) * 32;

    float acc[4][4][4];
#pragma unroll
    for (int mt = 0; mt < 4; mt++)
#pragma unroll
        for (int nt = 0; nt < 4; nt++)
#pragma unroll
            for (int c = 0; c < 4; c++) acc[mt][nt][c] = 0.0f;

    const int WSTR = WO_STRIDE / 4;   // 36 words

    // prologue: chunk 0 -> stage 0 (each buffer: 128 rows x 8 uint4)
#pragma unroll
    for (int it = 0; it < 4; it++) {
        int idx = it * 256 + tid;
        int row = idx >> 3, qd = idx & 7;
        long goA = (long)(m0 + row) * K + qd * 8;
        cp_async16(smw + row * WO_STRIDE + qd * 16, Ahp + goA);
        cp_async16(smw + WO_BUF + row * WO_STRIDE + qd * 16, Alp + goA);
        cp_async16(smw + 2 * WO_BUF + row * WO_STRIDE + qd * 16,
                   B + (long)(n0 + row) * K + qd * 8);
    }
    CP_COMMIT();

    int stage = 0;
    for (int k0 = 0; k0 < K; k0 += 64) {
        CP_WAIT0();
        __syncthreads();
        if (k0 + 64 < K) {
            char* d = smw + (stage ^ 1) * WO_STAGE;
#pragma unroll
            for (int it = 0; it < 4; it++) {
                int idx = it * 256 + tid;
                int row = idx >> 3, qd = idx & 7;
                long goA = (long)(m0 + row) * K + k0 + 64 + qd * 8;
                cp_async16(d + row * WO_STRIDE + qd * 16, Ahp + goA);
                cp_async16(d + WO_BUF + row * WO_STRIDE + qd * 16, Alp + goA);
                cp_async16(d + 2 * WO_BUF + row * WO_STRIDE + qd * 16,
                           B + (long)(n0 + row) * K + k0 + 64 + qd * 8);
            }
            CP_COMMIT();
        }

        const uint32_t* Ahw = reinterpret_cast<const uint32_t*>(smw + stage * WO_STAGE);
        const uint32_t* Alw = reinterpret_cast<const uint32_t*>(smw + stage * WO_STAGE + WO_BUF);
        const uint32_t* Bw  = reinterpret_cast<const uint32_t*>(smw + stage * WO_STAGE + 2 * WO_BUF);
#pragma unroll
        for (int ks = 0; ks < 4; ks++) {
            uint32_t ah[4][4], al[4][4], bf[4][2];
#pragma unroll
            for (int mt = 0; mt < 4; mt++) {
                int base = (wm + mt * 16 + g) * WSTR + ks * 8 + tig;
                ah[mt][0] = Ahw[base];
                ah[mt][1] = Ahw[base + 8 * WSTR];
                ah[mt][2] = Ahw[base + 4];
                ah[mt][3] = Ahw[base + 8 * WSTR + 4];
                al[mt][0] = Alw[base];
                al[mt][1] = Alw[base + 8 * WSTR];
                al[mt][2] = Alw[base + 4];
                al[mt][3] = Alw[base + 8 * WSTR + 4];
            }
#pragma unroll
            for (int nt = 0; nt < 4; nt++) {
                int base = (wn + nt * 8 + g) * WSTR + ks * 8 + tig;
                bf[nt][0] = Bw[base];
                bf[nt][1] = Bw[base + 4];
            }
#pragma unroll
            for (int mt = 0; mt < 4; mt++)
#pragma unroll
                for (int nt = 0; nt < 4; nt++) {
                    mma_f16(acc[mt][nt], ah[mt], bf[nt]);
                    mma_f16(acc[mt][nt], al[mt], bf[nt]);
                }
        }
        stage ^= 1;
    }

    const float scale = __ldg(aB) * (1.0f / 48.0f);
#pragma unroll
    for (int mt = 0; mt < 4; mt++) {
#pragma unroll
        for (int nt = 0; nt < 4; nt++) {
            long row = m0 + wm + mt * 16 + g;
            long col = n0 + wn + nt * 8 + tig * 2;
            float b0 = bias[col], b1 = bias[col + 1];
            float2 v0, v1;
            v0.x = acc[mt][nt][0] * scale + b0;
            v0.y = acc[mt][nt][1] * scale + b1;
            v1.x = acc[mt][nt][2] * scale + b0;
            v1.y = acc[mt][nt][3] * scale + b1;
            *reinterpret_cast<float2*>(C + row * (long)E_ + col) = v0;
            *reinterpret_cast<float2*>(C + (row + 8) * (long)E_ + col) = v1;
        }
    }
}

// ---------------------------------------------------------------------------
// Orchestration.
// ---------------------------------------------------------------------------
extern "C" void kernel_launch(void* const* d_in, const int* in_sizes, int n_in,
                              void* d_out, int out_size) {
    const float* q    = (const float*)d_in[0];
    const float* k    = (const float*)d_in[1];
    const float* v    = (const float*)d_in[2];
    const float* Wi   = (const float*)d_in[3];
    const float* bi   = (const float*)d_in[4];
    const float* Wo   = (const float*)d_in[5];
    const float* bo   = (const float*)d_in[6];
    const float* a_act = (const float*)d_in[7];
    const float* a_wi  = (const float*)d_in[8];
    const float* a_bi  = (const float*)d_in[9];
    const float* a_wo  = (const float*)d_in[10];
    const float* a_bo  = (const float*)d_in[11];
    float* out = (float*)d_out;

    int8_t *p_Wi8, *p_act8;
    __half *p_Woh, *p_ph, *p_pl, *p_vTh, *p_vTl, *p_cxh, *p_cxl;
    float *p_bi, *p_bo;
    cudaGetSymbolAddress((void**)&p_Wi8, g_Wi_i8);
    cudaGetSymbolAddress((void**)&p_act8, g_act_i8);
    cudaGetSymbolAddress((void**)&p_Woh, g_Wo_h);
    cudaGetSymbolAddress((void**)&p_bi, g_bi);
    cudaGetSymbolAddress((void**)&p_bo, g_bo);
    cudaGetSymbolAddress((void**)&p_ph, g_proj_h);
    cudaGetSymbolAddress((void**)&p_pl, g_proj_l);
    cudaGetSymbolAddress((void**)&p_vTh, g_vpT_h);
    cudaGetSymbolAddress((void**)&p_vTl, g_vpT_l);
    cudaGetSymbolAddress((void**)&p_cxh, g_ctx_h);
    cudaGetSymbolAddress((void**)&p_cxl, g_ctx_l);

    const long RE = (long)R_ * E_;

    cudaFuncSetAttribute(flash_attn_kernel,
                         cudaFuncAttributeMaxDynamicSharedMemorySize,
                         SM_TOTAL_FLASH);
    cudaFuncSetAttribute(gemm_ctx_wo_kernel,
                         cudaFuncAttributeMaxDynamicSharedMemorySize,
                         SM_TOTAL_WO);
    cudaFuncSetAttribute(gemm_i8_kernel,
                         cudaFuncAttributeMaxDynamicSharedMemorySize,
                         SM_TOTAL_I8);

    init_tables_kernel<<<1, 1>>>();

    // Fused quantization: weights + biases + activations in ONE launch
    quant_all_kernel<<<QB_TOT, 256>>>(
        Wi, Wo, bi, bo, q, k, v,
        p_Wi8, p_Woh, p_bi, p_bo, p_act8,
        a_wi, a_wo, a_bi, a_bo, a_act);

    // Projections via int8 tensor cores (exact) -> fp16 hi/lo planes
    gemm_i8_kernel<<<dim3(E_ / 128, R_ / 128, 3), 256, SM_TOTAL_I8>>>(
        p_act8, p_Wi8, p_ph, p_pl, p_bi, a_act, a_wi, E_, E_);

    // Transpose vp planes per head (B-operand layout for PV)
    transpose_v_kernel<<<dim3(S_ / 32, D_ / 32, Z_), dim3(32, 8)>>>(
        p_ph + 2 * RE, p_pl + 2 * RE, p_vTh, p_vTl);

    // Fused attention: scores + online softmax + PV -> ctx planes
    flash_attn_kernel<<<dim3(S_ / 128, Z_), 256, SM_TOTAL_FLASH>>>(
        p_ph, p_pl, p_ph + RE, p_pl + RE, p_vTh, p_vTl, p_cxh, p_cxl);

    // Output projection: ctx planes x Wo_k (exact fp16, 2 passes) -> out
    gemm_ctx_wo_kernel<<<dim3(8, 32), 256, SM_TOTAL_WO>>>(
        p_cxh, p_cxl, p_Woh, out, p_bo, a_wo);
}

// round 16
// speedup vs baseline: 5.9670x; 1.0177x over previous
#include <cuda_runtime.h>
#include <cuda_fp16.h>
#include <math.h>
#include <stdint.h>

#define EPSQ 1e-5f

// Problem sizes (fixed by the reference setup_inputs)
#define S_ 1024
#define B_ 4
#define E_ 1024
#define H_ 16
#define D_ 64
#define R_ (S_*B_)   // 4096 flattened (s,b) rows
#define Z_ (B_*H_)   // 64 batched heads

// ---------------------------------------------------------------------------
// Static device scratch (no runtime allocation allowed)
// ---------------------------------------------------------------------------
__device__ float g_LN[31];
__device__ float g_MIDS[30];
__device__ int   g_LN48[31];

__device__ __align__(16) int8_t g_Wi_i8[3*E_*E_];
__device__ __align__(16) __half g_Wo_h[E_*E_];         // Wo k-values (exact fp16)
__device__ __align__(16) float  g_bi[3*E_];
__device__ __align__(16) float  g_bo[E_];
__device__ __align__(16) int8_t g_act_i8[3L*R_*E_];
__device__ __align__(16) __half g_proj_h[3L*R_*E_];    // qp,kp,vp hi plane
__device__ __align__(16) __half g_proj_l[3L*R_*E_];    // qp,kp,vp lo plane
__device__ __align__(16) __half g_vpT_h[(long)Z_*D_*S_];
__device__ __align__(16) __half g_vpT_l[(long)Z_*D_*S_];
__device__ __align__(16) __half g_ctx_h[(long)R_*E_];
__device__ __align__(16) __half g_ctx_l[(long)R_*E_];

// ---------------------------------------------------------------------------
// cp.async helpers
// ---------------------------------------------------------------------------
__device__ __forceinline__ void cp_async16(void* smem_ptr, const void* gptr) {
    uint32_t a = (uint32_t)__cvta_generic_to_shared(smem_ptr);
    asm volatile("cp.async.cg.shared.global [%0], [%1], 16;"
                 :: "r"(a), "l"(gptr));
}
#define CP_COMMIT() asm volatile("cp.async.commit_group;" ::: "memory")
#define CP_WAIT0()  asm volatile("cp.async.wait_group 0;" ::: "memory")

// ---------------------------------------------------------------------------
// APoT tables (exact float emulation of the numpy construction)
// ---------------------------------------------------------------------------
__global__ void init_tables_kernel() {
    const float pos[15] = {0.03125f, 0.0625f, 0.09375f, 0.125f, 0.1875f,
                           0.25f, 0.28125f, 0.375f, 0.5f, 0.5625f,
                           0.75f, 1.0f, 1.03125f, 1.125f, 1.5f};
    const float G = (float)(1.0 / 1.5);
    for (int i = 0; i < 15; i++) {
        g_LN[i]      = (-pos[14 - i]) * G;
        g_LN[16 + i] = pos[i] * G;
    }
    g_LN[15] = 0.0f;
    for (int i = 0; i < 30; i++)
        g_MIDS[i] = (g_LN[i] + g_LN[i + 1]) * 0.5f;
    for (int i = 0; i < 31; i++)
        g_LN48[i] = (int)lrintf(g_LN[i] * 48.0f);
}

// Binary-search count(MD[i] < xc) over 30 sorted mids (== searchsorted left).
__device__ __forceinline__ int rcf_idx(float x, float alpha,
                                       const float* __restrict__ MD) {
    float xn = x / (alpha + EPSQ);
    float xc = fminf(1.0f, fmaxf(-1.0f, xn));
    int c = 0;
    if (MD[15] < xc) c = 16;
    if (c + 8 <= 30 && MD[c + 7] < xc) c += 8;
    if (c + 4 <= 30 && MD[c + 3] < xc) c += 4;
    if (c + 2 <= 30 && MD[c + 1] < xc) c += 2;
    if (c + 1 <= 30 && MD[c] < xc) c += 1;
    return c;
}
__device__ __forceinline__ float rcf_dev(float x, float alpha,
                                         const float* __restrict__ LN,
                                         const float* __restrict__ MD) {
    return LN[rcf_idx(x, alpha, MD)] * alpha;
}

// ---------------------------------------------------------------------------
// Fused quantization kernel: one launch handles
//   blocks [0, 3072)       : Wi row quant -> int8 k-values
//   blocks [3072, 4096)    : Wo row quant -> fp16 k-values (exact)
//   blocks [4096, 4112)    : bi / bo elementwise quant (fp32)
//   blocks [4112, 16400)   : q/k/v activation quant -> int8 k-values
// ---------------------------------------------------------------------------
#define QB_WI   3072
#define QB_WO   4096
#define QB_BIAS 4112
#define QB_TOT  16400

__global__ __launch_bounds__(256) void quant_all_kernel(
    const float* __restrict__ Wi, const float* __restrict__ Wo,
    const float* __restrict__ bi, const float* __restrict__ bo,
    const float* __restrict__ q, const float* __restrict__ k,
    const float* __restrict__ v,
    int8_t* __restrict__ Wq8, __half* __restrict__ Wqh,
    float* __restrict__ ybi, float* __restrict__ ybo,
    int8_t* __restrict__ yact,
    const float* __restrict__ a_wi, const float* __restrict__ a_wo,
    const float* __restrict__ a_bi, const float* __restrict__ a_bo,
    const float* __restrict__ a_act) {
    __shared__ float LN[31], MD[30];
    __shared__ int   L48[31];
    __shared__ float red[8];
    const int tid = threadIdx.x;
    const int lane = tid & 31, warp = tid >> 5;
    if (tid < 31) { LN[tid] = g_LN[tid]; L48[tid] = g_LN48[tid]; }
    if (tid < 30) MD[tid] = g_MIDS[tid];
    __syncthreads();

    const int b = blockIdx.x;
    if (b < QB_WO) {
        const bool isWi = (b < QB_WI);
        const int row = isWi ? b : (b - QB_WI);
        const float* w = (isWi ? Wi : Wo) + (long)row * E_;
        float4 w4 = *reinterpret_cast<const float4*>(w + tid * 4);

        float s = w4.x + w4.y + w4.z + w4.w;
#pragma unroll
        for (int o = 16; o > 0; o >>= 1) s += __shfl_xor_sync(0xffffffffu, s, o);
        if (lane == 0) red[warp] = s;
        __syncthreads();
        float tot = red[0];
#pragma unroll
        for (int i = 1; i < 8; i++) tot += red[i];
        float mu = tot * (1.0f / E_);

        float dx = w4.x - mu, dy = w4.y - mu, dz = w4.z - mu, dw = w4.w - mu;
        float s2 = dx * dx + dy * dy + dz * dz + dw * dw;
#pragma unroll
        for (int o = 16; o > 0; o >>= 1) s2 += __shfl_xor_sync(0xffffffffu, s2, o);
        __syncthreads();
        if (lane == 0) red[warp] = s2;
        __syncthreads();
        float tot2 = red[0];
#pragma unroll
        for (int i = 1; i < 8; i++) tot2 += red[i];
        float var = tot2 * (1.0f / E_);

        float inv = 1.0f / sqrtf(var + EPSQ);
        float a = isWi ? a_wi[0] : a_wo[0];
        int k0 = L48[rcf_idx(dx * inv, a, MD)];
        int k1 = L48[rcf_idx(dy * inv, a, MD)];
        int k2 = L48[rcf_idx(dz * inv, a, MD)];
        int k3 = L48[rcf_idx(dw * inv, a, MD)];
        if (isWi) {
            char4 o;
            o.x = (int8_t)k0; o.y = (int8_t)k1;
            o.z = (int8_t)k2; o.w = (int8_t)k3;
            *reinterpret_cast<char4*>(Wq8 + (long)row * E_ + tid * 4) = o;
        } else {
            __half2 h01 = __floats2half2_rn((float)k0, (float)k1);
            __half2 h23 = __floats2half2_rn((float)k2, (float)k3);
            uint2 pk;
            pk.x = *reinterpret_cast<uint32_t*>(&h01);
            pk.y = *reinterpret_cast<uint32_t*>(&h23);
            *reinterpret_cast<uint2*>(Wqh + (long)row * E_ + tid * 4) = pk;
        }
    } else if (b < QB_BIAS) {
        int bb = b - QB_WO;
        if (bb < 12) {
            int i = bb * 256 + tid;
            ybi[i] = rcf_dev(bi[i], a_bi[0], LN, MD);
        } else {
            int i = (bb - 12) * 256 + tid;
            ybo[i] = rcf_dev(bo[i], a_bo[0], LN, MD);
        }
    } else {
        int bb = b - QB_BIAS;
        int sel = bb >> 12;
        int blk = bb & 4095;
        const float* x = (sel == 0) ? q : (sel == 1) ? k : v;
        int8_t* yy = yact + (long)sel * R_ * E_;
        float a = a_act[0];
        long i0 = ((long)blk * 256 + tid) * 4;
        float4 vv = *reinterpret_cast<const float4*>(x + i0);
        char4 o;
        o.x = (int8_t)L48[rcf_idx(vv.x, a, MD)];
        o.y = (int8_t)L48[rcf_idx(vv.y, a, MD)];
        o.z = (int8_t)L48[rcf_idx(vv.z, a, MD)];
        o.w = (int8_t)L48[rcf_idx(vv.w, a, MD)];
        *reinterpret_cast<char4*>(yy + i0) = o;
    }
}

// ---------------------------------------------------------------------------
// fp16 split helper
// ---------------------------------------------------------------------------
__device__ __forceinline__ void split2(float a, float b, uint32_t& hi,
                                       uint32_t& lo) {
    __half2 h = __floats2half2_rn(a, b);
    __half2 l = __floats2half2_rn(a - __low2float(h), b - __high2float(h));
    hi = *reinterpret_cast<uint32_t*>(&h);
    lo = *reinterpret_cast<uint32_t*>(&l);
}

// ---------------------------------------------------------------------------
// int8 tensor-core projection GEMM, BK=128, cp.async ping-pong (dyn smem).
// ---------------------------------------------------------------------------
__device__ __forceinline__ void mma_i8(int* d, const uint32_t* a,
                                       const uint32_t* b) {
    asm volatile(
        "mma.sync.aligned.m16n8k32.row.col.s32.s8.s8.s32 "
        "{%0,%1,%2,%3}, {%4,%5,%6,%7}, {%8,%9}, {%0,%1,%2,%3};\n"
        : "+r"(d[0]), "+r"(d[1]), "+r"(d[2]), "+r"(d[3])
        : "r"(a[0]), "r"(a[1]), "r"(a[2]), "r"(a[3]), "r"(b[0]), "r"(b[1]));
}

#define I8_STRIDE 144                 // 128 data bytes + 16 pad
#define I8_BUF    (128 * I8_STRIDE)   // 18432
#define I8_STAGE  (2 * I8_BUF)
#define SM_TOTAL_I8 (2 * I8_STAGE)    // 73728

__global__ __launch_bounds__(256) void gemm_i8_kernel(
    const int8_t* __restrict__ A, const int8_t* __restrict__ B,
    __half* __restrict__ Ch, __half* __restrict__ Cl,
    const float* __restrict__ bias,
    const float* __restrict__ aA, const float* __restrict__ aB,
    int K, int N) {
    extern __shared__ char smi[];

    const int tid  = threadIdx.x;
    const int warp = tid >> 5;
    const int lane = tid & 31;
    const int g    = lane >> 2;
    const int tig  = lane & 3;

    const long z = blockIdx.z;
    A += z * (long)R_ * K;
    B += z * (long)N * K;
    Ch += z * (long)R_ * N;
    Cl += z * (long)R_ * N;
    bias += z * N;

    const int m0 = blockIdx.y * 128;
    const int n0 = blockIdx.x * 128;
    const int wm = (warp >> 2) * 64;
    const int wn = (warp & 3) * 32;

    int acc[4][4][4];
#pragma unroll
    for (int a_ = 0; a_ < 4; a_++)
#pragma unroll
        for (int b_ = 0; b_ < 4; b_++)
#pragma unroll
            for (int c_ = 0; c_ < 4; c_++) acc[a_][b_][c_] = 0;

    const int WSTR = I8_STRIDE / 4;   // 36 words

#pragma unroll
    for (int it = 0; it < 4; it++) {
        int idx = it * 256 + tid;
        int row = idx >> 3, c = idx & 7;
        cp_async16(smi + row * I8_STRIDE + c * 16,
                   A + (long)(m0 + row) * K + c * 16);
        cp_async16(smi + I8_BUF + row * I8_STRIDE + c * 16,
                   B + (long)(n0 + row) * K + c * 16);
    }
    CP_COMMIT();

    int stage = 0;
    for (int k0 = 0; k0 < K; k0 += 128) {
        CP_WAIT0();
        __syncthreads();
        if (k0 + 128 < K) {
            char* d = smi + (stage ^ 1) * I8_STAGE;
#pragma unroll
            for (int it = 0; it < 4; it++) {
                int idx = it * 256 + tid;
                int row = idx >> 3, c = idx & 7;
                cp_async16(d + row * I8_STRIDE + c * 16,
                           A + (long)(m0 + row) * K + k0 + 128 + c * 16);
                cp_async16(d + I8_BUF + row * I8_STRIDE + c * 16,
                           B + (long)(n0 + row) * K + k0 + 128 + c * 16);
            }
            CP_COMMIT();
        }

        const uint32_t* Aw = reinterpret_cast<const uint32_t*>(smi + stage * I8_STAGE);
        const uint32_t* Bw = reinterpret_cast<const uint32_t*>(smi + stage * I8_STAGE + I8_BUF);
#pragma unroll
        for (int ks = 0; ks < 4; ks++) {
            uint32_t af[4][4], bf[4][2];
#pragma unroll
            for (int mt = 0; mt < 4; mt++) {
                int base = (wm + mt * 16 + g) * WSTR + ks * 8 + tig;
                af[mt][0] = Aw[base];
                af[mt][1] = Aw[base + 8 * WSTR];
                af[mt][2] = Aw[base + 4];
                af[mt][3] = Aw[base + 8 * WSTR + 4];
            }
#pragma unroll
            for (int nt = 0; nt < 4; nt++) {
                int base = (wn + nt * 8 + g) * WSTR + ks * 8 + tig;
                bf[nt][0] = Bw[base];
                bf[nt][1] = Bw[base + 4];
            }
#pragma unroll
            for (int mt = 0; mt < 4; mt++)
#pragma unroll
                for (int nt = 0; nt < 4; nt++)
                    mma_i8(acc[mt][nt], af[mt], bf[nt]);
        }
        stage ^= 1;
    }

    const float f = (z == 0) ? 0.125f : 1.0f;
    const float scale = __ldg(aA) * __ldg(aB) * (1.0f / 2304.0f) * f;
#pragma unroll
    for (int mt = 0; mt < 4; mt++) {
#pragma unroll
        for (int nt = 0; nt < 4; nt++) {
            long row = m0 + wm + mt * 16 + g;
            long col = n0 + wn + nt * 8 + tig * 2;
            float b0 = bias[col] * f, b1 = bias[col + 1] * f;
            float v00 = (float)acc[mt][nt][0] * scale + b0;
            float v01 = (float)acc[mt][nt][1] * scale + b1;
            float v10 = (float)acc[mt][nt][2] * scale + b0;
            float v11 = (float)acc[mt][nt][3] * scale + b1;
            uint32_t h, l;
            split2(v00, v01, h, l);
            *reinterpret_cast<uint32_t*>(Ch + row * N + col) = h;
            *reinterpret_cast<uint32_t*>(Cl + row * N + col) = l;
            split2(v10, v11, h, l);
            *reinterpret_cast<uint32_t*>(Ch + (row + 8) * N + col) = h;
            *reinterpret_cast<uint32_t*>(Cl + (row + 8) * N + col) = l;
        }
    }
}

// ---------------------------------------------------------------------------
// Vectorized per-head transpose of vp planes (64x64 tiles, uint4 both sides):
//   vpT[z][d][t] = vp[t*4096 + 64*z + d]
// Load: uint4 along d (full sectors). Gather: warp lanes = consecutive d,
// 16 t per thread -> conflict-free LDS. Store: 32B contiguous along t.
// ---------------------------------------------------------------------------
#define TP_STRIDE 72   // ushorts per smem row (144 B, 16B-aligned)

__global__ __launch_bounds__(256) void transpose_v_kernel(
    const __half* __restrict__ vph, const __half* __restrict__ vpl,
    __half* __restrict__ vpTh, __half* __restrict__ vpTl) {
    __shared__ ushort tile[64 * TP_STRIDE];
    const int z = blockIdx.y;
    const int t0 = blockIdx.x * 64;
    const int tid = threadIdx.x;
#pragma unroll
    for (int p = 0; p < 2; p++) {
        const ushort* src =
            reinterpret_cast<const ushort*>(p ? vpl : vph) + 64L * z;
        ushort* dst =
            reinterpret_cast<ushort*>(p ? vpTl : vpTh) + (long)z * D_ * S_;
        // load 64 t-rows x 64 d halves (8 uint4 per row)
#pragma unroll
        for (int it = 0; it < 2; it++) {
            int idx = it * 256 + tid;
            int tt = idx >> 3, d8 = (idx & 7) * 8;
            uint4 vv = *reinterpret_cast<const uint4*>(
                src + (long)(t0 + tt) * 4096 + d8);
            *reinterpret_cast<uint4*>(&tile[tt * TP_STRIDE + d8]) = vv;
        }
        __syncthreads();
        // gather 16 t per thread for fixed d, store 32B along t
        {
            int tg = tid >> 6;       // 0..3
            int dd = tid & 63;
            int tt16 = tg * 16;
            __align__(16) ushort vals[16];
#pragma unroll
            for (int u = 0; u < 16; u++)
                vals[u] = tile[(tt16 + u) * TP_STRIDE + dd];
            ushort* dp = dst + (long)dd * S_ + t0 + tt16;
            *reinterpret_cast<uint4*>(dp) =
                *reinterpret_cast<uint4*>(&vals[0]);
            *reinterpret_cast<uint4*>(dp + 8) =
                *reinterpret_cast<uint4*>(&vals[8]);
        }
        __syncthreads();
    }
}

// ---------------------------------------------------------------------------
// fp16 mma helper
// ---------------------------------------------------------------------------
__device__ __forceinline__ void mma_f16(float* d, const uint32_t* a,
                                        const uint32_t* b) {
    asm volatile(
        "mma.sync.aligned.m16n8k16.row.col.f32.f16.f16.f32 "
        "{%0,%1,%2,%3}, {%4,%5,%6,%7}, {%8,%9}, {%0,%1,%2,%3};\n"
        : "+f"(d[0]), "+f"(d[1]), "+f"(d[2]), "+f"(d[3])
        : "r"(a[0]), "r"(a[1]), "r"(a[2]), "r"(a[3]), "r"(b[0]), "r"(b[1]));
}

// ---------------------------------------------------------------------------
// Fused flash attention with cp.async 2-stage K/V pipeline (unchanged).
// ---------------------------------------------------------------------------
#define KWORDS 36
#define VWORDS 68
#define STG_K  18432
#define STG_V  17408
#define STG_SZ (2*STG_K + 2*STG_V)      // 71680
#define SM_TOTAL_FLASH (2 * STG_SZ)     // 143360

__global__ __launch_bounds__(256) void flash_attn_kernel(
    const __half* __restrict__ Qh, const __half* __restrict__ Ql,
    const __half* __restrict__ Kh_, const __half* __restrict__ Kl_,
    const __half* __restrict__ Vh, const __half* __restrict__ Vl,
    __half* __restrict__ Oh, __half* __restrict__ Ol) {
    extern __shared__ char sm[];

    const int tid = threadIdx.x;
    const int warp = tid >> 5, lane = tid & 31;
    const int g = lane >> 2, tig = lane & 3;
    const int z = blockIdx.y;
    const int q0 = blockIdx.x * 128;

    const __half* Qbh = Qh + (long)z * 64;
    const __half* Qbl = Ql + (long)z * 64;
    const __half* Kbh = Kh_ + (long)z * 64;
    const __half* Kbl = Kl_ + (long)z * 64;
    const __half* Vbh = Vh + (long)z * D_ * S_;
    const __half* Vbl = Vl + (long)z * D_ * S_;

#pragma unroll
    for (int it = 0; it < 4; it++) {
        int idx = it * 256 + tid;
        int row = idx >> 3, qd = idx & 7;
        long gq = (long)(q0 + row) * 4096 + qd * 8;
        cp_async16(sm + STG_SZ + (row * 9 + qd) * 16, Qbh + gq);
        cp_async16(sm + STG_SZ + STG_K + (row * 9 + qd) * 16, Qbl + gq);
        long gk = (long)row * 4096 + qd * 8;
        cp_async16(sm + (row * 9 + qd) * 16, Kbh + gk);
        cp_async16(sm + STG_K + (row * 9 + qd) * 16, Kbl + gk);
        int vr = idx >> 4, vc = idx & 15;
        long gv = (long)vr * 1024 + vc * 8;
        cp_async16(sm + 2 * STG_K + (vr * 17 + vc) * 16, Vbh + gv);
        cp_async16(sm + 2 * STG_K + STG_V + (vr * 17 + vc) * 16, Vbl + gv);
    }
    CP_COMMIT();
    CP_WAIT0();
    __syncthreads();

    uint32_t qh[4][4], ql[4][4];
    {
        const uint32_t* QH = reinterpret_cast<const uint32_t*>(sm + STG_SZ);
        const uint32_t* QL = reinterpret_cast<const uint32_t*>(sm + STG_SZ + STG_K);
#pragma unroll
        for (int ks = 0; ks < 4; ks++) {
            int base = (warp * 16 + g) * KWORDS + ks * 8 + tig;
            qh[ks][0] = QH[base];
            qh[ks][1] = QH[base + 8 * KWORDS];
            qh[ks][2] = QH[base + 4];
            qh[ks][3] = QH[base + 8 * KWORDS + 4];
            ql[ks][0] = QL[base];
            ql[ks][1] = QL[base + 8 * KWORDS];
            ql[ks][2] = QL[base + 4];
            ql[ks][3] = QL[base + 8 * KWORDS + 4];
        }
    }
    __syncthreads();

    float ctx[8][4];
#pragma unroll
    for (int d8 = 0; d8 < 8; d8++)
#pragma unroll
        for (int c = 0; c < 4; c++) ctx[d8][c] = 0.0f;
    float M0 = -1e30f, M1 = -1e30f, T0 = 0.0f, T1 = 0.0f;

    int stage = 0;
    for (int t0 = 0; t0 < S_; t0 += 128) {
        if (t0 + 128 < S_) {
            char* d = sm + (stage ^ 1) * STG_SZ;
#pragma unroll
            for (int it = 0; it < 4; it++) {
                int idx = it * 256 + tid;
                int row = idx >> 3, qd = idx & 7;
                long gk = (long)(t0 + 128 + row) * 4096 + qd * 8;
                cp_async16(d + (row * 9 + qd) * 16, Kbh + gk);
                cp_async16(d + STG_K + (row * 9 + qd) * 16, Kbl + gk);
                int vr = idx >> 4, vc = idx & 15;
                long gv = (long)vr * 1024 + t0 + 128 + vc * 8;
                cp_async16(d + 2 * STG_K + (vr * 17 + vc) * 16, Vbh + gv);
                cp_async16(d + 2 * STG_K + STG_V + (vr * 17 + vc) * 16, Vbl + gv);
            }
            CP_COMMIT();
        }

        const uint32_t* KH = reinterpret_cast<const uint32_t*>(sm + stage * STG_SZ);
        const uint32_t* KL = reinterpret_cast<const uint32_t*>(sm + stage * STG_SZ + STG_K);
        const uint32_t* PH = reinterpret_cast<const uint32_t*>(sm + stage * STG_SZ + 2 * STG_K);
        const uint32_t* PL = reinterpret_cast<const uint32_t*>(sm + stage * STG_SZ + 2 * STG_K + STG_V);

        float acc[16][4];
#pragma unroll
        for (int nt = 0; nt < 16; nt++)
#pragma unroll
            for (int c = 0; c < 4; c++) acc[nt][c] = 0.0f;
#pragma unroll
        for (int nt = 0; nt < 16; nt++) {
#pragma unroll
            for (int ks = 0; ks < 4; ks++) {
                int base = (nt * 8 + g) * KWORDS + ks * 8 + tig;
                uint32_t bh[2] = {KH[base], KH[base + 4]};
                uint32_t bl[2] = {KL[base], KL[base + 4]};
                mma_f16(acc[nt], qh[ks], bh);
                mma_f16(acc[nt], qh[ks], bl);
                mma_f16(acc[nt], ql[ks], bh);
            }
        }

        float m0 = -1e30f, m1 = -1e30f;
#pragma unroll
        for (int nt = 0; nt < 16; nt++) {
            m0 = fmaxf(m0, fmaxf(acc[nt][0], acc[nt][1]));
            m1 = fmaxf(m1, fmaxf(acc[nt][2], acc[nt][3]));
        }
        m0 = fmaxf(m0, __shfl_xor_sync(0xffffffffu, m0, 1));
        m0 = fmaxf(m0, __shfl_xor_sync(0xffffffffu, m0, 2));
        m1 = fmaxf(m1, __shfl_xor_sync(0xffffffffu, m1, 1));
        m1 = fmaxf(m1, __shfl_xor_sync(0xffffffffu, m1, 2));
        float Mn0 = fmaxf(M0, m0), Mn1 = fmaxf(M1, m1);
        float a0 = __expf(M0 - Mn0), a1 = __expf(M1 - Mn1);
        M0 = Mn0; M1 = Mn1;

        float s0 = 0.0f, s1 = 0.0f;
#pragma unroll
        for (int nt = 0; nt < 16; nt++) {
            acc[nt][0] = __expf(acc[nt][0] - M0);
            acc[nt][1] = __expf(acc[nt][1] - M0);
            acc[nt][2] = __expf(acc[nt][2] - M1);
            acc[nt][3] = __expf(acc[nt][3] - M1);
            s0 += acc[nt][0] + acc[nt][1];
            s1 += acc[nt][2] + acc[nt][3];
        }
        s0 += __shfl_xor_sync(0xffffffffu, s0, 1);
        s0 += __shfl_xor_sync(0xffffffffu, s0, 2);
        s1 += __shfl_xor_sync(0xffffffffu, s1, 1);
        s1 += __shfl_xor_sync(0xffffffffu, s1, 2);
        T0 = T0 * a0 + s0;
        T1 = T1 * a1 + s1;
#pragma unroll
        for (int d8 = 0; d8 < 8; d8++) {
            ctx[d8][0] *= a0; ctx[d8][1] *= a0;
            ctx[d8][2] *= a1; ctx[d8][3] *= a1;
        }

#pragma unroll
        for (int c = 0; c < 8; c++) {
            uint32_t ah[4], al[4];
            split2(acc[2 * c][0],     acc[2 * c][1],     ah[0], al[0]);
            split2(acc[2 * c][2],     acc[2 * c][3],     ah[1], al[1]);
            split2(acc[2 * c + 1][0], acc[2 * c + 1][1], ah[2], al[2]);
            split2(acc[2 * c + 1][2], acc[2 * c + 1][3], ah[3], al[3]);
#pragma unroll
            for (int d8 = 0; d8 < 8; d8++) {
                int base = (d8 * 8 + g) * VWORDS + c * 8 + tig;
                uint32_t bh[2] = {PH[base], PH[base + 4]};
                uint32_t bl[2] = {PL[base], PL[base + 4]};
                mma_f16(ctx[d8], ah, bh);
                mma_f16(ctx[d8], ah, bl);
                mma_f16(ctx[d8], al, bh);
            }
        }

        CP_WAIT0();
        __syncthreads();
        stage ^= 1;
    }

    float i0 = 1.0f / T0, i1 = 1.0f / T1;
    const long r0 = q0 + warp * 16 + g;
#pragma unroll
    for (int d8 = 0; d8 < 8; d8++) {
        long col = (long)z * 64 + d8 * 8 + tig * 2;
        uint32_t h, l;
        split2(ctx[d8][0] * i0, ctx[d8][1] * i0, h, l);
        *reinterpret_cast<uint32_t*>(Oh + r0 * 4096 + col) = h;
        *reinterpret_cast<uint32_t*>(Ol + r0 * 4096 + col) = l;
        split2(ctx[d8][2] * i1, ctx[d8][3] * i1, h, l);
        *reinterpret_cast<uint32_t*>(Oh + (r0 + 8) * 4096 + col) = h;
        *reinterpret_cast<uint32_t*>(Ol + (r0 + 8) * 4096 + col) = l;
    }
}

// ---------------------------------------------------------------------------
// Output projection: ctx hi/lo planes x Wo_k (exact fp16) — 2 passes, BK=64,
// cp.async 2-stage ping-pong (unchanged from round 15).
// ---------------------------------------------------------------------------
#define WO_STRIDE 144
#define WO_BUF    (128 * WO_STRIDE)   // 18432
#define WO_STAGE  (3 * WO_BUF)
#define SM_TOTAL_WO (2 * WO_STAGE)    // 110592

__global__ __launch_bounds__(256) void gemm_ctx_wo_kernel(
    const __half* __restrict__ Ahp, const __half* __restrict__ Alp,
    const __half* __restrict__ B,
    float* __restrict__ C, const float* __restrict__ bias,
    const float* __restrict__ aB) {
    const int K = E_;
    extern __shared__ char smw[];

    const int tid  = threadIdx.x;
    const int warp = tid >> 5;
    const int lane = tid & 31;
    const int g    = lane >> 2;
    const int tig  = lane & 3;

    const int m0 = blockIdx.y * 128;
    const int n0 = blockIdx.x * 128;
    const int wm = (warp >> 2) * 64;
    const int wn = (warp & 3) * 32;

    float acc[4][4][4];
#pragma unroll
    for (int mt = 0; mt < 4; mt++)
#pragma unroll
        for (int nt = 0; nt < 4; nt++)
#pragma unroll
            for (int c = 0; c < 4; c++) acc[mt][nt][c] = 0.0f;

    const int WSTR = WO_STRIDE / 4;   // 36 words

#pragma unroll
    for (int it = 0; it < 4; it++) {
        int idx = it * 256 + tid;
        int row = idx >> 3, qd = idx & 7;
        long goA = (long)(m0 + row) * K + qd * 8;
        cp_async16(smw + row * WO_STRIDE + qd * 16, Ahp + goA);
        cp_async16(smw + WO_BUF + row * WO_STRIDE + qd * 16, Alp + goA);
        cp_async16(smw + 2 * WO_BUF + row * WO_STRIDE + qd * 16,
                   B + (long)(n0 + row) * K + qd * 8);
    }
    CP_COMMIT();

    int stage = 0;
    for (int k0 = 0; k0 < K; k0 += 64) {
        CP_WAIT0();
        __syncthreads();
        if (k0 + 64 < K) {
            char* d = smw + (stage ^ 1) * WO_STAGE;
#pragma unroll
            for (int it = 0; it < 4; it++) {
                int idx = it * 256 + tid;
                int row = idx >> 3, qd = idx & 7;
                long goA = (long)(m0 + row) * K + k0 + 64 + qd * 8;
                cp_async16(d + row * WO_STRIDE + qd * 16, Ahp + goA);
                cp_async16(d + WO_BUF + row * WO_STRIDE + qd * 16, Alp + goA);
                cp_async16(d + 2 * WO_BUF + row * WO_STRIDE + qd * 16,
                           B + (long)(n0 + row) * K + k0 + 64 + qd * 8);
            }
            CP_COMMIT();
        }

        const uint32_t* Ahw = reinterpret_cast<const uint32_t*>(smw + stage * WO_STAGE);
        const uint32_t* Alw = reinterpret_cast<const uint32_t*>(smw + stage * WO_STAGE + WO_BUF);
        const uint32_t* Bw  = reinterpret_cast<const uint32_t*>(smw + stage * WO_STAGE + 2 * WO_BUF);
#pragma unroll
        for (int ks = 0; ks < 4; ks++) {
            uint32_t ah[4][4], al[4][4], bf[4][2];
#pragma unroll
            for (int mt = 0; mt < 4; mt++) {
                int base = (wm + mt * 16 + g) * WSTR + ks * 8 + tig;
                ah[mt][0] = Ahw[base];
                ah[mt][1] = Ahw[base + 8 * WSTR];
                ah[mt][2] = Ahw[base + 4];
                ah[mt][3] = Ahw[base + 8 * WSTR + 4];
                al[mt][0] = Alw[base];
                al[mt][1] = Alw[base + 8 * WSTR];
                al[mt][2] = Alw[base + 4];
                al[mt][3] = Alw[base + 8 * WSTR + 4];
            }
#pragma unroll
            for (int nt = 0; nt < 4; nt++) {
                int base = (wn + nt * 8 + g) * WSTR + ks * 8 + tig;
                bf[nt][0] = Bw[base];
                bf[nt][1] = Bw[base + 4];
            }
#pragma unroll
            for (int mt = 0; mt < 4; mt++)
#pragma unroll
                for (int nt = 0; nt < 4; nt++) {
                    mma_f16(acc[mt][nt], ah[mt], bf[nt]);
                    mma_f16(acc[mt][nt], al[mt], bf[nt]);
                }
        }
        stage ^= 1;
    }

    const float scale = __ldg(aB) * (1.0f / 48.0f);
#pragma unroll
    for (int mt = 0; mt < 4; mt++) {
#pragma unroll
        for (int nt = 0; nt < 4; nt++) {
            long row = m0 + wm + mt * 16 + g;
            long col = n0 + wn + nt * 8 + tig * 2;
            float b0 = bias[col], b1 = bias[col + 1];
            float2 v0, v1;
            v0.x = acc[mt][nt][0] * scale + b0;
            v0.y = acc[mt][nt][1] * scale + b1;
            v1.x = acc[mt][nt][2] * scale + b0;
            v1.y = acc[mt][nt][3] * scale + b1;
            *reinterpret_cast<float2*>(C + row * (long)E_ + col) = v0;
            *reinterpret_cast<float2*>(C + (row + 8) * (long)E_ + col) = v1;
        }
    }
}

// ---------------------------------------------------------------------------
// Orchestration.
// ---------------------------------------------------------------------------
extern "C" void kernel_launch(void* const* d_in, const int* in_sizes, int n_in,
                              void* d_out, int out_size) {
    const float* q    = (const float*)d_in[0];
    const float* k    = (const float*)d_in[1];
    const float* v    = (const float*)d_in[2];
    const float* Wi   = (const float*)d_in[3];
    const float* bi   = (const float*)d_in[4];
    const float* Wo   = (const float*)d_in[5];
    const float* bo   = (const float*)d_in[6];
    const float* a_act = (const float*)d_in[7];
    const float* a_wi  = (const float*)d_in[8];
    const float* a_bi  = (const float*)d_in[9];
    const float* a_wo  = (const float*)d_in[10];
    const float* a_bo  = (const float*)d_in[11];
    float* out = (float*)d_out;

    int8_t *p_Wi8, *p_act8;
    __half *p_Woh, *p_ph, *p_pl, *p_vTh, *p_vTl, *p_cxh, *p_cxl;
    float *p_bi, *p_bo;
    cudaGetSymbolAddress((void**)&p_Wi8, g_Wi_i8);
    cudaGetSymbolAddress((void**)&p_act8, g_act_i8);
    cudaGetSymbolAddress((void**)&p_Woh, g_Wo_h);
    cudaGetSymbolAddress((void**)&p_bi, g_bi);
    cudaGetSymbolAddress((void**)&p_bo, g_bo);
    cudaGetSymbolAddress((void**)&p_ph, g_proj_h);
    cudaGetSymbolAddress((void**)&p_pl, g_proj_l);
    cudaGetSymbolAddress((void**)&p_vTh, g_vpT_h);
    cudaGetSymbolAddress((void**)&p_vTl, g_vpT_l);
    cudaGetSymbolAddress((void**)&p_cxh, g_ctx_h);
    cudaGetSymbolAddress((void**)&p_cxl, g_ctx_l);

    const long RE = (long)R_ * E_;

    cudaFuncSetAttribute(flash_attn_kernel,
                         cudaFuncAttributeMaxDynamicSharedMemorySize,
                         SM_TOTAL_FLASH);
    cudaFuncSetAttribute(gemm_ctx_wo_kernel,
                         cudaFuncAttributeMaxDynamicSharedMemorySize,
                         SM_TOTAL_WO);
    cudaFuncSetAttribute(gemm_i8_kernel,
                         cudaFuncAttributeMaxDynamicSharedMemorySize,
                         SM_TOTAL_I8);

    init_tables_kernel<<<1, 1>>>();

    // Fused quantization: weights + biases + activations in ONE launch
    quant_all_kernel<<<QB_TOT, 256>>>(
        Wi, Wo, bi, bo, q, k, v,
        p_Wi8, p_Woh, p_bi, p_bo, p_act8,
        a_wi, a_wo, a_bi, a_bo, a_act);

    // Projections via int8 tensor cores (exact) -> fp16 hi/lo planes
    gemm_i8_kernel<<<dim3(E_ / 128, R_ / 128, 3), 256, SM_TOTAL_I8>>>(
        p_act8, p_Wi8, p_ph, p_pl, p_bi, a_act, a_wi, E_, E_);

    // Vectorized transpose of vp planes per head (B-operand layout for PV)
    transpose_v_kernel<<<dim3(S_ / 64, Z_), 256>>>(
        p_ph + 2 * RE, p_pl + 2 * RE, p_vTh, p_vTl);

    // Fused attention: scores + online softmax + PV -> ctx planes
    flash_attn_kernel<<<dim3(S_ / 128, Z_), 256, SM_TOTAL_FLASH>>>(
        p_ph, p_pl, p_ph + RE, p_pl + RE, p_vTh, p_vTl, p_cxh, p_cxl);

    // Output projection: ctx planes x Wo_k (exact fp16, 2 passes) -> out
    gemm_ctx_wo_kernel<<<dim3(8, 32), 256, SM_TOTAL_WO>>>(
        p_cxh, p_cxl, p_Woh, out, p_bo, a_wo);
}

// round 17
// speedup vs baseline: 6.2203x; 1.0424x over previous
#include <cuda_runtime.h>
#include <cuda_fp16.h>
#include <math.h>
#include <stdint.h>

#define EPSQ 1e-5f

// Problem sizes (fixed by the reference setup_inputs)
#define S_ 1024
#define B_ 4
#define E_ 1024
#define H_ 16
#define D_ 64
#define R_ (S_*B_)   // 4096 flattened (s,b) rows
#define Z_ (B_*H_)   // 64 batched heads

// ---------------------------------------------------------------------------
// Static device scratch (no runtime allocation allowed)
// ---------------------------------------------------------------------------
__device__ float g_LN[31];
__device__ float g_MIDS[30];
__device__ int   g_LN48[31];

__device__ __align__(16) int8_t g_Wi_i8[3*E_*E_];
__device__ __align__(16) __half g_Wo_h[E_*E_];         // Wo k-values (exact fp16)
__device__ __align__(16) float  g_bi[3*E_];
__device__ __align__(16) float  g_bo[E_];
__device__ __align__(16) int8_t g_act_i8[3L*R_*E_];
__device__ __align__(16) __half g_proj_h[3L*R_*E_];    // qp,kp,vp hi plane
__device__ __align__(16) __half g_proj_l[3L*R_*E_];    // qp,kp,vp lo plane
__device__ __align__(16) __half g_ctx_h[(long)R_*E_];
__device__ __align__(16) __half g_ctx_l[(long)R_*E_];

// ---------------------------------------------------------------------------
// cp.async / ldmatrix helpers
// ---------------------------------------------------------------------------
__device__ __forceinline__ void cp_async16(void* smem_ptr, const void* gptr) {
    uint32_t a = (uint32_t)__cvta_generic_to_shared(smem_ptr);
    asm volatile("cp.async.cg.shared.global [%0], [%1], 16;"
                 :: "r"(a), "l"(gptr));
}
#define CP_COMMIT() asm volatile("cp.async.commit_group;" ::: "memory")
#define CP_WAIT0()  asm volatile("cp.async.wait_group 0;" ::: "memory")

__device__ __forceinline__ void ldsm_x4_trans(uint32_t& r0, uint32_t& r1,
                                              uint32_t& r2, uint32_t& r3,
                                              uint32_t addr) {
    asm volatile(
        "ldmatrix.sync.aligned.m8n8.x4.trans.shared.b16 {%0,%1,%2,%3}, [%4];"
        : "=r"(r0), "=r"(r1), "=r"(r2), "=r"(r3) : "r"(addr));
}

// ---------------------------------------------------------------------------
// APoT tables (exact float emulation of the numpy construction)
// ---------------------------------------------------------------------------
__global__ void init_tables_kernel() {
    const float pos[15] = {0.03125f, 0.0625f, 0.09375f, 0.125f, 0.1875f,
                           0.25f, 0.28125f, 0.375f, 0.5f, 0.5625f,
                           0.75f, 1.0f, 1.03125f, 1.125f, 1.5f};
    const float G = (float)(1.0 / 1.5);
    for (int i = 0; i < 15; i++) {
        g_LN[i]      = (-pos[14 - i]) * G;
        g_LN[16 + i] = pos[i] * G;
    }
    g_LN[15] = 0.0f;
    for (int i = 0; i < 30; i++)
        g_MIDS[i] = (g_LN[i] + g_LN[i + 1]) * 0.5f;
    for (int i = 0; i < 31; i++)
        g_LN48[i] = (int)lrintf(g_LN[i] * 48.0f);
}

// Binary-search count(MD[i] < xc) over 30 sorted mids (== searchsorted left).
__device__ __forceinline__ int rcf_idx(float x, float alpha,
                                       const float* __restrict__ MD) {
    float xn = x / (alpha + EPSQ);
    float xc = fminf(1.0f, fmaxf(-1.0f, xn));
    int c = 0;
    if (MD[15] < xc) c = 16;
    if (c + 8 <= 30 && MD[c + 7] < xc) c += 8;
    if (c + 4 <= 30 && MD[c + 3] < xc) c += 4;
    if (c + 2 <= 30 && MD[c + 1] < xc) c += 2;
    if (c + 1 <= 30 && MD[c] < xc) c += 1;
    return c;
}
__device__ __forceinline__ float rcf_dev(float x, float alpha,
                                         const float* __restrict__ LN,
                                         const float* __restrict__ MD) {
    return LN[rcf_idx(x, alpha, MD)] * alpha;
}

// ---------------------------------------------------------------------------
// Fused quantization kernel (unchanged from round 15/16)
// ---------------------------------------------------------------------------
#define QB_WI   3072
#define QB_WO   4096
#define QB_BIAS 4112
#define QB_TOT  16400

__global__ __launch_bounds__(256) void quant_all_kernel(
    const float* __restrict__ Wi, const float* __restrict__ Wo,
    const float* __restrict__ bi, const float* __restrict__ bo,
    const float* __restrict__ q, const float* __restrict__ k,
    const float* __restrict__ v,
    int8_t* __restrict__ Wq8, __half* __restrict__ Wqh,
    float* __restrict__ ybi, float* __restrict__ ybo,
    int8_t* __restrict__ yact,
    const float* __restrict__ a_wi, const float* __restrict__ a_wo,
    const float* __restrict__ a_bi, const float* __restrict__ a_bo,
    const float* __restrict__ a_act) {
    __shared__ float LN[31], MD[30];
    __shared__ int   L48[31];
    __shared__ float red[8];
    const int tid = threadIdx.x;
    const int lane = tid & 31, warp = tid >> 5;
    if (tid < 31) { LN[tid] = g_LN[tid]; L48[tid] = g_LN48[tid]; }
    if (tid < 30) MD[tid] = g_MIDS[tid];
    __syncthreads();

    const int b = blockIdx.x;
    if (b < QB_WO) {
        const bool isWi = (b < QB_WI);
        const int row = isWi ? b : (b - QB_WI);
        const float* w = (isWi ? Wi : Wo) + (long)row * E_;
        float4 w4 = *reinterpret_cast<const float4*>(w + tid * 4);

        float s = w4.x + w4.y + w4.z + w4.w;
#pragma unroll
        for (int o = 16; o > 0; o >>= 1) s += __shfl_xor_sync(0xffffffffu, s, o);
        if (lane == 0) red[warp] = s;
        __syncthreads();
        float tot = red[0];
#pragma unroll
        for (int i = 1; i < 8; i++) tot += red[i];
        float mu = tot * (1.0f / E_);

        float dx = w4.x - mu, dy = w4.y - mu, dz = w4.z - mu, dw = w4.w - mu;
        float s2 = dx * dx + dy * dy + dz * dz + dw * dw;
#pragma unroll
        for (int o = 16; o > 0; o >>= 1) s2 += __shfl_xor_sync(0xffffffffu, s2, o);
        __syncthreads();
        if (lane == 0) red[warp] = s2;
        __syncthreads();
        float tot2 = red[0];
#pragma unroll
        for (int i = 1; i < 8; i++) tot2 += red[i];
        float var = tot2 * (1.0f / E_);

        float inv = 1.0f / sqrtf(var + EPSQ);
        float a = isWi ? a_wi[0] : a_wo[0];
        int k0 = L48[rcf_idx(dx * inv, a, MD)];
        int k1 = L48[rcf_idx(dy * inv, a, MD)];
        int k2 = L48[rcf_idx(dz * inv, a, MD)];
        int k3 = L48[rcf_idx(dw * inv, a, MD)];
        if (isWi) {
            char4 o;
            o.x = (int8_t)k0; o.y = (int8_t)k1;
            o.z = (int8_t)k2; o.w = (int8_t)k3;
            *reinterpret_cast<char4*>(Wq8 + (long)row * E_ + tid * 4) = o;
        } else {
            __half2 h01 = __floats2half2_rn((float)k0, (float)k1);
            __half2 h23 = __floats2half2_rn((float)k2, (float)k3);
            uint2 pk;
            pk.x = *reinterpret_cast<uint32_t*>(&h01);
            pk.y = *reinterpret_cast<uint32_t*>(&h23);
            *reinterpret_cast<uint2*>(Wqh + (long)row * E_ + tid * 4) = pk;
        }
    } else if (b < QB_BIAS) {
        int bb = b - QB_WO;
        if (bb < 12) {
            int i = bb * 256 + tid;
            ybi[i] = rcf_dev(bi[i], a_bi[0], LN, MD);
        } else {
            int i = (bb - 12) * 256 + tid;
            ybo[i] = rcf_dev(bo[i], a_bo[0], LN, MD);
        }
    } else {
        int bb = b - QB_BIAS;
        int sel = bb >> 12;
        int blk = bb & 4095;
        const float* x = (sel == 0) ? q : (sel == 1) ? k : v;
        int8_t* yy = yact + (long)sel * R_ * E_;
        float a = a_act[0];
        long i0 = ((long)blk * 256 + tid) * 4;
        float4 vv = *reinterpret_cast<const float4*>(x + i0);
        char4 o;
        o.x = (int8_t)L48[rcf_idx(vv.x, a, MD)];
        o.y = (int8_t)L48[rcf_idx(vv.y, a, MD)];
        o.z = (int8_t)L48[rcf_idx(vv.z, a, MD)];
        o.w = (int8_t)L48[rcf_idx(vv.w, a, MD)];
        *reinterpret_cast<char4*>(yy + i0) = o;
    }
}

// ---------------------------------------------------------------------------
// fp16 split helper
// ---------------------------------------------------------------------------
__device__ __forceinline__ void split2(float a, float b, uint32_t& hi,
                                       uint32_t& lo) {
    __half2 h = __floats2half2_rn(a, b);
    __half2 l = __floats2half2_rn(a - __low2float(h), b - __high2float(h));
    hi = *reinterpret_cast<uint32_t*>(&h);
    lo = *reinterpret_cast<uint32_t*>(&l);
}

// ---------------------------------------------------------------------------
// int8 tensor-core projection GEMM, BK=128, cp.async ping-pong (unchanged).
// ---------------------------------------------------------------------------
__device__ __forceinline__ void mma_i8(int* d, const uint32_t* a,
                                       const uint32_t* b) {
    asm volatile(
        "mma.sync.aligned.m16n8k32.row.col.s32.s8.s8.s32 "
        "{%0,%1,%2,%3}, {%4,%5,%6,%7}, {%8,%9}, {%0,%1,%2,%3};\n"
        : "+r"(d[0]), "+r"(d[1]), "+r"(d[2]), "+r"(d[3])
        : "r"(a[0]), "r"(a[1]), "r"(a[2]), "r"(a[3]), "r"(b[0]), "r"(b[1]));
}

#define I8_STRIDE 144
#define I8_BUF    (128 * I8_STRIDE)   // 18432
#define I8_STAGE  (2 * I8_BUF)
#define SM_TOTAL_I8 (2 * I8_STAGE)    // 73728

__global__ __launch_bounds__(256) void gemm_i8_kernel(
    const int8_t* __restrict__ A, const int8_t* __restrict__ B,
    __half* __restrict__ Ch, __half* __restrict__ Cl,
    const float* __restrict__ bias,
    const float* __restrict__ aA, const float* __restrict__ aB,
    int K, int N) {
    extern __shared__ char smi[];

    const int tid  = threadIdx.x;
    const int warp = tid >> 5;
    const int lane = tid & 31;
    const int g    = lane >> 2;
    const int tig  = lane & 3;

    const long z = blockIdx.z;
    A += z * (long)R_ * K;
    B += z * (long)N * K;
    Ch += z * (long)R_ * N;
    Cl += z * (long)R_ * N;
    bias += z * N;

    const int m0 = blockIdx.y * 128;
    const int n0 = blockIdx.x * 128;
    const int wm = (warp >> 2) * 64;
    const int wn = (warp & 3) * 32;

    int acc[4][4][4];
#pragma unroll
    for (int a_ = 0; a_ < 4; a_++)
#pragma unroll
        for (int b_ = 0; b_ < 4; b_++)
#pragma unroll
            for (int c_ = 0; c_ < 4; c_++) acc[a_][b_][c_] = 0;

    const int WSTR = I8_STRIDE / 4;   // 36 words

#pragma unroll
    for (int it = 0; it < 4; it++) {
        int idx = it * 256 + tid;
        int row = idx >> 3, c = idx & 7;
        cp_async16(smi + row * I8_STRIDE + c * 16,
                   A + (long)(m0 + row) * K + c * 16);
        cp_async16(smi + I8_BUF + row * I8_STRIDE + c * 16,
                   B + (long)(n0 + row) * K + c * 16);
    }
    CP_COMMIT();

    int stage = 0;
    for (int k0 = 0; k0 < K; k0 += 128) {
        CP_WAIT0();
        __syncthreads();
        if (k0 + 128 < K) {
            char* d = smi + (stage ^ 1) * I8_STAGE;
#pragma unroll
            for (int it = 0; it < 4; it++) {
                int idx = it * 256 + tid;
                int row = idx >> 3, c = idx & 7;
                cp_async16(d + row * I8_STRIDE + c * 16,
                           A + (long)(m0 + row) * K + k0 + 128 + c * 16);
                cp_async16(d + I8_BUF + row * I8_STRIDE + c * 16,
                           B + (long)(n0 + row) * K + k0 + 128 + c * 16);
            }
            CP_COMMIT();
        }

        const uint32_t* Aw = reinterpret_cast<const uint32_t*>(smi + stage * I8_STAGE);
        const uint32_t* Bw = reinterpret_cast<const uint32_t*>(smi + stage * I8_STAGE + I8_BUF);
#pragma unroll
        for (int ks = 0; ks < 4; ks++) {
            uint32_t af[4][4], bf[4][2];
#pragma unroll
            for (int mt = 0; mt < 4; mt++) {
                int base = (wm + mt * 16 + g) * WSTR + ks * 8 + tig;
                af[mt][0] = Aw[base];
                af[mt][1] = Aw[base + 8 * WSTR];
                af[mt][2] = Aw[base + 4];
                af[mt][3] = Aw[base + 8 * WSTR + 4];
            }
#pragma unroll
            for (int nt = 0; nt < 4; nt++) {
                int base = (wn + nt * 8 + g) * WSTR + ks * 8 + tig;
                bf[nt][0] = Bw[base];
                bf[nt][1] = Bw[base + 4];
            }
#pragma unroll
            for (int mt = 0; mt < 4; mt++)
#pragma unroll
                for (int nt = 0; nt < 4; nt++)
                    mma_i8(acc[mt][nt], af[mt], bf[nt]);
        }
        stage ^= 1;
    }

    const float f = (z == 0) ? 0.125f : 1.0f;
    const float scale = __ldg(aA) * __ldg(aB) * (1.0f / 2304.0f) * f;
#pragma unroll
    for (int mt = 0; mt < 4; mt++) {
#pragma unroll
        for (int nt = 0; nt < 4; nt++) {
            long row = m0 + wm + mt * 16 + g;
            long col = n0 + wn + nt * 8 + tig * 2;
            float b0 = bias[col] * f, b1 = bias[col + 1] * f;
            float v00 = (float)acc[mt][nt][0] * scale + b0;
            float v01 = (float)acc[mt][nt][1] * scale + b1;
            float v10 = (float)acc[mt][nt][2] * scale + b0;
            float v11 = (float)acc[mt][nt][3] * scale + b1;
            uint32_t h, l;
            split2(v00, v01, h, l);
            *reinterpret_cast<uint32_t*>(Ch + row * N + col) = h;
            *reinterpret_cast<uint32_t*>(Cl + row * N + col) = l;
            split2(v10, v11, h, l);
            *reinterpret_cast<uint32_t*>(Ch + (row + 8) * N + col) = h;
            *reinterpret_cast<uint32_t*>(Cl + (row + 8) * N + col) = l;
        }
    }
}

// ---------------------------------------------------------------------------
// fp16 mma helper
// ---------------------------------------------------------------------------
__device__ __forceinline__ void mma_f16(float* d, const uint32_t* a,
                                        const uint32_t* b) {
    asm volatile(
        "mma.sync.aligned.m16n8k16.row.col.f32.f16.f16.f32 "
        "{%0,%1,%2,%3}, {%4,%5,%6,%7}, {%8,%9}, {%0,%1,%2,%3};\n"
        : "+f"(d[0]), "+f"(d[1]), "+f"(d[2]), "+f"(d[3])
        : "r"(a[0]), "r"(a[1]), "r"(a[2]), "r"(a[3]), "r"(b[0]), "r"(b[1]));
}

// ---------------------------------------------------------------------------
// Fused flash attention, cp.async 2-stage pipeline. V loaded in NATURAL
// layout (same row pattern as K) and transposed on the fly by
// ldmatrix.x4.trans -> no separate transpose kernel, no vpT buffers.
// Stage layout (bytes): KH@0, KL@STG_K, VH@2*STG_K, VL@3*STG_K.
// ---------------------------------------------------------------------------
#define KWORDS 36
#define STG_K  18432
#define STG_SZ (4 * STG_K)              // 73728
#define SM_TOTAL_FLASH (2 * STG_SZ)     // 147456

__global__ __launch_bounds__(256) void flash_attn_kernel(
    const __half* __restrict__ Qh, const __half* __restrict__ Ql,
    const __half* __restrict__ Kh_, const __half* __restrict__ Kl_,
    const __half* __restrict__ Vh, const __half* __restrict__ Vl,
    __half* __restrict__ Oh, __half* __restrict__ Ol) {
    extern __shared__ char sm[];
    const uint32_t smb = (uint32_t)__cvta_generic_to_shared(sm);

    const int tid = threadIdx.x;
    const int warp = tid >> 5, lane = tid & 31;
    const int g = lane >> 2, tig = lane & 3;
    const int z = blockIdx.y;
    const int q0 = blockIdx.x * 128;

    const __half* Qbh = Qh + (long)z * 64;     // s-stride 4096 halves
    const __half* Qbl = Ql + (long)z * 64;
    const __half* Kbh = Kh_ + (long)z * 64;
    const __half* Kbl = Kl_ + (long)z * 64;
    const __half* Vbh = Vh + (long)z * 64;     // natural layout, like K
    const __half* Vbl = Vl + (long)z * 64;

    // ldmatrix lane offset: tile = lane>>3 selects (t+8?, d+8?) quadrant
    const int lm_tile = lane >> 3, lm_r = lane & 7;
    const uint32_t lm_off =
        (uint32_t)(((lm_tile & 1) * 8 + lm_r) * 144 + ((lm_tile >> 1) * 8) * 2);

    // ---- prologue: Q -> stage1 K-region; tile0 K,V -> stage0
#pragma unroll
    for (int it = 0; it < 4; it++) {
        int idx = it * 256 + tid;
        int row = idx >> 3, qd = idx & 7;           // 128 rows x 8 uint4
        long gq = (long)(q0 + row) * 4096 + qd * 8;
        cp_async16(sm + STG_SZ + (row * 9 + qd) * 16, Qbh + gq);
        cp_async16(sm + STG_SZ + STG_K + (row * 9 + qd) * 16, Qbl + gq);
        long gk = (long)row * 4096 + qd * 8;        // t0 = 0
        cp_async16(sm + (row * 9 + qd) * 16, Kbh + gk);
        cp_async16(sm + STG_K + (row * 9 + qd) * 16, Kbl + gk);
        cp_async16(sm + 2 * STG_K + (row * 9 + qd) * 16, Vbh + gk);
        cp_async16(sm + 3 * STG_K + (row * 9 + qd) * 16, Vbl + gk);
    }
    CP_COMMIT();
    CP_WAIT0();
    __syncthreads();

    // ---- extract Q fragments from stage1 K-region
    uint32_t qh[4][4], ql[4][4];
    {
        const uint32_t* QH = reinterpret_cast<const uint32_t*>(sm + STG_SZ);
        const uint32_t* QL = reinterpret_cast<const uint32_t*>(sm + STG_SZ + STG_K);
#pragma unroll
        for (int ks = 0; ks < 4; ks++) {
            int base = (warp * 16 + g) * KWORDS + ks * 8 + tig;
            qh[ks][0] = QH[base];
            qh[ks][1] = QH[base + 8 * KWORDS];
            qh[ks][2] = QH[base + 4];
            qh[ks][3] = QH[base + 8 * KWORDS + 4];
            ql[ks][0] = QL[base];
            ql[ks][1] = QL[base + 8 * KWORDS];
            ql[ks][2] = QL[base + 4];
            ql[ks][3] = QL[base + 8 * KWORDS + 4];
        }
    }
    __syncthreads();   // stage1 free for tile1 copies

    float ctx[8][4];
#pragma unroll
    for (int d8 = 0; d8 < 8; d8++)
#pragma unroll
        for (int c = 0; c < 4; c++) ctx[d8][c] = 0.0f;
    float M0 = -1e30f, M1 = -1e30f, T0 = 0.0f, T1 = 0.0f;

    int stage = 0;
    for (int t0 = 0; t0 < S_; t0 += 128) {
        // ---- issue next tile into the other stage (overlaps compute)
        if (t0 + 128 < S_) {
            char* d = sm + (stage ^ 1) * STG_SZ;
#pragma unroll
            for (int it = 0; it < 4; it++) {
                int idx = it * 256 + tid;
                int row = idx >> 3, qd = idx & 7;
                long gk = (long)(t0 + 128 + row) * 4096 + qd * 8;
                cp_async16(d + (row * 9 + qd) * 16, Kbh + gk);
                cp_async16(d + STG_K + (row * 9 + qd) * 16, Kbl + gk);
                cp_async16(d + 2 * STG_K + (row * 9 + qd) * 16, Vbh + gk);
                cp_async16(d + 3 * STG_K + (row * 9 + qd) * 16, Vbl + gk);
            }
            CP_COMMIT();
        }

        const uint32_t* KH = reinterpret_cast<const uint32_t*>(sm + stage * STG_SZ);
        const uint32_t* KL = reinterpret_cast<const uint32_t*>(sm + stage * STG_SZ + STG_K);
        const uint32_t VHa = smb + stage * STG_SZ + 2 * STG_K + lm_off;
        const uint32_t VLa = smb + stage * STG_SZ + 3 * STG_K + lm_off;

        // ---- S = Q K^T (f16x3); 0.125 already folded into Q
        float acc[16][4];
#pragma unroll
        for (int nt = 0; nt < 16; nt++)
#pragma unroll
            for (int c = 0; c < 4; c++) acc[nt][c] = 0.0f;
#pragma unroll
        for (int nt = 0; nt < 16; nt++) {
#pragma unroll
            for (int ks = 0; ks < 4; ks++) {
                int base = (nt * 8 + g) * KWORDS + ks * 8 + tig;
                uint32_t bh[2] = {KH[base], KH[base + 4]};
                uint32_t bl[2] = {KL[base], KL[base + 4]};
                mma_f16(acc[nt], qh[ks], bh);
                mma_f16(acc[nt], qh[ks], bl);
                mma_f16(acc[nt], ql[ks], bh);
            }
        }

        // ---- online softmax stats (rows g and g+8, quad shuffles)
        float m0 = -1e30f, m1 = -1e30f;
#pragma unroll
        for (int nt = 0; nt < 16; nt++) {
            m0 = fmaxf(m0, fmaxf(acc[nt][0], acc[nt][1]));
            m1 = fmaxf(m1, fmaxf(acc[nt][2], acc[nt][3]));
        }
        m0 = fmaxf(m0, __shfl_xor_sync(0xffffffffu, m0, 1));
        m0 = fmaxf(m0, __shfl_xor_sync(0xffffffffu, m0, 2));
        m1 = fmaxf(m1, __shfl_xor_sync(0xffffffffu, m1, 1));
        m1 = fmaxf(m1, __shfl_xor_sync(0xffffffffu, m1, 2));
        float Mn0 = fmaxf(M0, m0), Mn1 = fmaxf(M1, m1);
        float a0 = __expf(M0 - Mn0), a1 = __expf(M1 - Mn1);
        M0 = Mn0; M1 = Mn1;

        float s0 = 0.0f, s1 = 0.0f;
#pragma unroll
        for (int nt = 0; nt < 16; nt++) {
            acc[nt][0] = __expf(acc[nt][0] - M0);
            acc[nt][1] = __expf(acc[nt][1] - M0);
            acc[nt][2] = __expf(acc[nt][2] - M1);
            acc[nt][3] = __expf(acc[nt][3] - M1);
            s0 += acc[nt][0] + acc[nt][1];
            s1 += acc[nt][2] + acc[nt][3];
        }
        s0 += __shfl_xor_sync(0xffffffffu, s0, 1);
        s0 += __shfl_xor_sync(0xffffffffu, s0, 2);
        s1 += __shfl_xor_sync(0xffffffffu, s1, 1);
        s1 += __shfl_xor_sync(0xffffffffu, s1, 2);
        T0 = T0 * a0 + s0;
        T1 = T1 * a1 + s1;
#pragma unroll
        for (int d8 = 0; d8 < 8; d8++) {
            ctx[d8][0] *= a0; ctx[d8][1] *= a0;
            ctx[d8][2] *= a1; ctx[d8][3] *= a1;
        }

        // ---- PV: P (register score fragments) x V (ldmatrix.trans on the fly)
#pragma unroll
        for (int c = 0; c < 8; c++) {
            uint32_t ah[4], al[4];
            split2(acc[2 * c][0],     acc[2 * c][1],     ah[0], al[0]);
            split2(acc[2 * c][2],     acc[2 * c][3],     ah[1], al[1]);
            split2(acc[2 * c + 1][0], acc[2 * c + 1][1], ah[2], al[2]);
            split2(acc[2 * c + 1][2], acc[2 * c + 1][3], ah[3], al[3]);
            const uint32_t cb = (uint32_t)(c * 16 * 144);   // 16 t-rows per c
#pragma unroll
            for (int dp = 0; dp < 4; dp++) {
                uint32_t addr = cb + (uint32_t)(dp * 32);   // 16 d-halves per dp
                uint32_t h0, h1, h2, h3, l0, l1, l2, l3;
                ldsm_x4_trans(h0, h1, h2, h3, VHa + addr);
                ldsm_x4_trans(l0, l1, l2, l3, VLa + addr);
                uint32_t bhA[2] = {h0, h1}, bhB[2] = {h2, h3};
                uint32_t blA[2] = {l0, l1}, blB[2] = {l2, l3};
                mma_f16(ctx[2 * dp], ah, bhA);
                mma_f16(ctx[2 * dp], ah, blA);
                mma_f16(ctx[2 * dp], al, bhA);
                mma_f16(ctx[2 * dp + 1], ah, bhB);
                mma_f16(ctx[2 * dp + 1], ah, blB);
                mma_f16(ctx[2 * dp + 1], al, bhB);
            }
        }

        CP_WAIT0();
        __syncthreads();
        stage ^= 1;
    }

    // ---- normalize and write ctx hi/lo planes
    float i0 = 1.0f / T0, i1 = 1.0f / T1;
    const long r0 = q0 + warp * 16 + g;
#pragma unroll
    for (int d8 = 0; d8 < 8; d8++) {
        long col = (long)z * 64 + d8 * 8 + tig * 2;
        uint32_t h, l;
        split2(ctx[d8][0] * i0, ctx[d8][1] * i0, h, l);
        *reinterpret_cast<uint32_t*>(Oh + r0 * 4096 + col) = h;
        *reinterpret_cast<uint32_t*>(Ol + r0 * 4096 + col) = l;
        split2(ctx[d8][2] * i1, ctx[d8][3] * i1, h, l);
        *reinterpret_cast<uint32_t*>(Oh + (r0 + 8) * 4096 + col) = h;
        *reinterpret_cast<uint32_t*>(Ol + (r0 + 8) * 4096 + col) = l;
    }
}

// ---------------------------------------------------------------------------
// Output projection: ctx hi/lo planes x Wo_k (exact fp16) — 2 passes, BK=64,
// cp.async 2-stage ping-pong (unchanged).
// ---------------------------------------------------------------------------
#define WO_STRIDE 144
#define WO_BUF    (128 * WO_STRIDE)   // 18432
#define WO_STAGE  (3 * WO_BUF)
#define SM_TOTAL_WO (2 * WO_STAGE)    // 110592

__global__ __launch_bounds__(256) void gemm_ctx_wo_kernel(
    const __half* __restrict__ Ahp, const __half* __restrict__ Alp,
    const __half* __restrict__ B,
    float* __restrict__ C, const float* __restrict__ bias,
    const float* __restrict__ aB) {
    const int K = E_;
    extern __shared__ char smw[];

    const int tid  = threadIdx.x;
    const int warp = tid >> 5;
    const int lane = tid & 31;
    const int g    = lane >> 2;
    const int tig  = lane & 3;

    const int m0 = blockIdx.y * 128;
    const int n0 = blockIdx.x * 128;
    const int wm = (warp >> 2) * 64;
    const int wn = (warp & 3) * 32;

    float acc[4][4][4];
#pragma unroll
    for (int mt = 0; mt < 4; mt++)
#pragma unroll
        for (int nt = 0; nt < 4; nt++)
#pragma unroll
            for (int c = 0; c < 4; c++) acc[mt][nt][c] = 0.0f;

    const int WSTR = WO_STRIDE / 4;

#pragma unroll
    for (int it = 0; it < 4; it++) {
        int idx = it * 256 + tid;
        int row = idx >> 3, qd = idx & 7;
        long goA = (long)(m0 + row) * K + qd * 8;
        cp_async16(smw + row * WO_STRIDE + qd * 16, Ahp + goA);
        cp_async16(smw + WO_BUF + row * WO_STRIDE + qd * 16, Alp + goA);
        cp_async16(smw + 2 * WO_BUF + row * WO_STRIDE + qd * 16,
                   B + (long)(n0 + row) * K + qd * 8);
    }
    CP_COMMIT();

    int stage = 0;
    for (int k0 = 0; k0 < K; k0 += 64) {
        CP_WAIT0();
        __syncthreads();
        if (k0 + 64 < K) {
            char* d = smw + (stage ^ 1) * WO_STAGE;
#pragma unroll
            for (int it = 0; it < 4; it++) {
                int idx = it * 256 + tid;
                int row = idx >> 3, qd = idx & 7;
                long goA = (long)(m0 + row) * K + k0 + 64 + qd * 8;
                cp_async16(d + row * WO_STRIDE + qd * 16, Ahp + goA);
                cp_async16(d + WO_BUF + row * WO_STRIDE + qd * 16, Alp + goA);
                cp_async16(d + 2 * WO_BUF + row * WO_STRIDE + qd * 16,
                           B + (long)(n0 + row) * K + k0 + 64 + qd * 8);
            }
            CP_COMMIT();
        }

        const uint32_t* Ahw = reinterpret_cast<const uint32_t*>(smw + stage * WO_STAGE);
        const uint32_t* Alw = reinterpret_cast<const uint32_t*>(smw + stage * WO_STAGE + WO_BUF);
        const uint32_t* Bw  = reinterpret_cast<const uint32_t*>(smw + stage * WO_STAGE + 2 * WO_BUF);
#pragma unroll
        for (int ks = 0; ks < 4; ks++) {
            uint32_t ah[4][4], al[4][4], bf[4][2];
#pragma unroll
            for (int mt = 0; mt < 4; mt++) {
                int base = (wm + mt * 16 + g) * WSTR + ks * 8 + tig;
                ah[mt][0] = Ahw[base];
                ah[mt][1] = Ahw[base + 8 * WSTR];
                ah[mt][2] = Ahw[base + 4];
                ah[mt][3] = Ahw[base + 8 * WSTR + 4];
                al[mt][0] = Alw[base];
                al[mt][1] = Alw[base + 8 * WSTR];
                al[mt][2] = Alw[base + 4];
                al[mt][3] = Alw[base + 8 * WSTR + 4];
            }
#pragma unroll
            for (int nt = 0; nt < 4; nt++) {
                int base = (wn + nt * 8 + g) * WSTR + ks * 8 + tig;
                bf[nt][0] = Bw[base];
                bf[nt][1] = Bw[base + 4];
            }
#pragma unroll
            for (int mt = 0; mt < 4; mt++)
#pragma unroll
                for (int nt = 0; nt < 4; nt++) {
                    mma_f16(acc[mt][nt], ah[mt], bf[nt]);
                    mma_f16(acc[mt][nt], al[mt], bf[nt]);
                }
        }
        stage ^= 1;
    }

    const float scale = __ldg(aB) * (1.0f / 48.0f);
#pragma unroll
    for (int mt = 0; mt < 4; mt++) {
#pragma unroll
        for (int nt = 0; nt < 4; nt++) {
            long row = m0 + wm + mt * 16 + g;
            long col = n0 + wn + nt * 8 + tig * 2;
            float b0 = bias[col], b1 = bias[col + 1];
            float2 v0, v1;
            v0.x = acc[mt][nt][0] * scale + b0;
            v0.y = acc[mt][nt][1] * scale + b1;
            v1.x = acc[mt][nt][2] * scale + b0;
            v1.y = acc[mt][nt][3] * scale + b1;
            *reinterpret_cast<float2*>(C + row * (long)E_ + col) = v0;
            *reinterpret_cast<float2*>(C + (row + 8) * (long)E_ + col) = v1;
        }
    }
}

// ---------------------------------------------------------------------------
// Orchestration.
// ---------------------------------------------------------------------------
extern "C" void kernel_launch(void* const* d_in, const int* in_sizes, int n_in,
                              void* d_out, int out_size) {
    const float* q    = (const float*)d_in[0];
    const float* k    = (const float*)d_in[1];
    const float* v    = (const float*)d_in[2];
    const float* Wi   = (const float*)d_in[3];
    const float* bi   = (const float*)d_in[4];
    const float* Wo   = (const float*)d_in[5];
    const float* bo   = (const float*)d_in[6];
    const float* a_act = (const float*)d_in[7];
    const float* a_wi  = (const float*)d_in[8];
    const float* a_bi  = (const float*)d_in[9];
    const float* a_wo  = (const float*)d_in[10];
    const float* a_bo  = (const float*)d_in[11];
    float* out = (float*)d_out;

    int8_t *p_Wi8, *p_act8;
    __half *p_Woh, *p_ph, *p_pl, *p_cxh, *p_cxl;
    float *p_bi, *p_bo;
    cudaGetSymbolAddress((void**)&p_Wi8, g_Wi_i8);
    cudaGetSymbolAddress((void**)&p_act8, g_act_i8);
    cudaGetSymbolAddress((void**)&p_Woh, g_Wo_h);
    cudaGetSymbolAddress((void**)&p_bi, g_bi);
    cudaGetSymbolAddress((void**)&p_bo, g_bo);
    cudaGetSymbolAddress((void**)&p_ph, g_proj_h);
    cudaGetSymbolAddress((void**)&p_pl, g_proj_l);
    cudaGetSymbolAddress((void**)&p_cxh, g_ctx_h);
    cudaGetSymbolAddress((void**)&p_cxl, g_ctx_l);

    const long RE = (long)R_ * E_;

    cudaFuncSetAttribute(flash_attn_kernel,
                         cudaFuncAttributeMaxDynamicSharedMemorySize,
                         SM_TOTAL_FLASH);
    cudaFuncSetAttribute(gemm_ctx_wo_kernel,
                         cudaFuncAttributeMaxDynamicSharedMemorySize,
                         SM_TOTAL_WO);
    cudaFuncSetAttribute(gemm_i8_kernel,
                         cudaFuncAttributeMaxDynamicSharedMemorySize,
                         SM_TOTAL_I8);

    init_tables_kernel<<<1, 1>>>();

    // Fused quantization: weights + biases + activations in ONE launch
    quant_all_kernel<<<QB_TOT, 256>>>(
        Wi, Wo, bi, bo, q, k, v,
        p_Wi8, p_Woh, p_bi, p_bo, p_act8,
        a_wi, a_wo, a_bi, a_bo, a_act);

    // Projections via int8 tensor cores (exact) -> fp16 hi/lo planes
    gemm_i8_kernel<<<dim3(E_ / 128, R_ / 128, 3), 256, SM_TOTAL_I8>>>(
        p_act8, p_Wi8, p_ph, p_pl, p_bi, a_act, a_wi, E_, E_);

    // Fused attention: scores + online softmax + PV (V transposed in-kernel
    // via ldmatrix.trans) -> ctx planes
    flash_attn_kernel<<<dim3(S_ / 128, Z_), 256, SM_TOTAL_FLASH>>>(
        p_ph, p_pl, p_ph + RE, p_pl + RE, p_ph + 2 * RE, p_pl + 2 * RE,
        p_cxh, p_cxl);

    // Output projection: ctx planes x Wo_k (exact fp16, 2 passes) -> out
    gemm_ctx_wo_kernel<<<dim3(8, 32), 256, SM_TOTAL_WO>>>(
        p_cxh, p_cxl, p_Woh, out, p_bo, a_wo);
}